// round 3
// baseline (speedup 1.0000x reference)
#include <cuda_runtime.h>
#include <math.h>
#include <stdint.h>

// ---------------------------------------------------------------------------
// Problem constants
// ---------------------------------------------------------------------------
#define Bb   2
#define Nn_  2048
#define Cc   512
#define Hh   8
#define HD   64
#define DFF  2048
#define Mrows (Bb*Nn_)          // 4096
#define BH   (Bb*Hh)            // 16

// ---------------------------------------------------------------------------
// Device scratch (static allocation — no cudaMalloc allowed).  88 MB total.
// ---------------------------------------------------------------------------
__device__ float g_ln1[Mrows*Cc];             // 8 MB
__device__ float g_q  [BH*Nn_*HD];            // 8 MB  [bh, n, d]
__device__ float g_k  [BH*Nn_*HD];            // 8 MB  [bh, n, d]
__device__ float g_v  [BH*Nn_*HD];            // 8 MB  [bh, n, d]
__device__ float g_o  [Mrows*Cc];             // 8 MB  attn out, [m, C]
__device__ float g_y  [Mrows*Cc];             // 8 MB  residual-1 out
__device__ float g_h2 [Mrows*Cc];             // 8 MB  LN2 out
__device__ float g_f  [Mrows*DFF];            // 32 MB FFN hidden

// ---------------------------------------------------------------------------
// LayerNorm: one block (128 thr) per row of 512
// ---------------------------------------------------------------------------
__global__ __launch_bounds__(128)
void layernorm_rows(const float* __restrict__ X, float* __restrict__ Y,
                    const float* __restrict__ g, const float* __restrict__ b)
{
    int row = blockIdx.x;
    int tid = threadIdx.x;
    const float* x = X + (size_t)row * Cc;
    float4 v = *reinterpret_cast<const float4*>(x + tid*4);

    __shared__ float red[128];
    red[tid] = v.x + v.y + v.z + v.w;
    __syncthreads();
    #pragma unroll
    for (int s = 64; s > 0; s >>= 1) {
        if (tid < s) red[tid] += red[tid+s];
        __syncthreads();
    }
    float mu = red[0] * (1.0f/Cc);
    __syncthreads();

    float dx = v.x-mu, dy = v.y-mu, dz = v.z-mu, dw = v.w-mu;
    red[tid] = dx*dx + dy*dy + dz*dz + dw*dw;
    __syncthreads();
    #pragma unroll
    for (int s = 64; s > 0; s >>= 1) {
        if (tid < s) red[tid] += red[tid+s];
        __syncthreads();
    }
    float var = red[0] * (1.0f/Cc);
    float r = rsqrtf(var + 1e-5f);

    float4 gg = *reinterpret_cast<const float4*>(g + tid*4);
    float4 bb = *reinterpret_cast<const float4*>(b + tid*4);
    float4 o;
    o.x = dx*r*gg.x + bb.x;
    o.y = dy*r*gg.y + bb.y;
    o.z = dz*r*gg.z + bb.z;
    o.w = dw*r*gg.w + bb.w;
    *reinterpret_cast<float4*>(Y + (size_t)row*Cc + tid*4) = o;
}

// ---------------------------------------------------------------------------
// Fused flash-style attention.
//   Grid: (N/64 q-tiles, BH).  Block: 256 threads (16x16).
//   Each thread owns a 4x4 fragment of the 64x64 S/P/O tiles with rows
//   r = ty + 16*i, cols c = tx + 16*j (strided => conflict-free SMEM).
//   Multiplicative mask is applied BEFORE softmax (masked scores become 0).
//   Online softmax with running max/sum; O accumulated in registers.
// ---------------------------------------------------------------------------
#define FST 65   // smem row stride (floats), pad for bank-conflict freedom

__global__ __launch_bounds__(256)
void flash_attn(const float* __restrict__ Q, const float* __restrict__ K,
                const float* __restrict__ V, const float* __restrict__ mask,
                float* __restrict__ O)
{
    extern __shared__ float sm[];
    float* sQ = sm;               // 64*FST
    float* sK = sQ + 64*FST;
    float* sV = sK + 64*FST;
    float* sP = sV + 64*FST;

    int tid = threadIdx.x;
    int tx  = tid & 15;
    int ty  = tid >> 4;
    int q0  = blockIdx.x * 64;
    int bh  = blockIdx.y;
    int b   = bh >> 3, hh = bh & 7;

    const float* Qb = Q + ((size_t)bh*Nn_ + q0)*HD;
    const float* Kb = K + (size_t)bh*Nn_*HD;
    const float* Vb = V + (size_t)bh*Nn_*HD;

    // Load Q tile (64x64) once.
    #pragma unroll
    for (int i = 0; i < 4; i++) {
        int f  = tid + i*256;          // float4 index 0..1023
        int r  = f >> 4;
        int c4 = (f & 15) << 2;
        float4 v = *reinterpret_cast<const float4*>(Qb + r*HD + c4);
        sQ[r*FST+c4+0]=v.x; sQ[r*FST+c4+1]=v.y;
        sQ[r*FST+c4+2]=v.z; sQ[r*FST+c4+3]=v.w;
    }

    float o[4][4];
    float rmax[4], rsum[4];
    #pragma unroll
    for (int i = 0; i < 4; i++) {
        rmax[i] = -1e30f; rsum[i] = 0.0f;
        #pragma unroll
        for (int j = 0; j < 4; j++) o[i][j] = 0.0f;
    }

    const float scale = 0.125f;

    for (int kt = 0; kt < Nn_; kt += 64) {
        __syncthreads();   // protect sK/sV (prev iter readers) and sQ (first iter)
        // Load K and V tiles (64 keys x 64 dims each)
        #pragma unroll
        for (int i = 0; i < 4; i++) {
            int f  = tid + i*256;
            int r  = f >> 4;
            int c4 = (f & 15) << 2;
            float4 kv = *reinterpret_cast<const float4*>(Kb + (size_t)(kt+r)*HD + c4);
            sK[r*FST+c4+0]=kv.x; sK[r*FST+c4+1]=kv.y;
            sK[r*FST+c4+2]=kv.z; sK[r*FST+c4+3]=kv.w;
            float4 vv = *reinterpret_cast<const float4*>(Vb + (size_t)(kt+r)*HD + c4);
            sV[r*FST+c4+0]=vv.x; sV[r*FST+c4+1]=vv.y;
            sV[r*FST+c4+2]=vv.z; sV[r*FST+c4+3]=vv.w;
        }
        __syncthreads();

        // S = Q @ K^T  (4x4 fragment per thread)
        float s[4][4];
        #pragma unroll
        for (int i = 0; i < 4; i++)
            #pragma unroll
            for (int j = 0; j < 4; j++) s[i][j] = 0.0f;
        #pragma unroll 8
        for (int k = 0; k < 64; k++) {
            float a[4], bb2[4];
            #pragma unroll
            for (int i = 0; i < 4; i++) a[i]   = sQ[(ty+16*i)*FST + k];
            #pragma unroll
            for (int j = 0; j < 4; j++) bb2[j] = sK[(tx+16*j)*FST + k];
            #pragma unroll
            for (int i = 0; i < 4; i++)
                #pragma unroll
                for (int j = 0; j < 4; j++)
                    s[i][j] = fmaf(a[i], bb2[j], s[i][j]);
        }

        // scale * mask (multiplicative, pre-softmax)
        #pragma unroll
        for (int i = 0; i < 4; i++) {
            const float* mrow = mask + (size_t)(q0+ty+16*i)*Nn_ + kt;
            #pragma unroll
            for (int j = 0; j < 4; j++)
                s[i][j] = s[i][j] * scale * mrow[tx+16*j];
        }

        // Online softmax update (row groups = 16 lanes, shfl width 16)
        #pragma unroll
        for (int i = 0; i < 4; i++) {
            float tmax = fmaxf(fmaxf(s[i][0], s[i][1]), fmaxf(s[i][2], s[i][3]));
            #pragma unroll
            for (int off = 8; off > 0; off >>= 1)
                tmax = fmaxf(tmax, __shfl_xor_sync(0xffffffffu, tmax, off, 16));
            float nm = fmaxf(rmax[i], tmax);
            float corr = __expf(rmax[i] - nm);
            rmax[i] = nm;
            float psum = 0.0f;
            #pragma unroll
            for (int j = 0; j < 4; j++) {
                float p = __expf(s[i][j] - nm);
                s[i][j] = p;
                psum += p;
            }
            #pragma unroll
            for (int off = 8; off > 0; off >>= 1)
                psum += __shfl_xor_sync(0xffffffffu, psum, off, 16);
            rsum[i] = rsum[i]*corr + psum;
            #pragma unroll
            for (int j = 0; j < 4; j++) o[i][j] *= corr;
        }

        // Stage P to SMEM
        #pragma unroll
        for (int i = 0; i < 4; i++)
            #pragma unroll
            for (int j = 0; j < 4; j++)
                sP[(ty+16*i)*FST + tx+16*j] = s[i][j];
        __syncthreads();

        // O += P @ V
        #pragma unroll 8
        for (int k = 0; k < 64; k++) {
            float pa[4], bv[4];
            #pragma unroll
            for (int i = 0; i < 4; i++) pa[i] = sP[(ty+16*i)*FST + k];
            #pragma unroll
            for (int j = 0; j < 4; j++) bv[j] = sV[k*FST + tx+16*j];
            #pragma unroll
            for (int i = 0; i < 4; i++)
                #pragma unroll
                for (int j = 0; j < 4; j++)
                    o[i][j] = fmaf(pa[i], bv[j], o[i][j]);
        }
    }

    // Normalize and scatter into [B*N, C] layout
    #pragma unroll
    for (int i = 0; i < 4; i++) {
        float inv = 1.0f / rsum[i];
        size_t base = ((size_t)(b*Nn_ + q0 + ty + 16*i))*Cc + hh*HD;
        #pragma unroll
        for (int j = 0; j < 4; j++)
            O[base + tx + 16*j] = o[i][j] * inv;
    }
}

// ---------------------------------------------------------------------------
// Generic tiled GEMM: C[m,n] = sum_k A[m,k] * B[n,k]   (A: MxK, B: NxK row-maj)
// Epilogues:
//   0: plain store
//   1: + bias[n]
//   2: gelu(acc + bias[n])              (erf gelu)
//   3: acc + bias[n] + res[m*ldc+n]     (residual)
//   5: QKV scatter (C=q, C2=k, C3=v), all [bh, n, d]
// ---------------------------------------------------------------------------
template<int BM, int BN, int BK, int TM, int TN, int EPI>
__global__ __launch_bounds__((BM/TM)*(BN/TN))
void gemm_kernel(const float* __restrict__ A, const float* __restrict__ B,
                 float* __restrict__ C, float* __restrict__ C2, float* __restrict__ C3,
                 int K, int lda, int ldb, int ldc,
                 const float* __restrict__ bias,
                 const float* __restrict__ res)
{
    constexpr int THREADS = (BM/TM)*(BN/TN);
    __shared__ float As[BK][BM];
    __shared__ float Bs[BK][BN];

    int tid = threadIdx.x;
    int tx  = tid % (BN/TN);
    int ty  = tid / (BN/TN);
    int m0  = blockIdx.y * BM;
    int n0  = blockIdx.x * BN;

    float acc[TM][TN];
    #pragma unroll
    for (int i = 0; i < TM; i++)
        #pragma unroll
        for (int j = 0; j < TN; j++) acc[i][j] = 0.0f;

    constexpr int K4      = BK/4;
    constexpr int A_LOADS = BM*K4/THREADS;
    constexpr int B_LOADS = BN*K4/THREADS;

    for (int kt = 0; kt < K; kt += BK) {
        #pragma unroll
        for (int i = 0; i < A_LOADS; i++) {
            int idx = tid + i*THREADS;
            int r   = idx / K4;
            int c4  = idx % K4;
            float4 v = *reinterpret_cast<const float4*>(A + (size_t)(m0+r)*lda + kt + c4*4);
            As[c4*4+0][r] = v.x; As[c4*4+1][r] = v.y;
            As[c4*4+2][r] = v.z; As[c4*4+3][r] = v.w;
        }
        #pragma unroll
        for (int i = 0; i < B_LOADS; i++) {
            int idx = tid + i*THREADS;
            int r   = idx / K4;
            int c4  = idx % K4;
            float4 v = *reinterpret_cast<const float4*>(B + (size_t)(n0+r)*ldb + kt + c4*4);
            Bs[c4*4+0][r] = v.x; Bs[c4*4+1][r] = v.y;
            Bs[c4*4+2][r] = v.z; Bs[c4*4+3][r] = v.w;
        }
        __syncthreads();
        #pragma unroll
        for (int k = 0; k < BK; k++) {
            float a[TM], bb[TN];
            #pragma unroll
            for (int i = 0; i < TM; i++) a[i]  = As[k][ty*TM+i];
            #pragma unroll
            for (int j = 0; j < TN; j++) bb[j] = Bs[k][tx*TN+j];
            #pragma unroll
            for (int i = 0; i < TM; i++)
                #pragma unroll
                for (int j = 0; j < TN; j++)
                    acc[i][j] = fmaf(a[i], bb[j], acc[i][j]);
        }
        __syncthreads();
    }

    #pragma unroll
    for (int i = 0; i < TM; i++) {
        int m = m0 + ty*TM + i;
        #pragma unroll
        for (int j = 0; j < TN; j++) {
            int n = n0 + tx*TN + j;
            float v = acc[i][j];
            if (EPI == 0) {
                C[(size_t)m*ldc + n] = v;
            } else if (EPI == 1) {
                C[(size_t)m*ldc + n] = v + bias[n];
            } else if (EPI == 2) {
                float t = v + bias[n];
                C[(size_t)m*ldc + n] = 0.5f * t * (1.0f + erff(t * 0.70710678118654752f));
            } else if (EPI == 3) {
                C[(size_t)m*ldc + n] = v + bias[n] + res[(size_t)m*ldc + n];
            } else if (EPI == 5) {
                int kind = n >> 9;           // 0:q 1:k 2:v
                int w    = n & 511;
                int hh   = w >> 6;
                int d    = w & 63;
                int b    = m >> 11;
                int ntok = m & 2047;
                size_t bh = (size_t)(b*Hh + hh);
                if      (kind == 0) C [(bh*Nn_ + ntok)*HD + d] = v;
                else if (kind == 1) C2[(bh*Nn_ + ntok)*HD + d] = v;
                else                C3[(bh*Nn_ + ntok)*HD + d] = v;
            }
        }
    }
}

// ---------------------------------------------------------------------------
// Launch
// ---------------------------------------------------------------------------
extern "C" void kernel_launch(void* const* d_in, const int* in_sizes, int n_in,
                              void* d_out, int out_size)
{
    const float* x      = (const float*)d_in[0];
    const float* mask   = (const float*)d_in[1];
    const float* w_qkv  = (const float*)d_in[2];
    const float* w_proj = (const float*)d_in[3];
    const float* b_proj = (const float*)d_in[4];
    const float* g1     = (const float*)d_in[5];
    const float* beta1  = (const float*)d_in[6];
    const float* g2     = (const float*)d_in[7];
    const float* beta2  = (const float*)d_in[8];
    const float* w1     = (const float*)d_in[9];
    const float* bm1    = (const float*)d_in[10];
    const float* w2     = (const float*)d_in[11];
    const float* bm2    = (const float*)d_in[12];
    float* out = (float*)d_out;

    float *ln1, *q, *k, *v, *o, *y, *h2, *f;
    cudaGetSymbolAddress((void**)&ln1, g_ln1);
    cudaGetSymbolAddress((void**)&q,   g_q);
    cudaGetSymbolAddress((void**)&k,   g_k);
    cudaGetSymbolAddress((void**)&v,   g_v);
    cudaGetSymbolAddress((void**)&o,   g_o);
    cudaGetSymbolAddress((void**)&y,   g_y);
    cudaGetSymbolAddress((void**)&h2,  g_h2);
    cudaGetSymbolAddress((void**)&f,   g_f);

    const int FLASH_SMEM = 4*64*FST*4;   // 66560 B dynamic smem
    cudaFuncSetAttribute(flash_attn,
        cudaFuncAttributeMaxDynamicSharedMemorySize, FLASH_SMEM);

    // 1) LN1
    layernorm_rows<<<Mrows, 128>>>(x, ln1, g1, beta1);

    // 2) QKV GEMM with scatter: M=4096, N=1536, K=512
    {
        dim3 grid(1536/128, Mrows/128, 1);
        gemm_kernel<128,128,16,8,8,5><<<grid, 256>>>(
            ln1, w_qkv, q, k, v, Cc, Cc, Cc, 0, nullptr, nullptr);
    }

    // 3) Fused attention (scores + mask + softmax + PV), scatters into o[m,C]
    {
        dim3 grid(Nn_/64, BH, 1);
        flash_attn<<<grid, 256, FLASH_SMEM>>>(q, k, v, mask, o);
    }

    // 4) proj + bias + residual: y = x + O @ w_proj^T + b_proj
    {
        dim3 grid(Cc/128, Mrows/128, 1);
        gemm_kernel<128,128,16,8,8,3><<<grid, 256>>>(
            o, w_proj, y, nullptr, nullptr, Cc, Cc, Cc, Cc, b_proj, x);
    }

    // 5) LN2
    layernorm_rows<<<Mrows, 128>>>(y, h2, g2, beta2);

    // 6) FFN1 + bias + gelu: f = gelu(h2 @ w1^T + bm1)
    {
        dim3 grid(DFF/128, Mrows/128, 1);
        gemm_kernel<128,128,16,8,8,2><<<grid, 256>>>(
            h2, w1, f, nullptr, nullptr, Cc, Cc, Cc, DFF, bm1, nullptr);
    }

    // 7) FFN2 + bias + residual: out = y + f @ w2^T + bm2
    {
        dim3 grid(Cc/128, Mrows/128, 1);
        gemm_kernel<128,128,16,8,8,3><<<grid, 256>>>(
            f, w2, out, nullptr, nullptr, DFF, DFF, DFF, Cc, bm2, y);
    }

    (void)in_sizes; (void)n_in; (void)out_size;
}

// round 4
// speedup vs baseline: 1.5762x; 1.5762x over previous
#include <cuda_runtime.h>
#include <math.h>
#include <stdint.h>

// ---------------------------------------------------------------------------
// Problem constants
// ---------------------------------------------------------------------------
#define Bb   2
#define Nn_  2048
#define Cc   512
#define Hh   8
#define HD   64
#define DFF  2048
#define Mrows (Bb*Nn_)          // 4096
#define BH   (Bb*Hh)            // 16

// ---------------------------------------------------------------------------
// Device scratch (static allocation — no cudaMalloc allowed).  88 MB total.
// ---------------------------------------------------------------------------
__device__ float g_ln1[Mrows*Cc];             // 8 MB
__device__ float g_q  [BH*Nn_*HD];            // 8 MB  [bh, n, d]
__device__ float g_k  [BH*Nn_*HD];            // 8 MB  [bh, n, d]
__device__ float g_v  [BH*Nn_*HD];            // 8 MB  [bh, n, d]
__device__ float g_o  [Mrows*Cc];             // 8 MB  attn out, [m, C]
__device__ float g_y  [Mrows*Cc];             // 8 MB  residual-1 out
__device__ float g_h2 [Mrows*Cc];             // 8 MB  LN2 out
__device__ float g_f  [Mrows*DFF];            // 32 MB FFN hidden

// ---------------------------------------------------------------------------
// LayerNorm: one block (128 thr) per row of 512
// ---------------------------------------------------------------------------
__global__ __launch_bounds__(128)
void layernorm_rows(const float* __restrict__ X, float* __restrict__ Y,
                    const float* __restrict__ g, const float* __restrict__ b)
{
    int row = blockIdx.x;
    int tid = threadIdx.x;
    const float* x = X + (size_t)row * Cc;
    float4 v = *reinterpret_cast<const float4*>(x + tid*4);

    __shared__ float red[128];
    red[tid] = v.x + v.y + v.z + v.w;
    __syncthreads();
    #pragma unroll
    for (int s = 64; s > 0; s >>= 1) {
        if (tid < s) red[tid] += red[tid+s];
        __syncthreads();
    }
    float mu = red[0] * (1.0f/Cc);
    __syncthreads();

    float dx = v.x-mu, dy = v.y-mu, dz = v.z-mu, dw = v.w-mu;
    red[tid] = dx*dx + dy*dy + dz*dz + dw*dw;
    __syncthreads();
    #pragma unroll
    for (int s = 64; s > 0; s >>= 1) {
        if (tid < s) red[tid] += red[tid+s];
        __syncthreads();
    }
    float var = red[0] * (1.0f/Cc);
    float r = rsqrtf(var + 1e-5f);

    float4 gg = *reinterpret_cast<const float4*>(g + tid*4);
    float4 bb = *reinterpret_cast<const float4*>(b + tid*4);
    float4 o;
    o.x = dx*r*gg.x + bb.x;
    o.y = dy*r*gg.y + bb.y;
    o.z = dz*r*gg.z + bb.z;
    o.w = dw*r*gg.w + bb.w;
    *reinterpret_cast<float4*>(Y + (size_t)row*Cc + tid*4) = o;
}

// ---------------------------------------------------------------------------
// Fused flash-style attention (unchanged from passing R2 kernel).
// ---------------------------------------------------------------------------
#define FST 65   // smem row stride (floats)

__global__ __launch_bounds__(256)
void flash_attn(const float* __restrict__ Q, const float* __restrict__ K,
                const float* __restrict__ V, const float* __restrict__ mask,
                float* __restrict__ O)
{
    extern __shared__ float sm[];
    float* sQ = sm;               // 64*FST
    float* sK = sQ + 64*FST;
    float* sV = sK + 64*FST;
    float* sP = sV + 64*FST;

    int tid = threadIdx.x;
    int tx  = tid & 15;
    int ty  = tid >> 4;
    int q0  = blockIdx.x * 64;
    int bh  = blockIdx.y;
    int b   = bh >> 3, hh = bh & 7;

    const float* Qb = Q + ((size_t)bh*Nn_ + q0)*HD;
    const float* Kb = K + (size_t)bh*Nn_*HD;
    const float* Vb = V + (size_t)bh*Nn_*HD;

    #pragma unroll
    for (int i = 0; i < 4; i++) {
        int f  = tid + i*256;
        int r  = f >> 4;
        int c4 = (f & 15) << 2;
        float4 v = *reinterpret_cast<const float4*>(Qb + r*HD + c4);
        sQ[r*FST+c4+0]=v.x; sQ[r*FST+c4+1]=v.y;
        sQ[r*FST+c4+2]=v.z; sQ[r*FST+c4+3]=v.w;
    }

    float o[4][4];
    float rmax[4], rsum[4];
    #pragma unroll
    for (int i = 0; i < 4; i++) {
        rmax[i] = -1e30f; rsum[i] = 0.0f;
        #pragma unroll
        for (int j = 0; j < 4; j++) o[i][j] = 0.0f;
    }

    const float scale = 0.125f;

    for (int kt = 0; kt < Nn_; kt += 64) {
        __syncthreads();
        #pragma unroll
        for (int i = 0; i < 4; i++) {
            int f  = tid + i*256;
            int r  = f >> 4;
            int c4 = (f & 15) << 2;
            float4 kv = *reinterpret_cast<const float4*>(Kb + (size_t)(kt+r)*HD + c4);
            sK[r*FST+c4+0]=kv.x; sK[r*FST+c4+1]=kv.y;
            sK[r*FST+c4+2]=kv.z; sK[r*FST+c4+3]=kv.w;
            float4 vv = *reinterpret_cast<const float4*>(Vb + (size_t)(kt+r)*HD + c4);
            sV[r*FST+c4+0]=vv.x; sV[r*FST+c4+1]=vv.y;
            sV[r*FST+c4+2]=vv.z; sV[r*FST+c4+3]=vv.w;
        }
        __syncthreads();

        float s[4][4];
        #pragma unroll
        for (int i = 0; i < 4; i++)
            #pragma unroll
            for (int j = 0; j < 4; j++) s[i][j] = 0.0f;
        #pragma unroll 8
        for (int k = 0; k < 64; k++) {
            float a[4], bb2[4];
            #pragma unroll
            for (int i = 0; i < 4; i++) a[i]   = sQ[(ty+16*i)*FST + k];
            #pragma unroll
            for (int j = 0; j < 4; j++) bb2[j] = sK[(tx+16*j)*FST + k];
            #pragma unroll
            for (int i = 0; i < 4; i++)
                #pragma unroll
                for (int j = 0; j < 4; j++)
                    s[i][j] = fmaf(a[i], bb2[j], s[i][j]);
        }

        #pragma unroll
        for (int i = 0; i < 4; i++) {
            const float* mrow = mask + (size_t)(q0+ty+16*i)*Nn_ + kt;
            #pragma unroll
            for (int j = 0; j < 4; j++)
                s[i][j] = s[i][j] * scale * mrow[tx+16*j];
        }

        #pragma unroll
        for (int i = 0; i < 4; i++) {
            float tmax = fmaxf(fmaxf(s[i][0], s[i][1]), fmaxf(s[i][2], s[i][3]));
            #pragma unroll
            for (int off = 8; off > 0; off >>= 1)
                tmax = fmaxf(tmax, __shfl_xor_sync(0xffffffffu, tmax, off, 16));
            float nm = fmaxf(rmax[i], tmax);
            float corr = __expf(rmax[i] - nm);
            rmax[i] = nm;
            float psum = 0.0f;
            #pragma unroll
            for (int j = 0; j < 4; j++) {
                float p = __expf(s[i][j] - nm);
                s[i][j] = p;
                psum += p;
            }
            #pragma unroll
            for (int off = 8; off > 0; off >>= 1)
                psum += __shfl_xor_sync(0xffffffffu, psum, off, 16);
            rsum[i] = rsum[i]*corr + psum;
            #pragma unroll
            for (int j = 0; j < 4; j++) o[i][j] *= corr;
        }

        #pragma unroll
        for (int i = 0; i < 4; i++)
            #pragma unroll
            for (int j = 0; j < 4; j++)
                sP[(ty+16*i)*FST + tx+16*j] = s[i][j];
        __syncthreads();

        #pragma unroll 8
        for (int k = 0; k < 64; k++) {
            float pa[4], bv[4];
            #pragma unroll
            for (int i = 0; i < 4; i++) pa[i] = sP[(ty+16*i)*FST + k];
            #pragma unroll
            for (int j = 0; j < 4; j++) bv[j] = sV[k*FST + tx+16*j];
            #pragma unroll
            for (int i = 0; i < 4; i++)
                #pragma unroll
                for (int j = 0; j < 4; j++)
                    o[i][j] = fmaf(pa[i], bv[j], o[i][j]);
        }
    }

    #pragma unroll
    for (int i = 0; i < 4; i++) {
        float inv = 1.0f / rsum[i];
        size_t base = ((size_t)(b*Nn_ + q0 + ty + 16*i))*Cc + hh*HD;
        #pragma unroll
        for (int j = 0; j < 4; j++)
            O[base + tx + 16*j] = o[i][j] * inv;
    }
}

// ---------------------------------------------------------------------------
// TF32 tensor-core GEMM:  C[m,n] = sum_k A[m,k]*B[n,k]
// Block 128x128xK, BK=32, 8 warps (2x4), warp tile 64x32, mma m16n8k8.
// Smem stride 36 floats -> fragment-load banks (4r+c) mod 32: conflict-free.
// Epilogues: 2 = gelu(v+bias), 3 = v+bias+res, 5 = QKV scatter.
// ---------------------------------------------------------------------------
__device__ __forceinline__ uint32_t f2tf32(float x) {
    uint32_t r;
    asm("cvt.rna.tf32.f32 %0, %1;" : "=r"(r) : "f"(x));
    return r;
}

__device__ __forceinline__ void mma_tf32(float* d, const uint32_t* a, const uint32_t* b) {
    asm volatile(
        "mma.sync.aligned.m16n8k8.row.col.f32.tf32.tf32.f32 "
        "{%0,%1,%2,%3}, {%4,%5,%6,%7}, {%8,%9}, {%0,%1,%2,%3};"
        : "+f"(d[0]), "+f"(d[1]), "+f"(d[2]), "+f"(d[3])
        : "r"(a[0]), "r"(a[1]), "r"(a[2]), "r"(a[3]), "r"(b[0]), "r"(b[1]));
}

#define GST 36   // smem tile stride in floats (BK=32 + 4 pad)

template<int EPI>
__global__ __launch_bounds__(256)
void gemm_tf32(const float* __restrict__ A, const float* __restrict__ B,
               float* __restrict__ C, float* __restrict__ C2, float* __restrict__ C3,
               int K, int lda, int ldb, int ldc,
               const float* __restrict__ bias, const float* __restrict__ res)
{
    __shared__ __align__(16) uint32_t As[128*GST];
    __shared__ __align__(16) uint32_t Bs[128*GST];

    int tid  = threadIdx.x;
    int lane = tid & 31;
    int w    = tid >> 5;
    int wm   = (w >> 2) * 64;     // 0 or 64
    int wn   = (w & 3)  * 32;     // 0,32,64,96
    int r    = lane >> 2;         // 0..7
    int cq   = lane & 3;          // 0..3
    int m0   = blockIdx.y * 128;
    int n0   = blockIdx.x * 128;

    float acc[16][4];
    #pragma unroll
    for (int i = 0; i < 16; i++)
        #pragma unroll
        for (int j = 0; j < 4; j++) acc[i][j] = 0.0f;

    // initial prefetch (tile kt=0): 4 float4 per thread per matrix
    float4 pa[4], pb[4];
    #pragma unroll
    for (int i = 0; i < 4; i++) {
        int f = tid + i*256;
        int ar = f >> 3, ac4 = (f & 7) << 2;
        pa[i] = *reinterpret_cast<const float4*>(A + (size_t)(m0+ar)*lda + ac4);
        pb[i] = *reinterpret_cast<const float4*>(B + (size_t)(n0+ar)*ldb + ac4);
    }

    for (int kt = 0; kt < K; kt += 32) {
        // store prefetched tile to smem (convert to tf32)
        #pragma unroll
        for (int i = 0; i < 4; i++) {
            int f = tid + i*256;
            int ar = f >> 3, ac4 = (f & 7) << 2;
            uint4 ua = { f2tf32(pa[i].x), f2tf32(pa[i].y), f2tf32(pa[i].z), f2tf32(pa[i].w) };
            *reinterpret_cast<uint4*>(&As[ar*GST + ac4]) = ua;
            uint4 ub = { f2tf32(pb[i].x), f2tf32(pb[i].y), f2tf32(pb[i].z), f2tf32(pb[i].w) };
            *reinterpret_cast<uint4*>(&Bs[ar*GST + ac4]) = ub;
        }
        __syncthreads();

        // prefetch next tile while computing
        if (kt + 32 < K) {
            #pragma unroll
            for (int i = 0; i < 4; i++) {
                int f = tid + i*256;
                int ar = f >> 3, ac4 = (f & 7) << 2;
                pa[i] = *reinterpret_cast<const float4*>(A + (size_t)(m0+ar)*lda + kt+32 + ac4);
                pb[i] = *reinterpret_cast<const float4*>(B + (size_t)(n0+ar)*ldb + kt+32 + ac4);
            }
        }

        #pragma unroll
        for (int ks = 0; ks < 4; ks++) {
            int koff = ks * 8;
            uint32_t af[4][4];
            #pragma unroll
            for (int mt = 0; mt < 4; mt++) {
                int mr = wm + mt*16;
                af[mt][0] = As[(mr+r  )*GST + koff + cq];
                af[mt][1] = As[(mr+r+8)*GST + koff + cq];
                af[mt][2] = As[(mr+r  )*GST + koff + cq + 4];
                af[mt][3] = As[(mr+r+8)*GST + koff + cq + 4];
            }
            uint32_t bf[4][2];
            #pragma unroll
            for (int nt = 0; nt < 4; nt++) {
                int nr = wn + nt*8;
                bf[nt][0] = Bs[(nr+r)*GST + koff + cq];
                bf[nt][1] = Bs[(nr+r)*GST + koff + cq + 4];
            }
            #pragma unroll
            for (int mt = 0; mt < 4; mt++)
                #pragma unroll
                for (int nt = 0; nt < 4; nt++)
                    mma_tf32(acc[mt*4+nt], af[mt], bf[nt]);
        }
        __syncthreads();
    }

    // ---------------- epilogue ----------------
    #pragma unroll
    for (int mt = 0; mt < 4; mt++) {
        #pragma unroll
        for (int nt = 0; nt < 4; nt++) {
            const float* a4 = acc[mt*4+nt];
            int n = n0 + wn + nt*8 + 2*cq;
            #pragma unroll
            for (int p = 0; p < 2; p++) {
                int m = m0 + wm + mt*16 + r + 8*p;
                float v0 = a4[2*p+0];
                float v1 = a4[2*p+1];
                if (EPI == 2) {
                    float t0 = v0 + bias[n];
                    float t1 = v1 + bias[n+1];
                    float2 o2;
                    o2.x = 0.5f * t0 * (1.0f + erff(t0 * 0.70710678118654752f));
                    o2.y = 0.5f * t1 * (1.0f + erff(t1 * 0.70710678118654752f));
                    *reinterpret_cast<float2*>(C + (size_t)m*ldc + n) = o2;
                } else if (EPI == 3) {
                    float2 rr = *reinterpret_cast<const float2*>(res + (size_t)m*ldc + n);
                    float2 o2;
                    o2.x = v0 + bias[n]   + rr.x;
                    o2.y = v1 + bias[n+1] + rr.y;
                    *reinterpret_cast<float2*>(C + (size_t)m*ldc + n) = o2;
                } else if (EPI == 5) {
                    int kind = n >> 9;
                    int ww   = n & 511;
                    int hh   = ww >> 6;
                    int d    = ww & 63;
                    int b    = m >> 11;
                    int ntok = m & 2047;
                    size_t base = (((size_t)(b*Hh + hh))*Nn_ + ntok)*HD + d;
                    float2 o2; o2.x = v0; o2.y = v1;
                    if      (kind == 0) *reinterpret_cast<float2*>(C  + base) = o2;
                    else if (kind == 1) *reinterpret_cast<float2*>(C2 + base) = o2;
                    else                *reinterpret_cast<float2*>(C3 + base) = o2;
                }
            }
        }
    }
}

// ---------------------------------------------------------------------------
// Launch
// ---------------------------------------------------------------------------
extern "C" void kernel_launch(void* const* d_in, const int* in_sizes, int n_in,
                              void* d_out, int out_size)
{
    const float* x      = (const float*)d_in[0];
    const float* mask   = (const float*)d_in[1];
    const float* w_qkv  = (const float*)d_in[2];
    const float* w_proj = (const float*)d_in[3];
    const float* b_proj = (const float*)d_in[4];
    const float* g1     = (const float*)d_in[5];
    const float* beta1  = (const float*)d_in[6];
    const float* g2     = (const float*)d_in[7];
    const float* beta2  = (const float*)d_in[8];
    const float* w1     = (const float*)d_in[9];
    const float* bm1    = (const float*)d_in[10];
    const float* w2     = (const float*)d_in[11];
    const float* bm2    = (const float*)d_in[12];
    float* out = (float*)d_out;

    float *ln1, *q, *k, *v, *o, *y, *h2, *f;
    cudaGetSymbolAddress((void**)&ln1, g_ln1);
    cudaGetSymbolAddress((void**)&q,   g_q);
    cudaGetSymbolAddress((void**)&k,   g_k);
    cudaGetSymbolAddress((void**)&v,   g_v);
    cudaGetSymbolAddress((void**)&o,   g_o);
    cudaGetSymbolAddress((void**)&y,   g_y);
    cudaGetSymbolAddress((void**)&h2,  g_h2);
    cudaGetSymbolAddress((void**)&f,   g_f);

    const int FLASH_SMEM = 4*64*FST*4;
    cudaFuncSetAttribute(flash_attn,
        cudaFuncAttributeMaxDynamicSharedMemorySize, FLASH_SMEM);

    // 1) LN1
    layernorm_rows<<<Mrows, 128>>>(x, ln1, g1, beta1);

    // 2) QKV (tf32) with scatter: M=4096, N=1536, K=512
    {
        dim3 grid(1536/128, Mrows/128);
        gemm_tf32<5><<<grid, 256>>>(ln1, w_qkv, q, k, v,
                                    Cc, Cc, Cc, 0, nullptr, nullptr);
    }

    // 3) Fused attention (fp32)
    {
        dim3 grid(Nn_/64, BH);
        flash_attn<<<grid, 256, FLASH_SMEM>>>(q, k, v, mask, o);
    }

    // 4) proj + bias + residual (tf32)
    {
        dim3 grid(Cc/128, Mrows/128);
        gemm_tf32<3><<<grid, 256>>>(o, w_proj, y, nullptr, nullptr,
                                    Cc, Cc, Cc, Cc, b_proj, x);
    }

    // 5) LN2
    layernorm_rows<<<Mrows, 128>>>(y, h2, g2, beta2);

    // 6) FFN1 + bias + gelu (tf32)
    {
        dim3 grid(DFF/128, Mrows/128);
        gemm_tf32<2><<<grid, 256>>>(h2, w1, f, nullptr, nullptr,
                                    Cc, Cc, Cc, DFF, bm1, nullptr);
    }

    // 7) FFN2 + bias + residual (tf32)
    {
        dim3 grid(Cc/128, Mrows/128);
        gemm_tf32<3><<<grid, 256>>>(f, w2, out, nullptr, nullptr,
                                    DFF, DFF, DFF, Cc, bm2, y);
    }

    (void)in_sizes; (void)n_in; (void)out_size;
}

// round 8
// speedup vs baseline: 2.5949x; 1.6463x over previous
#include <cuda_runtime.h>
#include <math.h>
#include <stdint.h>

// ---------------------------------------------------------------------------
// Problem constants
// ---------------------------------------------------------------------------
#define Bb   2
#define Nn_  2048
#define Cc   512
#define Hh   8
#define HD   64
#define DFF  2048
#define Mrows (Bb*Nn_)          // 4096
#define BH   (Bb*Hh)            // 16

// ---------------------------------------------------------------------------
// Device scratch (static allocation — no cudaMalloc allowed).  88 MB total.
// ---------------------------------------------------------------------------
__device__ float g_ln1[Mrows*Cc];
__device__ float g_q  [BH*Nn_*HD];
__device__ float g_k  [BH*Nn_*HD];
__device__ float g_v  [BH*Nn_*HD];
__device__ float g_o  [Mrows*Cc];
__device__ float g_y  [Mrows*Cc];
__device__ float g_h2 [Mrows*Cc];
__device__ float g_f  [Mrows*DFF];

// ---------------------------------------------------------------------------
// TF32 helpers (conventions validated by the passing R3/R4 GEMM)
// ---------------------------------------------------------------------------
__device__ __forceinline__ uint32_t f2tf32(float x) {
    uint32_t r;
    asm("cvt.rna.tf32.f32 %0, %1;" : "=r"(r) : "f"(x));
    return r;
}

__device__ __forceinline__ void mma_tf32(float* d, const uint32_t* a, const uint32_t* b) {
    asm volatile(
        "mma.sync.aligned.m16n8k8.row.col.f32.tf32.tf32.f32 "
        "{%0,%1,%2,%3}, {%4,%5,%6,%7}, {%8,%9}, {%0,%1,%2,%3};"
        : "+f"(d[0]), "+f"(d[1]), "+f"(d[2]), "+f"(d[3])
        : "r"(a[0]), "r"(a[1]), "r"(a[2]), "r"(a[3]), "r"(b[0]), "r"(b[1]));
}

// ---------------------------------------------------------------------------
// LayerNorm: one block (128 thr) per row of 512
// ---------------------------------------------------------------------------
__global__ __launch_bounds__(128)
void layernorm_rows(const float* __restrict__ X, float* __restrict__ Y,
                    const float* __restrict__ g, const float* __restrict__ b)
{
    int row = blockIdx.x;
    int tid = threadIdx.x;
    const float* x = X + (size_t)row * Cc;
    float4 v = *reinterpret_cast<const float4*>(x + tid*4);

    __shared__ float red[128];
    red[tid] = v.x + v.y + v.z + v.w;
    __syncthreads();
    #pragma unroll
    for (int s = 64; s > 0; s >>= 1) {
        if (tid < s) red[tid] += red[tid+s];
        __syncthreads();
    }
    float mu = red[0] * (1.0f/Cc);
    __syncthreads();

    float dx = v.x-mu, dy = v.y-mu, dz = v.z-mu, dw = v.w-mu;
    red[tid] = dx*dx + dy*dy + dz*dz + dw*dw;
    __syncthreads();
    #pragma unroll
    for (int s = 64; s > 0; s >>= 1) {
        if (tid < s) red[tid] += red[tid+s];
        __syncthreads();
    }
    float var = red[0] * (1.0f/Cc);
    float r = rsqrtf(var + 1e-5f);

    float4 gg = *reinterpret_cast<const float4*>(g + tid*4);
    float4 bb = *reinterpret_cast<const float4*>(b + tid*4);
    float4 o;
    o.x = dx*r*gg.x + bb.x;
    o.y = dy*r*gg.y + bb.y;
    o.z = dz*r*gg.z + bb.z;
    o.w = dw*r*gg.w + bb.w;
    *reinterpret_cast<float4*>(Y + (size_t)row*Cc + tid*4) = o;
}

// ---------------------------------------------------------------------------
// Tensor-core flash attention (tf32), SMEM-lean variant.
//   Grid: (N/64, BH).  Block: 256 thr = 8 warps in 4x2 (wm x wn).
//   S tile 64x64 via m16n8k8; online softmax with 2-way cross-warp combine.
//   P ALIASES the K tile: every warp's S-mma reads of sK finish before the
//   smax barrier; P is written only after it; next iteration's K load lands
//   after the loop-top barrier that follows the PV reads.  53 KB dyn SMEM.
// ---------------------------------------------------------------------------
#define AST 68   // u32 stride for sQ/sK/sVt

__global__ __launch_bounds__(256)
void flash_attn_tc(const float* __restrict__ Q, const float* __restrict__ K,
                   const float* __restrict__ V, const float* __restrict__ mask,
                   float* __restrict__ O)
{
    extern __shared__ uint32_t smu[];
    uint32_t* sQ  = smu;                 // [64][AST]
    uint32_t* sK  = sQ  + 64*AST;        // aliased by P after smax barrier
    uint32_t* sVt = sK  + 64*AST;        // [d][j]
    uint32_t* sP  = sK;                  // ALIAS
    float*    smax = (float*)(sVt + 64*AST); // [2][64]
    float*    ssum = smax + 128;             // [2][64]

    int tid  = threadIdx.x;
    int lane = tid & 31;
    int w    = tid >> 5;
    int wm   = (w >> 1) * 16;     // 0,16,32,48
    int cw   = w & 1;             // column-warp id
    int wn   = cw * 32;
    int rg   = lane >> 2;         // 0..7
    int cq   = lane & 3;          // 0..3

    int q0 = blockIdx.x * 64;
    int bh = blockIdx.y;
    int b  = bh >> 3, hh = bh & 7;

    const float* Qb = Q + ((size_t)bh*Nn_ + q0)*HD;
    const float* Kb = K + (size_t)bh*Nn_*HD;
    const float* Vb = V + (size_t)bh*Nn_*HD;

    // Load Q tile once (tf32)
    #pragma unroll
    for (int i = 0; i < 4; i++) {
        int f  = tid + i*256;
        int r  = f >> 4;
        int c4 = (f & 15) << 2;
        float4 v = *reinterpret_cast<const float4*>(Qb + r*HD + c4);
        uint4 u = { f2tf32(v.x), f2tf32(v.y), f2tf32(v.z), f2tf32(v.w) };
        *reinterpret_cast<uint4*>(&sQ[r*AST + c4]) = u;
    }

    float oacc[4][4];
    #pragma unroll
    for (int nt = 0; nt < 4; nt++)
        #pragma unroll
        for (int c = 0; c < 4; c++) oacc[nt][c] = 0.0f;
    float rmax0 = -1e30f, rmax1 = -1e30f, rsum0 = 0.0f, rsum1 = 0.0f;

    int row0 = wm + rg;
    int row1 = wm + rg + 8;

    for (int kt = 0; kt < Nn_; kt += 64) {
        __syncthreads();   // prior-iter PV reads of sP(=sK) and sVt complete
        // Load K (natural [j][d]) and V (transposed [d][j]) as tf32
        #pragma unroll
        for (int i = 0; i < 4; i++) {
            int f  = tid + i*256;
            int r  = f >> 4;
            int c4 = (f & 15) << 2;
            float4 kv = *reinterpret_cast<const float4*>(Kb + (size_t)(kt+r)*HD + c4);
            uint4 uk = { f2tf32(kv.x), f2tf32(kv.y), f2tf32(kv.z), f2tf32(kv.w) };
            *reinterpret_cast<uint4*>(&sK[r*AST + c4]) = uk;
            float4 vv = *reinterpret_cast<const float4*>(Vb + (size_t)(kt+r)*HD + c4);
            sVt[(c4+0)*AST + r] = f2tf32(vv.x);
            sVt[(c4+1)*AST + r] = f2tf32(vv.y);
            sVt[(c4+2)*AST + r] = f2tf32(vv.z);
            sVt[(c4+3)*AST + r] = f2tf32(vv.w);
        }
        __syncthreads();

        // S = Q @ K^T   (all sK reads happen in this block)
        float sc[4][4];
        #pragma unroll
        for (int nt = 0; nt < 4; nt++)
            #pragma unroll
            for (int c = 0; c < 4; c++) sc[nt][c] = 0.0f;
        #pragma unroll
        for (int ks = 0; ks < 8; ks++) {
            int ko = ks*8;
            uint32_t a[4];
            a[0] = sQ[row0*AST + ko + cq];
            a[1] = sQ[row1*AST + ko + cq];
            a[2] = sQ[row0*AST + ko + cq + 4];
            a[3] = sQ[row1*AST + ko + cq + 4];
            #pragma unroll
            for (int nt = 0; nt < 4; nt++) {
                int key = wn + nt*8 + rg;
                uint32_t bf[2];
                bf[0] = sK[key*AST + ko + cq];
                bf[1] = sK[key*AST + ko + cq + 4];
                mma_tf32(sc[nt], a, bf);
            }
        }

        // scale * multiplicative mask
        #pragma unroll
        for (int nt = 0; nt < 4; nt++) {
            int colg = kt + wn + nt*8 + 2*cq;
            float2 m0 = *reinterpret_cast<const float2*>(mask + (size_t)(q0+row0)*Nn_ + colg);
            float2 m1 = *reinterpret_cast<const float2*>(mask + (size_t)(q0+row1)*Nn_ + colg);
            sc[nt][0] *= 0.125f * m0.x;
            sc[nt][1] *= 0.125f * m0.y;
            sc[nt][2] *= 0.125f * m1.x;
            sc[nt][3] *= 0.125f * m1.y;
        }

        // row-max: quad reduce then cross-warp combine
        float mx0 = -1e30f, mx1 = -1e30f;
        #pragma unroll
        for (int nt = 0; nt < 4; nt++) {
            mx0 = fmaxf(mx0, fmaxf(sc[nt][0], sc[nt][1]));
            mx1 = fmaxf(mx1, fmaxf(sc[nt][2], sc[nt][3]));
        }
        #pragma unroll
        for (int off = 1; off <= 2; off <<= 1) {
            mx0 = fmaxf(mx0, __shfl_xor_sync(0xffffffffu, mx0, off));
            mx1 = fmaxf(mx1, __shfl_xor_sync(0xffffffffu, mx1, off));
        }
        if (cq == 0) {
            smax[cw*64 + row0] = mx0;
            smax[cw*64 + row1] = mx1;
        }
        __syncthreads();   // smax visible; ALL sK reads complete => P may alias
        float tmax0 = fmaxf(smax[row0], smax[64 + row0]);
        float tmax1 = fmaxf(smax[row1], smax[64 + row1]);
        float nm0 = fmaxf(rmax0, tmax0);
        float nm1 = fmaxf(rmax1, tmax1);
        float corr0 = __expf(rmax0 - nm0);
        float corr1 = __expf(rmax1 - nm1);
        rmax0 = nm0; rmax1 = nm1;

        // exp, partial sums, P store (into sK's storage)
        float ps0 = 0.0f, ps1 = 0.0f;
        #pragma unroll
        for (int nt = 0; nt < 4; nt++) {
            sc[nt][0] = __expf(sc[nt][0] - nm0);
            sc[nt][1] = __expf(sc[nt][1] - nm0);
            sc[nt][2] = __expf(sc[nt][2] - nm1);
            sc[nt][3] = __expf(sc[nt][3] - nm1);
            ps0 += sc[nt][0] + sc[nt][1];
            ps1 += sc[nt][2] + sc[nt][3];
            int colp = wn + nt*8 + 2*cq;
            sP[row0*AST + colp    ] = f2tf32(sc[nt][0]);
            sP[row0*AST + colp + 1] = f2tf32(sc[nt][1]);
            sP[row1*AST + colp    ] = f2tf32(sc[nt][2]);
            sP[row1*AST + colp + 1] = f2tf32(sc[nt][3]);
        }
        #pragma unroll
        for (int off = 1; off <= 2; off <<= 1) {
            ps0 += __shfl_xor_sync(0xffffffffu, ps0, off);
            ps1 += __shfl_xor_sync(0xffffffffu, ps1, off);
        }
        if (cq == 0) {
            ssum[cw*64 + row0] = ps0;
            ssum[cw*64 + row1] = ps1;
        }
        // rescale O accumulators
        #pragma unroll
        for (int nt = 0; nt < 4; nt++) {
            oacc[nt][0] *= corr0;
            oacc[nt][1] *= corr0;
            oacc[nt][2] *= corr1;
            oacc[nt][3] *= corr1;
        }
        __syncthreads();   // ssum + sP visible
        rsum0 = rsum0*corr0 + ssum[row0] + ssum[64 + row0];
        rsum1 = rsum1*corr1 + ssum[row1] + ssum[64 + row1];

        // O += P @ V   (B operand = V^T stored [d][j])
        #pragma unroll
        for (int ks = 0; ks < 8; ks++) {
            int ko = ks*8;
            uint32_t a[4];
            a[0] = sP[row0*AST + ko + cq];
            a[1] = sP[row1*AST + ko + cq];
            a[2] = sP[row0*AST + ko + cq + 4];
            a[3] = sP[row1*AST + ko + cq + 4];
            #pragma unroll
            for (int nt = 0; nt < 4; nt++) {
                int d = wn + nt*8 + rg;
                uint32_t bf[2];
                bf[0] = sVt[d*AST + ko + cq];
                bf[1] = sVt[d*AST + ko + cq + 4];
                mma_tf32(oacc[nt], a, bf);
            }
        }
    }

    // epilogue: normalize, scatter into [B*N, C]
    float inv0 = 1.0f / rsum0;
    float inv1 = 1.0f / rsum1;
    #pragma unroll
    for (int nt = 0; nt < 4; nt++) {
        int col = hh*HD + wn + nt*8 + 2*cq;
        size_t m0g = (size_t)(b*Nn_ + q0 + row0);
        size_t m1g = (size_t)(b*Nn_ + q0 + row1);
        float2 o0; o0.x = oacc[nt][0]*inv0; o0.y = oacc[nt][1]*inv0;
        float2 o1; o1.x = oacc[nt][2]*inv1; o1.y = oacc[nt][3]*inv1;
        *reinterpret_cast<float2*>(O + m0g*Cc + col) = o0;
        *reinterpret_cast<float2*>(O + m1g*Cc + col) = o1;
    }
}

// ---------------------------------------------------------------------------
// TF32 tensor-core GEMM (unchanged from passing R3/R4 kernel)
// ---------------------------------------------------------------------------
#define GST 36

template<int EPI>
__global__ __launch_bounds__(256)
void gemm_tf32(const float* __restrict__ A, const float* __restrict__ B,
               float* __restrict__ C, float* __restrict__ C2, float* __restrict__ C3,
               int K, int lda, int ldb, int ldc,
               const float* __restrict__ bias, const float* __restrict__ res)
{
    __shared__ __align__(16) uint32_t As[128*GST];
    __shared__ __align__(16) uint32_t Bs[128*GST];

    int tid  = threadIdx.x;
    int lane = tid & 31;
    int w    = tid >> 5;
    int wm   = (w >> 2) * 64;
    int wn   = (w & 3)  * 32;
    int r    = lane >> 2;
    int cq   = lane & 3;
    int m0   = blockIdx.y * 128;
    int n0   = blockIdx.x * 128;

    float acc[16][4];
    #pragma unroll
    for (int i = 0; i < 16; i++)
        #pragma unroll
        for (int j = 0; j < 4; j++) acc[i][j] = 0.0f;

    float4 pa[4], pb[4];
    #pragma unroll
    for (int i = 0; i < 4; i++) {
        int f = tid + i*256;
        int ar = f >> 3, ac4 = (f & 7) << 2;
        pa[i] = *reinterpret_cast<const float4*>(A + (size_t)(m0+ar)*lda + ac4);
        pb[i] = *reinterpret_cast<const float4*>(B + (size_t)(n0+ar)*ldb + ac4);
    }

    for (int kt = 0; kt < K; kt += 32) {
        #pragma unroll
        for (int i = 0; i < 4; i++) {
            int f = tid + i*256;
            int ar = f >> 3, ac4 = (f & 7) << 2;
            uint4 ua = { f2tf32(pa[i].x), f2tf32(pa[i].y), f2tf32(pa[i].z), f2tf32(pa[i].w) };
            *reinterpret_cast<uint4*>(&As[ar*GST + ac4]) = ua;
            uint4 ub = { f2tf32(pb[i].x), f2tf32(pb[i].y), f2tf32(pb[i].z), f2tf32(pb[i].w) };
            *reinterpret_cast<uint4*>(&Bs[ar*GST + ac4]) = ub;
        }
        __syncthreads();

        if (kt + 32 < K) {
            #pragma unroll
            for (int i = 0; i < 4; i++) {
                int f = tid + i*256;
                int ar = f >> 3, ac4 = (f & 7) << 2;
                pa[i] = *reinterpret_cast<const float4*>(A + (size_t)(m0+ar)*lda + kt+32 + ac4);
                pb[i] = *reinterpret_cast<const float4*>(B + (size_t)(n0+ar)*ldb + kt+32 + ac4);
            }
        }

        #pragma unroll
        for (int ks = 0; ks < 4; ks++) {
            int koff = ks * 8;
            uint32_t af[4][4];
            #pragma unroll
            for (int mt = 0; mt < 4; mt++) {
                int mr = wm + mt*16;
                af[mt][0] = As[(mr+r  )*GST + koff + cq];
                af[mt][1] = As[(mr+r+8)*GST + koff + cq];
                af[mt][2] = As[(mr+r  )*GST + koff + cq + 4];
                af[mt][3] = As[(mr+r+8)*GST + koff + cq + 4];
            }
            uint32_t bf[4][2];
            #pragma unroll
            for (int nt = 0; nt < 4; nt++) {
                int nr = wn + nt*8;
                bf[nt][0] = Bs[(nr+r)*GST + koff + cq];
                bf[nt][1] = Bs[(nr+r)*GST + koff + cq + 4];
            }
            #pragma unroll
            for (int mt = 0; mt < 4; mt++)
                #pragma unroll
                for (int nt = 0; nt < 4; nt++)
                    mma_tf32(acc[mt*4+nt], af[mt], bf[nt]);
        }
        __syncthreads();
    }

    #pragma unroll
    for (int mt = 0; mt < 4; mt++) {
        #pragma unroll
        for (int nt = 0; nt < 4; nt++) {
            const float* a4 = acc[mt*4+nt];
            int n = n0 + wn + nt*8 + 2*cq;
            #pragma unroll
            for (int p = 0; p < 2; p++) {
                int m = m0 + wm + mt*16 + r + 8*p;
                float v0 = a4[2*p+0];
                float v1 = a4[2*p+1];
                if (EPI == 2) {
                    float t0 = v0 + bias[n];
                    float t1 = v1 + bias[n+1];
                    float2 o2;
                    o2.x = 0.5f * t0 * (1.0f + erff(t0 * 0.70710678118654752f));
                    o2.y = 0.5f * t1 * (1.0f + erff(t1 * 0.70710678118654752f));
                    *reinterpret_cast<float2*>(C + (size_t)m*ldc + n) = o2;
                } else if (EPI == 3) {
                    float2 rr = *reinterpret_cast<const float2*>(res + (size_t)m*ldc + n);
                    float2 o2;
                    o2.x = v0 + bias[n]   + rr.x;
                    o2.y = v1 + bias[n+1] + rr.y;
                    *reinterpret_cast<float2*>(C + (size_t)m*ldc + n) = o2;
                } else if (EPI == 5) {
                    int kind = n >> 9;
                    int ww   = n & 511;
                    int hh   = ww >> 6;
                    int d    = ww & 63;
                    int b    = m >> 11;
                    int ntok = m & 2047;
                    size_t base = (((size_t)(b*Hh + hh))*Nn_ + ntok)*HD + d;
                    float2 o2; o2.x = v0; o2.y = v1;
                    if      (kind == 0) *reinterpret_cast<float2*>(C  + base) = o2;
                    else if (kind == 1) *reinterpret_cast<float2*>(C2 + base) = o2;
                    else                *reinterpret_cast<float2*>(C3 + base) = o2;
                }
            }
        }
    }
}

// ---------------------------------------------------------------------------
// Launch
// ---------------------------------------------------------------------------
extern "C" void kernel_launch(void* const* d_in, const int* in_sizes, int n_in,
                              void* d_out, int out_size)
{
    const float* x      = (const float*)d_in[0];
    const float* mask   = (const float*)d_in[1];
    const float* w_qkv  = (const float*)d_in[2];
    const float* w_proj = (const float*)d_in[3];
    const float* b_proj = (const float*)d_in[4];
    const float* g1     = (const float*)d_in[5];
    const float* beta1  = (const float*)d_in[6];
    const float* g2     = (const float*)d_in[7];
    const float* beta2  = (const float*)d_in[8];
    const float* w1     = (const float*)d_in[9];
    const float* bm1    = (const float*)d_in[10];
    const float* w2     = (const float*)d_in[11];
    const float* bm2    = (const float*)d_in[12];
    float* out = (float*)d_out;

    float *ln1, *q, *k, *v, *o, *y, *h2, *f;
    cudaGetSymbolAddress((void**)&ln1, g_ln1);
    cudaGetSymbolAddress((void**)&q,   g_q);
    cudaGetSymbolAddress((void**)&k,   g_k);
    cudaGetSymbolAddress((void**)&v,   g_v);
    cudaGetSymbolAddress((void**)&o,   g_o);
    cudaGetSymbolAddress((void**)&y,   g_y);
    cudaGetSymbolAddress((void**)&h2,  g_h2);
    cudaGetSymbolAddress((void**)&f,   g_f);

    const int FLASH_SMEM = (3*64*AST)*4 + 256*4;  // 53248 B (P aliases K tile)
    cudaFuncSetAttribute(flash_attn_tc,
        cudaFuncAttributeMaxDynamicSharedMemorySize, FLASH_SMEM);

    // 1) LN1
    layernorm_rows<<<Mrows, 128>>>(x, ln1, g1, beta1);

    // 2) QKV (tf32) with scatter: M=4096, N=1536, K=512
    {
        dim3 grid(1536/128, Mrows/128);
        gemm_tf32<5><<<grid, 256>>>(ln1, w_qkv, q, k, v,
                                    Cc, Cc, Cc, 0, nullptr, nullptr);
    }

    // 3) Fused attention (tf32 tensor cores)
    {
        dim3 grid(Nn_/64, BH);
        flash_attn_tc<<<grid, 256, FLASH_SMEM>>>(q, k, v, mask, o);
    }

    // 4) proj + bias + residual (tf32)
    {
        dim3 grid(Cc/128, Mrows/128);
        gemm_tf32<3><<<grid, 256>>>(o, w_proj, y, nullptr, nullptr,
                                    Cc, Cc, Cc, Cc, b_proj, x);
    }

    // 5) LN2
    layernorm_rows<<<Mrows, 128>>>(y, h2, g2, beta2);

    // 6) FFN1 + bias + gelu (tf32)
    {
        dim3 grid(DFF/128, Mrows/128);
        gemm_tf32<2><<<grid, 256>>>(h2, w1, f, nullptr, nullptr,
                                    Cc, Cc, Cc, DFF, bm1, nullptr);
    }

    // 7) FFN2 + bias + residual (tf32)
    {
        dim3 grid(Cc/128, Mrows/128);
        gemm_tf32<3><<<grid, 256>>>(f, w2, out, nullptr, nullptr,
                                    DFF, DFF, DFF, Cc, bm2, y);
    }

    (void)in_sizes; (void)n_in; (void)out_size;
}

// round 10
// speedup vs baseline: 2.6827x; 1.0338x over previous
#include <cuda_runtime.h>
#include <math.h>
#include <stdint.h>

// ---------------------------------------------------------------------------
// Problem constants
// ---------------------------------------------------------------------------
#define Bb   2
#define Nn_  2048
#define Cc   512
#define Hh   8
#define HD   64
#define DFF  2048
#define Mrows (Bb*Nn_)          // 4096
#define BH   (Bb*Hh)            // 16

// ---------------------------------------------------------------------------
// Device scratch (static allocation — no cudaMalloc allowed).  88 MB total.
// ---------------------------------------------------------------------------
__device__ float g_ln1[Mrows*Cc];
__device__ float g_q  [BH*Nn_*HD];
__device__ float g_k  [BH*Nn_*HD];
__device__ float g_v  [BH*Nn_*HD];
__device__ float g_o  [Mrows*Cc];
__device__ float g_y  [Mrows*Cc];
__device__ float g_h2 [Mrows*Cc];
__device__ float g_f  [Mrows*DFF];

// ---------------------------------------------------------------------------
// TF32 helpers
// ---------------------------------------------------------------------------
__device__ __forceinline__ uint32_t f2tf32(float x) {
    uint32_t r;
    asm("cvt.rna.tf32.f32 %0, %1;" : "=r"(r) : "f"(x));
    return r;
}

__device__ __forceinline__ void mma_tf32(float* d, const uint32_t* a, const uint32_t* b) {
    asm volatile(
        "mma.sync.aligned.m16n8k8.row.col.f32.tf32.tf32.f32 "
        "{%0,%1,%2,%3}, {%4,%5,%6,%7}, {%8,%9}, {%0,%1,%2,%3};"
        : "+f"(d[0]), "+f"(d[1]), "+f"(d[2]), "+f"(d[3])
        : "r"(a[0]), "r"(a[1]), "r"(a[2]), "r"(a[3]), "r"(b[0]), "r"(b[1]));
}

__device__ __forceinline__ void ldsm_x4(uint32_t& r0, uint32_t& r1,
                                        uint32_t& r2, uint32_t& r3, uint32_t addr) {
    asm volatile("ldmatrix.sync.aligned.m8n8.x4.shared.b16 {%0,%1,%2,%3}, [%4];"
                 : "=r"(r0), "=r"(r1), "=r"(r2), "=r"(r3) : "r"(addr));
}

// ---------------------------------------------------------------------------
// LayerNorm: one block (128 thr) per row of 512   (unchanged, passing)
// ---------------------------------------------------------------------------
__global__ __launch_bounds__(128)
void layernorm_rows(const float* __restrict__ X, float* __restrict__ Y,
                    const float* __restrict__ g, const float* __restrict__ b)
{
    int row = blockIdx.x;
    int tid = threadIdx.x;
    const float* x = X + (size_t)row * Cc;
    float4 v = *reinterpret_cast<const float4*>(x + tid*4);

    __shared__ float red[128];
    red[tid] = v.x + v.y + v.z + v.w;
    __syncthreads();
    #pragma unroll
    for (int s = 64; s > 0; s >>= 1) {
        if (tid < s) red[tid] += red[tid+s];
        __syncthreads();
    }
    float mu = red[0] * (1.0f/Cc);
    __syncthreads();

    float dx = v.x-mu, dy = v.y-mu, dz = v.z-mu, dw = v.w-mu;
    red[tid] = dx*dx + dy*dy + dz*dz + dw*dw;
    __syncthreads();
    #pragma unroll
    for (int s = 64; s > 0; s >>= 1) {
        if (tid < s) red[tid] += red[tid+s];
        __syncthreads();
    }
    float var = red[0] * (1.0f/Cc);
    float r = rsqrtf(var + 1e-5f);

    float4 gg = *reinterpret_cast<const float4*>(g + tid*4);
    float4 bb = *reinterpret_cast<const float4*>(b + tid*4);
    float4 o;
    o.x = dx*r*gg.x + bb.x;
    o.y = dy*r*gg.y + bb.y;
    o.z = dz*r*gg.z + bb.z;
    o.w = dw*r*gg.w + bb.w;
    *reinterpret_cast<float4*>(Y + (size_t)row*Cc + tid*4) = o;
}

// ---------------------------------------------------------------------------
// Tensor-core flash attention (tf32) — byte-identical to passing R8 kernel.
// ---------------------------------------------------------------------------
#define AST 68   // u32 stride for sQ/sK/sVt

__global__ __launch_bounds__(256)
void flash_attn_tc(const float* __restrict__ Q, const float* __restrict__ K,
                   const float* __restrict__ V, const float* __restrict__ mask,
                   float* __restrict__ O)
{
    extern __shared__ uint32_t smu[];
    uint32_t* sQ  = smu;                 // [64][AST]
    uint32_t* sK  = sQ  + 64*AST;        // aliased by P after smax barrier
    uint32_t* sVt = sK  + 64*AST;        // [d][j]
    uint32_t* sP  = sK;                  // ALIAS
    float*    smax = (float*)(sVt + 64*AST); // [2][64]
    float*    ssum = smax + 128;             // [2][64]

    int tid  = threadIdx.x;
    int lane = tid & 31;
    int w    = tid >> 5;
    int wm   = (w >> 1) * 16;
    int cw   = w & 1;
    int wn   = cw * 32;
    int rg   = lane >> 2;
    int cq   = lane & 3;

    int q0 = blockIdx.x * 64;
    int bh = blockIdx.y;
    int b  = bh >> 3, hh = bh & 7;

    const float* Qb = Q + ((size_t)bh*Nn_ + q0)*HD;
    const float* Kb = K + (size_t)bh*Nn_*HD;
    const float* Vb = V + (size_t)bh*Nn_*HD;

    #pragma unroll
    for (int i = 0; i < 4; i++) {
        int f  = tid + i*256;
        int r  = f >> 4;
        int c4 = (f & 15) << 2;
        float4 v = *reinterpret_cast<const float4*>(Qb + r*HD + c4);
        uint4 u = { f2tf32(v.x), f2tf32(v.y), f2tf32(v.z), f2tf32(v.w) };
        *reinterpret_cast<uint4*>(&sQ[r*AST + c4]) = u;
    }

    float oacc[4][4];
    #pragma unroll
    for (int nt = 0; nt < 4; nt++)
        #pragma unroll
        for (int c = 0; c < 4; c++) oacc[nt][c] = 0.0f;
    float rmax0 = -1e30f, rmax1 = -1e30f, rsum0 = 0.0f, rsum1 = 0.0f;

    int row0 = wm + rg;
    int row1 = wm + rg + 8;

    for (int kt = 0; kt < Nn_; kt += 64) {
        __syncthreads();
        #pragma unroll
        for (int i = 0; i < 4; i++) {
            int f  = tid + i*256;
            int r  = f >> 4;
            int c4 = (f & 15) << 2;
            float4 kv = *reinterpret_cast<const float4*>(Kb + (size_t)(kt+r)*HD + c4);
            uint4 uk = { f2tf32(kv.x), f2tf32(kv.y), f2tf32(kv.z), f2tf32(kv.w) };
            *reinterpret_cast<uint4*>(&sK[r*AST + c4]) = uk;
            float4 vv = *reinterpret_cast<const float4*>(Vb + (size_t)(kt+r)*HD + c4);
            sVt[(c4+0)*AST + r] = f2tf32(vv.x);
            sVt[(c4+1)*AST + r] = f2tf32(vv.y);
            sVt[(c4+2)*AST + r] = f2tf32(vv.z);
            sVt[(c4+3)*AST + r] = f2tf32(vv.w);
        }
        __syncthreads();

        float sc[4][4];
        #pragma unroll
        for (int nt = 0; nt < 4; nt++)
            #pragma unroll
            for (int c = 0; c < 4; c++) sc[nt][c] = 0.0f;
        #pragma unroll
        for (int ks = 0; ks < 8; ks++) {
            int ko = ks*8;
            uint32_t a[4];
            a[0] = sQ[row0*AST + ko + cq];
            a[1] = sQ[row1*AST + ko + cq];
            a[2] = sQ[row0*AST + ko + cq + 4];
            a[3] = sQ[row1*AST + ko + cq + 4];
            #pragma unroll
            for (int nt = 0; nt < 4; nt++) {
                int key = wn + nt*8 + rg;
                uint32_t bf[2];
                bf[0] = sK[key*AST + ko + cq];
                bf[1] = sK[key*AST + ko + cq + 4];
                mma_tf32(sc[nt], a, bf);
            }
        }

        #pragma unroll
        for (int nt = 0; nt < 4; nt++) {
            int colg = kt + wn + nt*8 + 2*cq;
            float2 m0 = *reinterpret_cast<const float2*>(mask + (size_t)(q0+row0)*Nn_ + colg);
            float2 m1 = *reinterpret_cast<const float2*>(mask + (size_t)(q0+row1)*Nn_ + colg);
            sc[nt][0] *= 0.125f * m0.x;
            sc[nt][1] *= 0.125f * m0.y;
            sc[nt][2] *= 0.125f * m1.x;
            sc[nt][3] *= 0.125f * m1.y;
        }

        float mx0 = -1e30f, mx1 = -1e30f;
        #pragma unroll
        for (int nt = 0; nt < 4; nt++) {
            mx0 = fmaxf(mx0, fmaxf(sc[nt][0], sc[nt][1]));
            mx1 = fmaxf(mx1, fmaxf(sc[nt][2], sc[nt][3]));
        }
        #pragma unroll
        for (int off = 1; off <= 2; off <<= 1) {
            mx0 = fmaxf(mx0, __shfl_xor_sync(0xffffffffu, mx0, off));
            mx1 = fmaxf(mx1, __shfl_xor_sync(0xffffffffu, mx1, off));
        }
        if (cq == 0) {
            smax[cw*64 + row0] = mx0;
            smax[cw*64 + row1] = mx1;
        }
        __syncthreads();
        float tmax0 = fmaxf(smax[row0], smax[64 + row0]);
        float tmax1 = fmaxf(smax[row1], smax[64 + row1]);
        float nm0 = fmaxf(rmax0, tmax0);
        float nm1 = fmaxf(rmax1, tmax1);
        float corr0 = __expf(rmax0 - nm0);
        float corr1 = __expf(rmax1 - nm1);
        rmax0 = nm0; rmax1 = nm1;

        float ps0 = 0.0f, ps1 = 0.0f;
        #pragma unroll
        for (int nt = 0; nt < 4; nt++) {
            sc[nt][0] = __expf(sc[nt][0] - nm0);
            sc[nt][1] = __expf(sc[nt][1] - nm0);
            sc[nt][2] = __expf(sc[nt][2] - nm1);
            sc[nt][3] = __expf(sc[nt][3] - nm1);
            ps0 += sc[nt][0] + sc[nt][1];
            ps1 += sc[nt][2] + sc[nt][3];
            int colp = wn + nt*8 + 2*cq;
            sP[row0*AST + colp    ] = f2tf32(sc[nt][0]);
            sP[row0*AST + colp + 1] = f2tf32(sc[nt][1]);
            sP[row1*AST + colp    ] = f2tf32(sc[nt][2]);
            sP[row1*AST + colp + 1] = f2tf32(sc[nt][3]);
        }
        #pragma unroll
        for (int off = 1; off <= 2; off <<= 1) {
            ps0 += __shfl_xor_sync(0xffffffffu, ps0, off);
            ps1 += __shfl_xor_sync(0xffffffffu, ps1, off);
        }
        if (cq == 0) {
            ssum[cw*64 + row0] = ps0;
            ssum[cw*64 + row1] = ps1;
        }
        #pragma unroll
        for (int nt = 0; nt < 4; nt++) {
            oacc[nt][0] *= corr0;
            oacc[nt][1] *= corr0;
            oacc[nt][2] *= corr1;
            oacc[nt][3] *= corr1;
        }
        __syncthreads();
        rsum0 = rsum0*corr0 + ssum[row0] + ssum[64 + row0];
        rsum1 = rsum1*corr1 + ssum[row1] + ssum[64 + row1];

        #pragma unroll
        for (int ks = 0; ks < 8; ks++) {
            int ko = ks*8;
            uint32_t a[4];
            a[0] = sP[row0*AST + ko + cq];
            a[1] = sP[row1*AST + ko + cq];
            a[2] = sP[row0*AST + ko + cq + 4];
            a[3] = sP[row1*AST + ko + cq + 4];
            #pragma unroll
            for (int nt = 0; nt < 4; nt++) {
                int d = wn + nt*8 + rg;
                uint32_t bf[2];
                bf[0] = sVt[d*AST + ko + cq];
                bf[1] = sVt[d*AST + ko + cq + 4];
                mma_tf32(oacc[nt], a, bf);
            }
        }
    }

    float inv0 = 1.0f / rsum0;
    float inv1 = 1.0f / rsum1;
    #pragma unroll
    for (int nt = 0; nt < 4; nt++) {
        int col = hh*HD + wn + nt*8 + 2*cq;
        size_t m0g = (size_t)(b*Nn_ + q0 + row0);
        size_t m1g = (size_t)(b*Nn_ + q0 + row1);
        float2 o0; o0.x = oacc[nt][0]*inv0; o0.y = oacc[nt][1]*inv0;
        float2 o1; o1.x = oacc[nt][2]*inv1; o1.y = oacc[nt][3]*inv1;
        *reinterpret_cast<float2*>(O + m0g*Cc + col) = o0;
        *reinterpret_cast<float2*>(O + m1g*Cc + col) = o1;
    }
}

// ---------------------------------------------------------------------------
// TF32 GEMM v2: ldmatrix fragments + double-buffered SMEM (1 sync/K-tile).
//   C[m,n] = sum_k A[m,k]*B[n,k].  Block 128x128, BK=32, 8 warps (2x4).
//   Dynamic SMEM: 2 bufs x (A 128x36 + B 128x36) u32 = 73728 B.
// ---------------------------------------------------------------------------
#define GST 36
#define GTILE (128*GST)          // words per buffer per matrix

template<int EPI>
__global__ __launch_bounds__(256)
void gemm_tf32(const float* __restrict__ A, const float* __restrict__ B,
               float* __restrict__ C, float* __restrict__ C2, float* __restrict__ C3,
               int K, int lda, int ldb, int ldc,
               const float* __restrict__ bias, const float* __restrict__ res)
{
    extern __shared__ __align__(16) uint32_t dsm[];
    uint32_t* As = dsm;                 // [2][GTILE]
    uint32_t* Bs = dsm + 2*GTILE;       // [2][GTILE]

    int tid  = threadIdx.x;
    int lane = tid & 31;
    int w    = tid >> 5;
    int wm   = (w >> 2) * 64;
    int wn   = (w & 3)  * 32;
    int r    = lane >> 2;
    int cq   = lane & 3;
    int m0   = blockIdx.y * 128;
    int n0   = blockIdx.x * 128;

    // ldmatrix lane geometry (matrices 0..3 <- thread groups 0-7/8-15/16-23/24-31)
    int rA = (lane & 7) + ((lane >> 3) & 1) * 8;   // A: M1/M3 take +8 rows
    int cA = ((lane >> 4) & 1) * 4;                //    M2/M3 take +4 cols
    int rB = (lane & 7) + ((lane >> 4) & 1) * 8;   // B: M2/M3 take +8 rows
    int cB = ((lane >> 3) & 1) * 4;                //    M1/M3 take +4 cols
    uint32_t aBase = (uint32_t)__cvta_generic_to_shared(As) + ((wm + rA)*GST + cA)*4u;
    uint32_t bBase = (uint32_t)__cvta_generic_to_shared(Bs) + ((wn + rB)*GST + cB)*4u;

    float acc[16][4];
    #pragma unroll
    for (int i = 0; i < 16; i++)
        #pragma unroll
        for (int j = 0; j < 4; j++) acc[i][j] = 0.0f;

    float4 pa[4], pb[4];

    // prologue: LDG tile0, STS->buf0, LDG tile1
    #pragma unroll
    for (int i = 0; i < 4; i++) {
        int f = tid + i*256;
        int ar = f >> 3, ac4 = (f & 7) << 2;
        pa[i] = *reinterpret_cast<const float4*>(A + (size_t)(m0+ar)*lda + ac4);
        pb[i] = *reinterpret_cast<const float4*>(B + (size_t)(n0+ar)*ldb + ac4);
    }
    #pragma unroll
    for (int i = 0; i < 4; i++) {
        int f = tid + i*256;
        int ar = f >> 3, ac4 = (f & 7) << 2;
        uint4 ua = { f2tf32(pa[i].x), f2tf32(pa[i].y), f2tf32(pa[i].z), f2tf32(pa[i].w) };
        *reinterpret_cast<uint4*>(&As[ar*GST + ac4]) = ua;
        uint4 ub = { f2tf32(pb[i].x), f2tf32(pb[i].y), f2tf32(pb[i].z), f2tf32(pb[i].w) };
        *reinterpret_cast<uint4*>(&Bs[ar*GST + ac4]) = ub;
    }
    if (K > 32) {
        #pragma unroll
        for (int i = 0; i < 4; i++) {
            int f = tid + i*256;
            int ar = f >> 3, ac4 = (f & 7) << 2;
            pa[i] = *reinterpret_cast<const float4*>(A + (size_t)(m0+ar)*lda + 32 + ac4);
            pb[i] = *reinterpret_cast<const float4*>(B + (size_t)(n0+ar)*ldb + 32 + ac4);
        }
    }
    __syncthreads();

    int cur = 0;
    for (int kt = 0; kt < K; kt += 32) {
        // stage next tile into the other buffer (prev mma on it done at last sync)
        if (kt + 32 < K) {
            uint32_t* Ad = As + (cur^1)*GTILE;
            uint32_t* Bd = Bs + (cur^1)*GTILE;
            #pragma unroll
            for (int i = 0; i < 4; i++) {
                int f = tid + i*256;
                int ar = f >> 3, ac4 = (f & 7) << 2;
                uint4 ua = { f2tf32(pa[i].x), f2tf32(pa[i].y), f2tf32(pa[i].z), f2tf32(pa[i].w) };
                *reinterpret_cast<uint4*>(&Ad[ar*GST + ac4]) = ua;
                uint4 ub = { f2tf32(pb[i].x), f2tf32(pb[i].y), f2tf32(pb[i].z), f2tf32(pb[i].w) };
                *reinterpret_cast<uint4*>(&Bd[ar*GST + ac4]) = ub;
            }
        }
        if (kt + 64 < K) {
            #pragma unroll
            for (int i = 0; i < 4; i++) {
                int f = tid + i*256;
                int ar = f >> 3, ac4 = (f & 7) << 2;
                pa[i] = *reinterpret_cast<const float4*>(A + (size_t)(m0+ar)*lda + kt+64 + ac4);
                pb[i] = *reinterpret_cast<const float4*>(B + (size_t)(n0+ar)*ldb + kt+64 + ac4);
            }
        }

        // MMA over current buffer via ldmatrix
        uint32_t abuf = aBase + (uint32_t)(cur*GTILE)*4u;
        uint32_t bbuf = bBase + (uint32_t)(cur*GTILE)*4u;
        #pragma unroll
        for (int ks = 0; ks < 4; ks++) {
            uint32_t af[4][4];
            #pragma unroll
            for (int mt = 0; mt < 4; mt++)
                ldsm_x4(af[mt][0], af[mt][1], af[mt][2], af[mt][3],
                        abuf + (uint32_t)(mt*16*GST + ks*8)*4u);
            uint32_t bf[4][2];
            #pragma unroll
            for (int p = 0; p < 2; p++)
                ldsm_x4(bf[2*p][0], bf[2*p][1], bf[2*p+1][0], bf[2*p+1][1],
                        bbuf + (uint32_t)(p*16*GST + ks*8)*4u);
            #pragma unroll
            for (int mt = 0; mt < 4; mt++)
                #pragma unroll
                for (int nt = 0; nt < 4; nt++)
                    mma_tf32(acc[mt*4+nt], af[mt], bf[nt]);
        }
        cur ^= 1;
        __syncthreads();
    }

    // ---------------- epilogue ----------------
    #pragma unroll
    for (int mt = 0; mt < 4; mt++) {
        #pragma unroll
        for (int nt = 0; nt < 4; nt++) {
            const float* a4 = acc[mt*4+nt];
            int n = n0 + wn + nt*8 + 2*cq;
            #pragma unroll
            for (int p = 0; p < 2; p++) {
                int m = m0 + wm + mt*16 + r + 8*p;
                float v0 = a4[2*p+0];
                float v1 = a4[2*p+1];
                if (EPI == 2) {
                    float t0 = v0 + bias[n];
                    float t1 = v1 + bias[n+1];
                    float2 o2;
                    o2.x = 0.5f * t0 * (1.0f + erff(t0 * 0.70710678118654752f));
                    o2.y = 0.5f * t1 * (1.0f + erff(t1 * 0.70710678118654752f));
                    *reinterpret_cast<float2*>(C + (size_t)m*ldc + n) = o2;
                } else if (EPI == 3) {
                    float2 rr = *reinterpret_cast<const float2*>(res + (size_t)m*ldc + n);
                    float2 o2;
                    o2.x = v0 + bias[n]   + rr.x;
                    o2.y = v1 + bias[n+1] + rr.y;
                    *reinterpret_cast<float2*>(C + (size_t)m*ldc + n) = o2;
                } else if (EPI == 5) {
                    int kind = n >> 9;
                    int ww   = n & 511;
                    int hh   = ww >> 6;
                    int d    = ww & 63;
                    int b    = m >> 11;
                    int ntok = m & 2047;
                    size_t base = (((size_t)(b*Hh + hh))*Nn_ + ntok)*HD + d;
                    float2 o2; o2.x = v0; o2.y = v1;
                    if      (kind == 0) *reinterpret_cast<float2*>(C  + base) = o2;
                    else if (kind == 1) *reinterpret_cast<float2*>(C2 + base) = o2;
                    else                *reinterpret_cast<float2*>(C3 + base) = o2;
                }
            }
        }
    }
}

// ---------------------------------------------------------------------------
// Launch
// ---------------------------------------------------------------------------
extern "C" void kernel_launch(void* const* d_in, const int* in_sizes, int n_in,
                              void* d_out, int out_size)
{
    const float* x      = (const float*)d_in[0];
    const float* mask   = (const float*)d_in[1];
    const float* w_qkv  = (const float*)d_in[2];
    const float* w_proj = (const float*)d_in[3];
    const float* b_proj = (const float*)d_in[4];
    const float* g1     = (const float*)d_in[5];
    const float* beta1  = (const float*)d_in[6];
    const float* g2     = (const float*)d_in[7];
    const float* beta2  = (const float*)d_in[8];
    const float* w1     = (const float*)d_in[9];
    const float* bm1    = (const float*)d_in[10];
    const float* w2     = (const float*)d_in[11];
    const float* bm2    = (const float*)d_in[12];
    float* out = (float*)d_out;

    float *ln1, *q, *k, *v, *o, *y, *h2, *f;
    cudaGetSymbolAddress((void**)&ln1, g_ln1);
    cudaGetSymbolAddress((void**)&q,   g_q);
    cudaGetSymbolAddress((void**)&k,   g_k);
    cudaGetSymbolAddress((void**)&v,   g_v);
    cudaGetSymbolAddress((void**)&o,   g_o);
    cudaGetSymbolAddress((void**)&y,   g_y);
    cudaGetSymbolAddress((void**)&h2,  g_h2);
    cudaGetSymbolAddress((void**)&f,   g_f);

    const int FLASH_SMEM = (3*64*AST)*4 + 256*4;  // 53248 B
    cudaFuncSetAttribute(flash_attn_tc,
        cudaFuncAttributeMaxDynamicSharedMemorySize, FLASH_SMEM);
    const int GEMM_SMEM = 4*GTILE*4;              // 73728 B
    cudaFuncSetAttribute(gemm_tf32<2>,
        cudaFuncAttributeMaxDynamicSharedMemorySize, GEMM_SMEM);
    cudaFuncSetAttribute(gemm_tf32<3>,
        cudaFuncAttributeMaxDynamicSharedMemorySize, GEMM_SMEM);
    cudaFuncSetAttribute(gemm_tf32<5>,
        cudaFuncAttributeMaxDynamicSharedMemorySize, GEMM_SMEM);

    // 1) LN1
    layernorm_rows<<<Mrows, 128>>>(x, ln1, g1, beta1);

    // 2) QKV (tf32) with scatter: M=4096, N=1536, K=512
    {
        dim3 grid(1536/128, Mrows/128);
        gemm_tf32<5><<<grid, 256, GEMM_SMEM>>>(ln1, w_qkv, q, k, v,
                                    Cc, Cc, Cc, 0, nullptr, nullptr);
    }

    // 3) Fused attention (tf32 tensor cores)
    {
        dim3 grid(Nn_/64, BH);
        flash_attn_tc<<<grid, 256, FLASH_SMEM>>>(q, k, v, mask, o);
    }

    // 4) proj + bias + residual (tf32)
    {
        dim3 grid(Cc/128, Mrows/128);
        gemm_tf32<3><<<grid, 256, GEMM_SMEM>>>(o, w_proj, y, nullptr, nullptr,
                                    Cc, Cc, Cc, Cc, b_proj, x);
    }

    // 5) LN2
    layernorm_rows<<<Mrows, 128>>>(y, h2, g2, beta2);

    // 6) FFN1 + bias + gelu (tf32)
    {
        dim3 grid(DFF/128, Mrows/128);
        gemm_tf32<2><<<grid, 256, GEMM_SMEM>>>(h2, w1, f, nullptr, nullptr,
                                    Cc, Cc, Cc, DFF, bm1, nullptr);
    }

    // 7) FFN2 + bias + residual (tf32)
    {
        dim3 grid(Cc/128, Mrows/128);
        gemm_tf32<3><<<grid, 256, GEMM_SMEM>>>(f, w2, out, nullptr, nullptr,
                                    DFF, DFF, DFF, Cc, bm2, y);
    }

    (void)in_sizes; (void)n_in; (void)out_size;
}

// round 12
// speedup vs baseline: 2.7905x; 1.0402x over previous
#include <cuda_runtime.h>
#include <math.h>
#include <stdint.h>

// ---------------------------------------------------------------------------
// Problem constants
// ---------------------------------------------------------------------------
#define Bb   2
#define Nn_  2048
#define Cc   512
#define Hh   8
#define HD   64
#define DFF  2048
#define Mrows (Bb*Nn_)          // 4096
#define BH   (Bb*Hh)            // 16

// ---------------------------------------------------------------------------
// Device scratch (static allocation — no cudaMalloc allowed).  ~101 MB total.
// ---------------------------------------------------------------------------
__device__ float g_ln1[Mrows*Cc];
__device__ float g_q  [BH*Nn_*HD];
__device__ float g_k  [BH*Nn_*HD];
__device__ float g_v  [BH*Nn_*HD];
__device__ float g_o  [Mrows*Cc];
__device__ float g_y  [Mrows*Cc];
__device__ float g_h2 [Mrows*Cc];
__device__ float g_f  [Mrows*DFF];
// tf32-pre-rounded weight copies
__device__ float g_wq [3*Cc*Cc];      // 786432
__device__ float g_wp [Cc*Cc];        // 262144
__device__ float g_w1 [DFF*Cc];       // 1048576
__device__ float g_w2 [Cc*DFF];       // 1048576

// ---------------------------------------------------------------------------
// TF32 helpers
// ---------------------------------------------------------------------------
__device__ __forceinline__ uint32_t f2tf32(float x) {
    uint32_t r;
    asm("cvt.rna.tf32.f32 %0, %1;" : "=r"(r) : "f"(x));
    return r;
}
__device__ __forceinline__ float tf32r(float x) {     // round-to-tf32, as float
    return __uint_as_float(f2tf32(x));
}

__device__ __forceinline__ void mma_tf32(float* d, const uint32_t* a, const uint32_t* b) {
    asm volatile(
        "mma.sync.aligned.m16n8k8.row.col.f32.tf32.tf32.f32 "
        "{%0,%1,%2,%3}, {%4,%5,%6,%7}, {%8,%9}, {%0,%1,%2,%3};"
        : "+f"(d[0]), "+f"(d[1]), "+f"(d[2]), "+f"(d[3])
        : "r"(a[0]), "r"(a[1]), "r"(a[2]), "r"(a[3]), "r"(b[0]), "r"(b[1]));
}

__device__ __forceinline__ void ldsm_x4(uint32_t& r0, uint32_t& r1,
                                        uint32_t& r2, uint32_t& r3, uint32_t addr) {
    asm volatile("ldmatrix.sync.aligned.m8n8.x4.shared.b16 {%0,%1,%2,%3}, [%4];"
                 : "=r"(r0), "=r"(r1), "=r"(r2), "=r"(r3) : "r"(addr));
}

// ---------------------------------------------------------------------------
// Weight pre-rounding to tf32 (values only; stays fp32 storage)
// ---------------------------------------------------------------------------
__global__ __launch_bounds__(256)
void round_tf32_kernel(const float* __restrict__ in, float* __restrict__ out, int n)
{
    int i = blockIdx.x*256 + threadIdx.x;
    if (i < n) out[i] = tf32r(in[i]);
}

// ---------------------------------------------------------------------------
// LayerNorm: one block (128 thr) per row of 512.  Output tf32-rounded
// (consumed only by mma A operands: ln1 -> QKV, h2 -> FFN1).
// ---------------------------------------------------------------------------
__global__ __launch_bounds__(128)
void layernorm_rows(const float* __restrict__ X, float* __restrict__ Y,
                    const float* __restrict__ g, const float* __restrict__ b)
{
    int row = blockIdx.x;
    int tid = threadIdx.x;
    const float* x = X + (size_t)row * Cc;
    float4 v = *reinterpret_cast<const float4*>(x + tid*4);

    __shared__ float red[128];
    red[tid] = v.x + v.y + v.z + v.w;
    __syncthreads();
    #pragma unroll
    for (int s = 64; s > 0; s >>= 1) {
        if (tid < s) red[tid] += red[tid+s];
        __syncthreads();
    }
    float mu = red[0] * (1.0f/Cc);
    __syncthreads();

    float dx = v.x-mu, dy = v.y-mu, dz = v.z-mu, dw = v.w-mu;
    red[tid] = dx*dx + dy*dy + dz*dz + dw*dw;
    __syncthreads();
    #pragma unroll
    for (int s = 64; s > 0; s >>= 1) {
        if (tid < s) red[tid] += red[tid+s];
        __syncthreads();
    }
    float var = red[0] * (1.0f/Cc);
    float r = rsqrtf(var + 1e-5f);

    float4 gg = *reinterpret_cast<const float4*>(g + tid*4);
    float4 bb = *reinterpret_cast<const float4*>(b + tid*4);
    float4 o;
    o.x = tf32r(dx*r*gg.x + bb.x);
    o.y = tf32r(dy*r*gg.y + bb.y);
    o.z = tf32r(dz*r*gg.z + bb.z);
    o.w = tf32r(dw*r*gg.w + bb.w);
    *reinterpret_cast<float4*>(Y + (size_t)row*Cc + tid*4) = o;
}

// ---------------------------------------------------------------------------
// Tensor-core flash attention (tf32) — identical to passing R8/R9 kernel
// except O stores are tf32-rounded (O feeds only the proj mma).
// ---------------------------------------------------------------------------
#define AST 68   // u32 stride for sQ/sK/sVt

__global__ __launch_bounds__(256)
void flash_attn_tc(const float* __restrict__ Q, const float* __restrict__ K,
                   const float* __restrict__ V, const float* __restrict__ mask,
                   float* __restrict__ O)
{
    extern __shared__ uint32_t smu[];
    uint32_t* sQ  = smu;                 // [64][AST]
    uint32_t* sK  = sQ  + 64*AST;        // aliased by P after smax barrier
    uint32_t* sVt = sK  + 64*AST;        // [d][j]
    uint32_t* sP  = sK;                  // ALIAS
    float*    smax = (float*)(sVt + 64*AST); // [2][64]
    float*    ssum = smax + 128;             // [2][64]

    int tid  = threadIdx.x;
    int lane = tid & 31;
    int w    = tid >> 5;
    int wm   = (w >> 1) * 16;
    int cw   = w & 1;
    int wn   = cw * 32;
    int rg   = lane >> 2;
    int cq   = lane & 3;

    int q0 = blockIdx.x * 64;
    int bh = blockIdx.y;
    int b  = bh >> 3, hh = bh & 7;

    const float* Qb = Q + ((size_t)bh*Nn_ + q0)*HD;
    const float* Kb = K + (size_t)bh*Nn_*HD;
    const float* Vb = V + (size_t)bh*Nn_*HD;

    #pragma unroll
    for (int i = 0; i < 4; i++) {
        int f  = tid + i*256;
        int r  = f >> 4;
        int c4 = (f & 15) << 2;
        float4 v = *reinterpret_cast<const float4*>(Qb + r*HD + c4);
        uint4 u = { f2tf32(v.x), f2tf32(v.y), f2tf32(v.z), f2tf32(v.w) };
        *reinterpret_cast<uint4*>(&sQ[r*AST + c4]) = u;
    }

    float oacc[4][4];
    #pragma unroll
    for (int nt = 0; nt < 4; nt++)
        #pragma unroll
        for (int c = 0; c < 4; c++) oacc[nt][c] = 0.0f;
    float rmax0 = -1e30f, rmax1 = -1e30f, rsum0 = 0.0f, rsum1 = 0.0f;

    int row0 = wm + rg;
    int row1 = wm + rg + 8;

    for (int kt = 0; kt < Nn_; kt += 64) {
        __syncthreads();
        #pragma unroll
        for (int i = 0; i < 4; i++) {
            int f  = tid + i*256;
            int r  = f >> 4;
            int c4 = (f & 15) << 2;
            float4 kv = *reinterpret_cast<const float4*>(Kb + (size_t)(kt+r)*HD + c4);
            uint4 uk = { f2tf32(kv.x), f2tf32(kv.y), f2tf32(kv.z), f2tf32(kv.w) };
            *reinterpret_cast<uint4*>(&sK[r*AST + c4]) = uk;
            float4 vv = *reinterpret_cast<const float4*>(Vb + (size_t)(kt+r)*HD + c4);
            sVt[(c4+0)*AST + r] = f2tf32(vv.x);
            sVt[(c4+1)*AST + r] = f2tf32(vv.y);
            sVt[(c4+2)*AST + r] = f2tf32(vv.z);
            sVt[(c4+3)*AST + r] = f2tf32(vv.w);
        }
        __syncthreads();

        float sc[4][4];
        #pragma unroll
        for (int nt = 0; nt < 4; nt++)
            #pragma unroll
            for (int c = 0; c < 4; c++) sc[nt][c] = 0.0f;
        #pragma unroll
        for (int ks = 0; ks < 8; ks++) {
            int ko = ks*8;
            uint32_t a[4];
            a[0] = sQ[row0*AST + ko + cq];
            a[1] = sQ[row1*AST + ko + cq];
            a[2] = sQ[row0*AST + ko + cq + 4];
            a[3] = sQ[row1*AST + ko + cq + 4];
            #pragma unroll
            for (int nt = 0; nt < 4; nt++) {
                int key = wn + nt*8 + rg;
                uint32_t bf[2];
                bf[0] = sK[key*AST + ko + cq];
                bf[1] = sK[key*AST + ko + cq + 4];
                mma_tf32(sc[nt], a, bf);
            }
        }

        #pragma unroll
        for (int nt = 0; nt < 4; nt++) {
            int colg = kt + wn + nt*8 + 2*cq;
            float2 m0 = *reinterpret_cast<const float2*>(mask + (size_t)(q0+row0)*Nn_ + colg);
            float2 m1 = *reinterpret_cast<const float2*>(mask + (size_t)(q0+row1)*Nn_ + colg);
            sc[nt][0] *= 0.125f * m0.x;
            sc[nt][1] *= 0.125f * m0.y;
            sc[nt][2] *= 0.125f * m1.x;
            sc[nt][3] *= 0.125f * m1.y;
        }

        float mx0 = -1e30f, mx1 = -1e30f;
        #pragma unroll
        for (int nt = 0; nt < 4; nt++) {
            mx0 = fmaxf(mx0, fmaxf(sc[nt][0], sc[nt][1]));
            mx1 = fmaxf(mx1, fmaxf(sc[nt][2], sc[nt][3]));
        }
        #pragma unroll
        for (int off = 1; off <= 2; off <<= 1) {
            mx0 = fmaxf(mx0, __shfl_xor_sync(0xffffffffu, mx0, off));
            mx1 = fmaxf(mx1, __shfl_xor_sync(0xffffffffu, mx1, off));
        }
        if (cq == 0) {
            smax[cw*64 + row0] = mx0;
            smax[cw*64 + row1] = mx1;
        }
        __syncthreads();
        float tmax0 = fmaxf(smax[row0], smax[64 + row0]);
        float tmax1 = fmaxf(smax[row1], smax[64 + row1]);
        float nm0 = fmaxf(rmax0, tmax0);
        float nm1 = fmaxf(rmax1, tmax1);
        float corr0 = __expf(rmax0 - nm0);
        float corr1 = __expf(rmax1 - nm1);
        rmax0 = nm0; rmax1 = nm1;

        float ps0 = 0.0f, ps1 = 0.0f;
        #pragma unroll
        for (int nt = 0; nt < 4; nt++) {
            sc[nt][0] = __expf(sc[nt][0] - nm0);
            sc[nt][1] = __expf(sc[nt][1] - nm0);
            sc[nt][2] = __expf(sc[nt][2] - nm1);
            sc[nt][3] = __expf(sc[nt][3] - nm1);
            ps0 += sc[nt][0] + sc[nt][1];
            ps1 += sc[nt][2] + sc[nt][3];
            int colp = wn + nt*8 + 2*cq;
            sP[row0*AST + colp    ] = f2tf32(sc[nt][0]);
            sP[row0*AST + colp + 1] = f2tf32(sc[nt][1]);
            sP[row1*AST + colp    ] = f2tf32(sc[nt][2]);
            sP[row1*AST + colp + 1] = f2tf32(sc[nt][3]);
        }
        #pragma unroll
        for (int off = 1; off <= 2; off <<= 1) {
            ps0 += __shfl_xor_sync(0xffffffffu, ps0, off);
            ps1 += __shfl_xor_sync(0xffffffffu, ps1, off);
        }
        if (cq == 0) {
            ssum[cw*64 + row0] = ps0;
            ssum[cw*64 + row1] = ps1;
        }
        #pragma unroll
        for (int nt = 0; nt < 4; nt++) {
            oacc[nt][0] *= corr0;
            oacc[nt][1] *= corr0;
            oacc[nt][2] *= corr1;
            oacc[nt][3] *= corr1;
        }
        __syncthreads();
        rsum0 = rsum0*corr0 + ssum[row0] + ssum[64 + row0];
        rsum1 = rsum1*corr1 + ssum[row1] + ssum[64 + row1];

        #pragma unroll
        for (int ks = 0; ks < 8; ks++) {
            int ko = ks*8;
            uint32_t a[4];
            a[0] = sP[row0*AST + ko + cq];
            a[1] = sP[row1*AST + ko + cq];
            a[2] = sP[row0*AST + ko + cq + 4];
            a[3] = sP[row1*AST + ko + cq + 4];
            #pragma unroll
            for (int nt = 0; nt < 4; nt++) {
                int d = wn + nt*8 + rg;
                uint32_t bf[2];
                bf[0] = sVt[d*AST + ko + cq];
                bf[1] = sVt[d*AST + ko + cq + 4];
                mma_tf32(oacc[nt], a, bf);
            }
        }
    }

    float inv0 = 1.0f / rsum0;
    float inv1 = 1.0f / rsum1;
    #pragma unroll
    for (int nt = 0; nt < 4; nt++) {
        int col = hh*HD + wn + nt*8 + 2*cq;
        size_t m0g = (size_t)(b*Nn_ + q0 + row0);
        size_t m1g = (size_t)(b*Nn_ + q0 + row1);
        float2 o0; o0.x = tf32r(oacc[nt][0]*inv0); o0.y = tf32r(oacc[nt][1]*inv0);
        float2 o1; o1.x = tf32r(oacc[nt][2]*inv1); o1.y = tf32r(oacc[nt][3]*inv1);
        *reinterpret_cast<float2*>(O + m0g*Cc + col) = o0;
        *reinterpret_cast<float2*>(O + m1g*Cc + col) = o1;
    }
}

// ---------------------------------------------------------------------------
// TF32 GEMM v3: cp.async 3-stage pipeline + ldmatrix.  Inputs must be
// tf32-pre-rounded in global (mma truncation then exact).  2 CTAs/SM target.
//   Dynamic SMEM: 3 stages x (A 128x36 + B 128x36) u32 = 110592 B.
// ---------------------------------------------------------------------------
#define GST 36
#define GTILE (128*GST)          // words per matrix per stage
#define STGW (2*GTILE)           // words per stage (A then B)

template<int EPI>
__global__ __launch_bounds__(256, 2)
void gemm_tf32(const float* __restrict__ A, const float* __restrict__ B,
               float* __restrict__ C, float* __restrict__ C2, float* __restrict__ C3,
               int K, int lda, int ldb, int ldc,
               const float* __restrict__ bias, const float* __restrict__ res)
{
    extern __shared__ __align__(16) uint32_t dsm[];   // [3][STGW]

    int tid  = threadIdx.x;
    int lane = tid & 31;
    int w    = tid >> 5;
    int wm   = (w >> 2) * 64;
    int wn   = (w & 3)  * 32;
    int r    = lane >> 2;
    int cq   = lane & 3;
    int m0   = blockIdx.y * 128;
    int n0   = blockIdx.x * 128;

    uint32_t smemb = (uint32_t)__cvta_generic_to_shared(dsm);

    // ldmatrix lane geometry
    int rA = (lane & 7) + ((lane >> 3) & 1) * 8;
    int cA = ((lane >> 4) & 1) * 4;
    int rB = (lane & 7) + ((lane >> 4) & 1) * 8;
    int cB = ((lane >> 3) & 1) * 4;
    uint32_t aBase = smemb + ((wm + rA)*GST + cA)*4u;
    uint32_t bBase = smemb + (GTILE + (wn + rB)*GST + cB)*4u;

    // per-thread copy slots
    int f0 = tid;          // i=0..3 -> f = tid + i*256
    float acc[16][4];
    #pragma unroll
    for (int i = 0; i < 16; i++)
        #pragma unroll
        for (int j = 0; j < 4; j++) acc[i][j] = 0.0f;

    // ---- async stage issue ----
    auto issue_stage = [&](int stage, int kt) {
        uint32_t sb = smemb + (uint32_t)(stage*STGW)*4u;
        #pragma unroll
        for (int i = 0; i < 4; i++) {
            int f  = f0 + i*256;
            int ar = f >> 3, ac4 = (f & 7) << 2;
            uint32_t da = sb + (uint32_t)(ar*GST + ac4)*4u;
            const float* sa = A + (size_t)(m0+ar)*lda + kt + ac4;
            asm volatile("cp.async.cg.shared.global [%0], [%1], 16;\n" :: "r"(da), "l"(sa));
            uint32_t db = sb + (uint32_t)(GTILE + ar*GST + ac4)*4u;
            const float* sb2 = B + (size_t)(n0+ar)*ldb + kt + ac4;
            asm volatile("cp.async.cg.shared.global [%0], [%1], 16;\n" :: "r"(db), "l"(sb2));
        }
        asm volatile("cp.async.commit_group;\n");
    };
    auto empty_group = [&]() {
        asm volatile("cp.async.commit_group;\n");
    };

    // prologue: stages 0 and 1 in flight
    issue_stage(0, 0);
    if (K > 32) issue_stage(1, 32); else empty_group();

    int nT = K >> 5;
    for (int t = 0; t < nT; t++) {
        asm volatile("cp.async.wait_group 1;\n");   // stage t complete
        __syncthreads();                             // visible to all; stage t-1 free
        if (t + 2 < nT) issue_stage((t+2)%3, (t+2)*32); else empty_group();

        int cur = t % 3;
        uint32_t abuf = aBase + (uint32_t)(cur*STGW)*4u;
        uint32_t bbuf = bBase + (uint32_t)(cur*STGW)*4u;
        #pragma unroll
        for (int ks = 0; ks < 4; ks++) {
            uint32_t af[4][4];
            #pragma unroll
            for (int mt = 0; mt < 4; mt++)
                ldsm_x4(af[mt][0], af[mt][1], af[mt][2], af[mt][3],
                        abuf + (uint32_t)(mt*16*GST + ks*8)*4u);
            uint32_t bf[4][2];
            #pragma unroll
            for (int p = 0; p < 2; p++)
                ldsm_x4(bf[2*p][0], bf[2*p][1], bf[2*p+1][0], bf[2*p+1][1],
                        bbuf + (uint32_t)(p*16*GST + ks*8)*4u);
            #pragma unroll
            for (int mt = 0; mt < 4; mt++)
                #pragma unroll
                for (int nt = 0; nt < 4; nt++)
                    mma_tf32(acc[mt*4+nt], af[mt], bf[nt]);
        }
    }

    // ---------------- epilogue ----------------
    #pragma unroll
    for (int mt = 0; mt < 4; mt++) {
        #pragma unroll
        for (int nt = 0; nt < 4; nt++) {
            const float* a4 = acc[mt*4+nt];
            int n = n0 + wn + nt*8 + 2*cq;
            #pragma unroll
            for (int p = 0; p < 2; p++) {
                int m = m0 + wm + mt*16 + r + 8*p;
                float v0 = a4[2*p+0];
                float v1 = a4[2*p+1];
                if (EPI == 2) {
                    // gelu output feeds FFN2 mma -> store tf32-rounded
                    float t0 = v0 + bias[n];
                    float t1 = v1 + bias[n+1];
                    float2 o2;
                    o2.x = tf32r(0.5f * t0 * (1.0f + erff(t0 * 0.70710678118654752f)));
                    o2.y = tf32r(0.5f * t1 * (1.0f + erff(t1 * 0.70710678118654752f)));
                    *reinterpret_cast<float2*>(C + (size_t)m*ldc + n) = o2;
                } else if (EPI == 3) {
                    float2 rr = *reinterpret_cast<const float2*>(res + (size_t)m*ldc + n);
                    float2 o2;
                    o2.x = v0 + bias[n]   + rr.x;
                    o2.y = v1 + bias[n+1] + rr.y;
                    *reinterpret_cast<float2*>(C + (size_t)m*ldc + n) = o2;
                } else if (EPI == 5) {
                    int kind = n >> 9;
                    int ww   = n & 511;
                    int hh   = ww >> 6;
                    int d    = ww & 63;
                    int b    = m >> 11;
                    int ntok = m & 2047;
                    size_t base = (((size_t)(b*Hh + hh))*Nn_ + ntok)*HD + d;
                    float2 o2; o2.x = v0; o2.y = v1;
                    if      (kind == 0) *reinterpret_cast<float2*>(C  + base) = o2;
                    else if (kind == 1) *reinterpret_cast<float2*>(C2 + base) = o2;
                    else                *reinterpret_cast<float2*>(C3 + base) = o2;
                }
            }
        }
    }
}

// ---------------------------------------------------------------------------
// Launch
// ---------------------------------------------------------------------------
extern "C" void kernel_launch(void* const* d_in, const int* in_sizes, int n_in,
                              void* d_out, int out_size)
{
    const float* x      = (const float*)d_in[0];
    const float* mask   = (const float*)d_in[1];
    const float* w_qkv  = (const float*)d_in[2];
    const float* w_proj = (const float*)d_in[3];
    const float* b_proj = (const float*)d_in[4];
    const float* g1     = (const float*)d_in[5];
    const float* beta1  = (const float*)d_in[6];
    const float* g2     = (const float*)d_in[7];
    const float* beta2  = (const float*)d_in[8];
    const float* w1     = (const float*)d_in[9];
    const float* bm1    = (const float*)d_in[10];
    const float* w2     = (const float*)d_in[11];
    const float* bm2    = (const float*)d_in[12];
    float* out = (float*)d_out;

    float *ln1, *q, *k, *v, *o, *y, *h2, *f, *wq, *wp, *w1r, *w2r;
    cudaGetSymbolAddress((void**)&ln1, g_ln1);
    cudaGetSymbolAddress((void**)&q,   g_q);
    cudaGetSymbolAddress((void**)&k,   g_k);
    cudaGetSymbolAddress((void**)&v,   g_v);
    cudaGetSymbolAddress((void**)&o,   g_o);
    cudaGetSymbolAddress((void**)&y,   g_y);
    cudaGetSymbolAddress((void**)&h2,  g_h2);
    cudaGetSymbolAddress((void**)&f,   g_f);
    cudaGetSymbolAddress((void**)&wq,  g_wq);
    cudaGetSymbolAddress((void**)&wp,  g_wp);
    cudaGetSymbolAddress((void**)&w1r, g_w1);
    cudaGetSymbolAddress((void**)&w2r, g_w2);

    const int FLASH_SMEM = (3*64*AST)*4 + 256*4;  // 53248 B
    cudaFuncSetAttribute(flash_attn_tc,
        cudaFuncAttributeMaxDynamicSharedMemorySize, FLASH_SMEM);
    const int GEMM_SMEM = 3*STGW*4;               // 110592 B
    cudaFuncSetAttribute(gemm_tf32<2>,
        cudaFuncAttributeMaxDynamicSharedMemorySize, GEMM_SMEM);
    cudaFuncSetAttribute(gemm_tf32<3>,
        cudaFuncAttributeMaxDynamicSharedMemorySize, GEMM_SMEM);
    cudaFuncSetAttribute(gemm_tf32<5>,
        cudaFuncAttributeMaxDynamicSharedMemorySize, GEMM_SMEM);

    // 0) pre-round weights to tf32 values
    round_tf32_kernel<<<(3*Cc*Cc+255)/256, 256>>>(w_qkv,  wq,  3*Cc*Cc);
    round_tf32_kernel<<<(Cc*Cc+255)/256,   256>>>(w_proj, wp,  Cc*Cc);
    round_tf32_kernel<<<(DFF*Cc+255)/256,  256>>>(w1,     w1r, DFF*Cc);
    round_tf32_kernel<<<(Cc*DFF+255)/256,  256>>>(w2,     w2r, Cc*DFF);

    // 1) LN1 (tf32-rounded output)
    layernorm_rows<<<Mrows, 128>>>(x, ln1, g1, beta1);

    // 2) QKV with scatter: M=4096, N=1536, K=512
    {
        dim3 grid(1536/128, Mrows/128);
        gemm_tf32<5><<<grid, 256, GEMM_SMEM>>>(ln1, wq, q, k, v,
                                    Cc, Cc, Cc, 0, nullptr, nullptr);
    }

    // 3) Fused attention (tf32 tensor cores; O tf32-rounded)
    {
        dim3 grid(Nn_/64, BH);
        flash_attn_tc<<<grid, 256, FLASH_SMEM>>>(q, k, v, mask, o);
    }

    // 4) proj + bias + residual
    {
        dim3 grid(Cc/128, Mrows/128);
        gemm_tf32<3><<<grid, 256, GEMM_SMEM>>>(o, wp, y, nullptr, nullptr,
                                    Cc, Cc, Cc, Cc, b_proj, x);
    }

    // 5) LN2 (tf32-rounded output)
    layernorm_rows<<<Mrows, 128>>>(y, h2, g2, beta2);

    // 6) FFN1 + bias + gelu (tf32-rounded output)
    {
        dim3 grid(DFF/128, Mrows/128);
        gemm_tf32<2><<<grid, 256, GEMM_SMEM>>>(h2, w1r, f, nullptr, nullptr,
                                    Cc, Cc, Cc, DFF, bm1, nullptr);
    }

    // 7) FFN2 + bias + residual
    {
        dim3 grid(Cc/128, Mrows/128);
        gemm_tf32<3><<<grid, 256, GEMM_SMEM>>>(f, w2r, out, nullptr, nullptr,
                                    DFF, DFF, DFF, Cc, bm2, y);
    }

    (void)in_sizes; (void)n_in; (void)out_size;
}

// round 13
// speedup vs baseline: 3.4746x; 1.2451x over previous
#include <cuda_runtime.h>
#include <math.h>
#include <stdint.h>

// ---------------------------------------------------------------------------
// Problem constants
// ---------------------------------------------------------------------------
#define Bb   2
#define Nn_  2048
#define Cc   512
#define Hh   8
#define HD   64
#define DFF  2048
#define Mrows (Bb*Nn_)          // 4096
#define BH   (Bb*Hh)            // 16

// ---------------------------------------------------------------------------
// Device scratch (static allocation — no cudaMalloc allowed).  ~101 MB total.
// ---------------------------------------------------------------------------
__device__ float g_ln1[Mrows*Cc];
__device__ float g_q  [BH*Nn_*HD];
__device__ float g_k  [BH*Nn_*HD];
__device__ float g_v  [BH*Nn_*HD];
__device__ float g_o  [Mrows*Cc];
__device__ float g_y  [Mrows*Cc];
__device__ float g_h2 [Mrows*Cc];
__device__ float g_f  [Mrows*DFF];
// tf32-pre-rounded weight copies
__device__ float g_wq [3*Cc*Cc];      // 786432
__device__ float g_wp [Cc*Cc];        // 262144
__device__ float g_w1 [DFF*Cc];       // 1048576
__device__ float g_w2 [Cc*DFF];       // 1048576

// ---------------------------------------------------------------------------
// TF32 helpers
// ---------------------------------------------------------------------------
__device__ __forceinline__ uint32_t f2tf32(float x) {
    uint32_t r;
    asm("cvt.rna.tf32.f32 %0, %1;" : "=r"(r) : "f"(x));
    return r;
}
__device__ __forceinline__ float tf32r(float x) {
    return __uint_as_float(f2tf32(x));
}

__device__ __forceinline__ void mma_tf32(float* d, const uint32_t* a, const uint32_t* b) {
    asm volatile(
        "mma.sync.aligned.m16n8k8.row.col.f32.tf32.tf32.f32 "
        "{%0,%1,%2,%3}, {%4,%5,%6,%7}, {%8,%9}, {%0,%1,%2,%3};"
        : "+f"(d[0]), "+f"(d[1]), "+f"(d[2]), "+f"(d[3])
        : "r"(a[0]), "r"(a[1]), "r"(a[2]), "r"(a[3]), "r"(b[0]), "r"(b[1]));
}

__device__ __forceinline__ void ldsm_x4(uint32_t& r0, uint32_t& r1,
                                        uint32_t& r2, uint32_t& r3, uint32_t addr) {
    asm volatile("ldmatrix.sync.aligned.m8n8.x4.shared.b16 {%0,%1,%2,%3}, [%4];"
                 : "=r"(r0), "=r"(r1), "=r"(r2), "=r"(r3) : "r"(addr));
}

// ---------------------------------------------------------------------------
// Fused weight pre-rounding: one kernel, all four arrays (float4 strided).
// Sizes: wq 786432 | wp 262144 | w1 1048576 | w2 1048576  (total 3145728)
// ---------------------------------------------------------------------------
__global__ __launch_bounds__(256)
void round_all_tf32(const float* __restrict__ wq_in, const float* __restrict__ wp_in,
                    const float* __restrict__ w1_in, const float* __restrict__ w2_in,
                    float* __restrict__ wq, float* __restrict__ wp,
                    float* __restrict__ w1o, float* __restrict__ w2o)
{
    int i4 = (blockIdx.x*256 + threadIdx.x) * 4;
    const float* src; float* dst; int off;
    if      (i4 < 786432)  { src = wq_in; dst = wq;  off = i4; }
    else if (i4 < 1048576) { src = wp_in; dst = wp;  off = i4 - 786432; }
    else if (i4 < 2097152) { src = w1_in; dst = w1o; off = i4 - 1048576; }
    else                   { src = w2_in; dst = w2o; off = i4 - 2097152; }
    float4 v = *reinterpret_cast<const float4*>(src + off);
    float4 o;
    o.x = tf32r(v.x); o.y = tf32r(v.y); o.z = tf32r(v.z); o.w = tf32r(v.w);
    *reinterpret_cast<float4*>(dst + off) = o;
}

// ---------------------------------------------------------------------------
// LayerNorm: one block (128 thr) per row of 512.  Output tf32-rounded.
// ---------------------------------------------------------------------------
__global__ __launch_bounds__(128)
void layernorm_rows(const float* __restrict__ X, float* __restrict__ Y,
                    const float* __restrict__ g, const float* __restrict__ b)
{
    int row = blockIdx.x;
    int tid = threadIdx.x;
    const float* x = X + (size_t)row * Cc;
    float4 v = *reinterpret_cast<const float4*>(x + tid*4);

    __shared__ float red[128];
    red[tid] = v.x + v.y + v.z + v.w;
    __syncthreads();
    #pragma unroll
    for (int s = 64; s > 0; s >>= 1) {
        if (tid < s) red[tid] += red[tid+s];
        __syncthreads();
    }
    float mu = red[0] * (1.0f/Cc);
    __syncthreads();

    float dx = v.x-mu, dy = v.y-mu, dz = v.z-mu, dw = v.w-mu;
    red[tid] = dx*dx + dy*dy + dz*dz + dw*dw;
    __syncthreads();
    #pragma unroll
    for (int s = 64; s > 0; s >>= 1) {
        if (tid < s) red[tid] += red[tid+s];
        __syncthreads();
    }
    float var = red[0] * (1.0f/Cc);
    float r = rsqrtf(var + 1e-5f);

    float4 gg = *reinterpret_cast<const float4*>(g + tid*4);
    float4 bb = *reinterpret_cast<const float4*>(b + tid*4);
    float4 o;
    o.x = tf32r(dx*r*gg.x + bb.x);
    o.y = tf32r(dy*r*gg.y + bb.y);
    o.z = tf32r(dz*r*gg.z + bb.z);
    o.w = tf32r(dw*r*gg.w + bb.w);
    *reinterpret_cast<float4*>(Y + (size_t)row*Cc + tid*4) = o;
}

// ---------------------------------------------------------------------------
// Flash attention v2 (tf32): 128-row Q tile, warp-per-16-rows, ldmatrix
// fragments, in-warp softmax stats (no cross-warp combine), 2 CTAs/SM.
//   Grid: (N/128, BH).  Block: 256 thr = 8 warps.
//   SMEM: sQ[128][AST] | sK[64][AST] | sVt[64][AST] | sP[128][AST] = 104448 B
// ---------------------------------------------------------------------------
#define AST 68   // u32 stride; ldsm row bank = (4r+c) mod 32: conflict-free

__global__ __launch_bounds__(256, 2)
void flash_attn_tc(const float* __restrict__ Q, const float* __restrict__ K,
                   const float* __restrict__ V, const float* __restrict__ mask,
                   float* __restrict__ O)
{
    extern __shared__ uint32_t smu[];
    uint32_t* sQ  = smu;                 // [128][AST]
    uint32_t* sK  = smu + 128*AST;       // [64][AST]
    uint32_t* sVt = smu + 192*AST;       // [64][AST]  (d-major)
    uint32_t* sP  = smu + 256*AST;       // [128][AST]

    int tid  = threadIdx.x;
    int lane = tid & 31;
    int w    = tid >> 5;                 // warp owns rows [w*16, w*16+16)
    int rg   = lane >> 2;
    int cq   = lane & 3;

    int q0 = blockIdx.x * 128;
    int bh = blockIdx.y;
    int b  = bh >> 3, hh = bh & 7;

    const float* Qb = Q + ((size_t)bh*Nn_ + q0)*HD;
    const float* Kb = K + (size_t)bh*Nn_*HD;
    const float* Vb = V + (size_t)bh*Nn_*HD;

    // ldmatrix lane geometry (validated in passing GEMM)
    int rA = (lane & 7) + ((lane >> 3) & 1) * 8;
    int cA = ((lane >> 4) & 1) * 4;
    int rB = (lane & 7) + ((lane >> 4) & 1) * 8;
    int cB = ((lane >> 3) & 1) * 4;
    uint32_t smemb = (uint32_t)__cvta_generic_to_shared(smu);
    uint32_t qB_ = smemb + (uint32_t)(((w*16 + rA)*AST) + cA)*4u;
    uint32_t kB_ = smemb + (uint32_t)(((128 + rB)*AST) + cB)*4u;
    uint32_t vB_ = smemb + (uint32_t)(((192 + rB)*AST) + cB)*4u;
    uint32_t pB_ = smemb + (uint32_t)(((256 + w*16 + rA)*AST) + cA)*4u;

    // Load Q tile (128x64) once, tf32
    #pragma unroll
    for (int i = 0; i < 8; i++) {
        int f  = tid + i*256;
        int r  = f >> 4;
        int c4 = (f & 15) << 2;
        float4 v = *reinterpret_cast<const float4*>(Qb + r*HD + c4);
        uint4 u = { f2tf32(v.x), f2tf32(v.y), f2tf32(v.z), f2tf32(v.w) };
        *reinterpret_cast<uint4*>(&sQ[r*AST + c4]) = u;
    }

    float oacc[8][4];
    #pragma unroll
    for (int nt = 0; nt < 8; nt++)
        #pragma unroll
        for (int c = 0; c < 4; c++) oacc[nt][c] = 0.0f;
    float rmax0 = -1e30f, rmax1 = -1e30f, rsum0 = 0.0f, rsum1 = 0.0f;

    int row0 = w*16 + rg;        // global row within 128-tile
    int row1 = row0 + 8;

    for (int kt = 0; kt < Nn_; kt += 64) {
        __syncthreads();   // all warps done reading prev sK/sVt
        // Load K (natural) and V (transposed) tiles, tf32
        #pragma unroll
        for (int i = 0; i < 4; i++) {
            int f  = tid + i*256;
            int r  = f >> 4;
            int c4 = (f & 15) << 2;
            float4 kv = *reinterpret_cast<const float4*>(Kb + (size_t)(kt+r)*HD + c4);
            uint4 uk = { f2tf32(kv.x), f2tf32(kv.y), f2tf32(kv.z), f2tf32(kv.w) };
            *reinterpret_cast<uint4*>(&sK[r*AST + c4]) = uk;
            float4 vv = *reinterpret_cast<const float4*>(Vb + (size_t)(kt+r)*HD + c4);
            sVt[(c4+0)*AST + r] = f2tf32(vv.x);
            sVt[(c4+1)*AST + r] = f2tf32(vv.y);
            sVt[(c4+2)*AST + r] = f2tf32(vv.z);
            sVt[(c4+3)*AST + r] = f2tf32(vv.w);
        }
        __syncthreads();

        // S = Q @ K^T : this warp's 16 rows x all 64 keys
        float sc[8][4];
        #pragma unroll
        for (int nt = 0; nt < 8; nt++)
            #pragma unroll
            for (int c = 0; c < 4; c++) sc[nt][c] = 0.0f;
        #pragma unroll
        for (int ks = 0; ks < 8; ks++) {
            uint32_t a[4];
            ldsm_x4(a[0], a[1], a[2], a[3], qB_ + (uint32_t)(ks*8)*4u);
            uint32_t bf[8][2];
            #pragma unroll
            for (int p = 0; p < 4; p++)
                ldsm_x4(bf[2*p][0], bf[2*p][1], bf[2*p+1][0], bf[2*p+1][1],
                        kB_ + (uint32_t)(p*16*AST + ks*8)*4u);
            #pragma unroll
            for (int nt = 0; nt < 8; nt++)
                mma_tf32(sc[nt], a, bf[nt]);
        }

        // scale * multiplicative mask
        #pragma unroll
        for (int nt = 0; nt < 8; nt++) {
            int colg = kt + nt*8 + 2*cq;
            float2 m0 = *reinterpret_cast<const float2*>(mask + (size_t)(q0+row0)*Nn_ + colg);
            float2 m1 = *reinterpret_cast<const float2*>(mask + (size_t)(q0+row1)*Nn_ + colg);
            sc[nt][0] *= 0.125f * m0.x;
            sc[nt][1] *= 0.125f * m0.y;
            sc[nt][2] *= 0.125f * m1.x;
            sc[nt][3] *= 0.125f * m1.y;
        }

        // in-warp row max (quad shuffles only — warp owns full rows)
        float mx0 = -1e30f, mx1 = -1e30f;
        #pragma unroll
        for (int nt = 0; nt < 8; nt++) {
            mx0 = fmaxf(mx0, fmaxf(sc[nt][0], sc[nt][1]));
            mx1 = fmaxf(mx1, fmaxf(sc[nt][2], sc[nt][3]));
        }
        #pragma unroll
        for (int off = 1; off <= 2; off <<= 1) {
            mx0 = fmaxf(mx0, __shfl_xor_sync(0xffffffffu, mx0, off));
            mx1 = fmaxf(mx1, __shfl_xor_sync(0xffffffffu, mx1, off));
        }
        float nm0 = fmaxf(rmax0, mx0);
        float nm1 = fmaxf(rmax1, mx1);
        float corr0 = __expf(rmax0 - nm0);
        float corr1 = __expf(rmax1 - nm1);
        rmax0 = nm0; rmax1 = nm1;

        // exp, partial sums, packed P store (own rows only)
        float ps0 = 0.0f, ps1 = 0.0f;
        #pragma unroll
        for (int nt = 0; nt < 8; nt++) {
            float e0 = __expf(sc[nt][0] - nm0);
            float e1 = __expf(sc[nt][1] - nm0);
            float e2 = __expf(sc[nt][2] - nm1);
            float e3 = __expf(sc[nt][3] - nm1);
            ps0 += e0 + e1;
            ps1 += e2 + e3;
            int colp = nt*8 + 2*cq;
            uint2 u0; u0.x = f2tf32(e0); u0.y = f2tf32(e1);
            uint2 u1; u1.x = f2tf32(e2); u1.y = f2tf32(e3);
            *reinterpret_cast<uint2*>(&sP[row0*AST + colp]) = u0;
            *reinterpret_cast<uint2*>(&sP[row1*AST + colp]) = u1;
        }
        #pragma unroll
        for (int off = 1; off <= 2; off <<= 1) {
            ps0 += __shfl_xor_sync(0xffffffffu, ps0, off);
            ps1 += __shfl_xor_sync(0xffffffffu, ps1, off);
        }
        rsum0 = rsum0*corr0 + ps0;
        rsum1 = rsum1*corr1 + ps1;
        #pragma unroll
        for (int nt = 0; nt < 8; nt++) {
            oacc[nt][0] *= corr0;
            oacc[nt][1] *= corr0;
            oacc[nt][2] *= corr1;
            oacc[nt][3] *= corr1;
        }
        __syncwarp();   // P stores visible to ldmatrix within the warp

        // O += P @ V
        #pragma unroll
        for (int ks = 0; ks < 8; ks++) {
            uint32_t a[4];
            ldsm_x4(a[0], a[1], a[2], a[3], pB_ + (uint32_t)(ks*8)*4u);
            uint32_t bf[8][2];
            #pragma unroll
            for (int p = 0; p < 4; p++)
                ldsm_x4(bf[2*p][0], bf[2*p][1], bf[2*p+1][0], bf[2*p+1][1],
                        vB_ + (uint32_t)(p*16*AST + ks*8)*4u);
            #pragma unroll
            for (int nt = 0; nt < 8; nt++)
                mma_tf32(oacc[nt], a, bf[nt]);
        }
    }

    // epilogue: normalize, tf32-round, scatter into [B*N, C]
    float inv0 = 1.0f / rsum0;
    float inv1 = 1.0f / rsum1;
    #pragma unroll
    for (int nt = 0; nt < 8; nt++) {
        int col = hh*HD + nt*8 + 2*cq;
        size_t m0g = (size_t)(b*Nn_ + q0 + row0);
        size_t m1g = (size_t)(b*Nn_ + q0 + row1);
        float2 o0; o0.x = tf32r(oacc[nt][0]*inv0); o0.y = tf32r(oacc[nt][1]*inv0);
        float2 o1; o1.x = tf32r(oacc[nt][2]*inv1); o1.y = tf32r(oacc[nt][3]*inv1);
        *reinterpret_cast<float2*>(O + m0g*Cc + col) = o0;
        *reinterpret_cast<float2*>(O + m1g*Cc + col) = o1;
    }
}

// ---------------------------------------------------------------------------
// TF32 GEMM v3 (unchanged from passing R11): cp.async 3-stage + ldmatrix.
// ---------------------------------------------------------------------------
#define GST 36
#define GTILE (128*GST)
#define STGW (2*GTILE)

template<int EPI>
__global__ __launch_bounds__(256, 2)
void gemm_tf32(const float* __restrict__ A, const float* __restrict__ B,
               float* __restrict__ C, float* __restrict__ C2, float* __restrict__ C3,
               int K, int lda, int ldb, int ldc,
               const float* __restrict__ bias, const float* __restrict__ res)
{
    extern __shared__ __align__(16) uint32_t dsm[];   // [3][STGW]

    int tid  = threadIdx.x;
    int lane = tid & 31;
    int w    = tid >> 5;
    int wm   = (w >> 2) * 64;
    int wn   = (w & 3)  * 32;
    int r    = lane >> 2;
    int cq   = lane & 3;
    int m0   = blockIdx.y * 128;
    int n0   = blockIdx.x * 128;

    uint32_t smemb = (uint32_t)__cvta_generic_to_shared(dsm);

    int rA = (lane & 7) + ((lane >> 3) & 1) * 8;
    int cA = ((lane >> 4) & 1) * 4;
    int rB = (lane & 7) + ((lane >> 4) & 1) * 8;
    int cB = ((lane >> 3) & 1) * 4;
    uint32_t aBase = smemb + ((wm + rA)*GST + cA)*4u;
    uint32_t bBase = smemb + (GTILE + (wn + rB)*GST + cB)*4u;

    int f0 = tid;
    float acc[16][4];
    #pragma unroll
    for (int i = 0; i < 16; i++)
        #pragma unroll
        for (int j = 0; j < 4; j++) acc[i][j] = 0.0f;

    auto issue_stage = [&](int stage, int kt) {
        uint32_t sb = smemb + (uint32_t)(stage*STGW)*4u;
        #pragma unroll
        for (int i = 0; i < 4; i++) {
            int f  = f0 + i*256;
            int ar = f >> 3, ac4 = (f & 7) << 2;
            uint32_t da = sb + (uint32_t)(ar*GST + ac4)*4u;
            const float* sa = A + (size_t)(m0+ar)*lda + kt + ac4;
            asm volatile("cp.async.cg.shared.global [%0], [%1], 16;\n" :: "r"(da), "l"(sa));
            uint32_t db = sb + (uint32_t)(GTILE + ar*GST + ac4)*4u;
            const float* sb2 = B + (size_t)(n0+ar)*ldb + kt + ac4;
            asm volatile("cp.async.cg.shared.global [%0], [%1], 16;\n" :: "r"(db), "l"(sb2));
        }
        asm volatile("cp.async.commit_group;\n");
    };
    auto empty_group = [&]() {
        asm volatile("cp.async.commit_group;\n");
    };

    issue_stage(0, 0);
    if (K > 32) issue_stage(1, 32); else empty_group();

    int nT = K >> 5;
    for (int t = 0; t < nT; t++) {
        asm volatile("cp.async.wait_group 1;\n");
        __syncthreads();
        if (t + 2 < nT) issue_stage((t+2)%3, (t+2)*32); else empty_group();

        int cur = t % 3;
        uint32_t abuf = aBase + (uint32_t)(cur*STGW)*4u;
        uint32_t bbuf = bBase + (uint32_t)(cur*STGW)*4u;
        #pragma unroll
        for (int ks = 0; ks < 4; ks++) {
            uint32_t af[4][4];
            #pragma unroll
            for (int mt = 0; mt < 4; mt++)
                ldsm_x4(af[mt][0], af[mt][1], af[mt][2], af[mt][3],
                        abuf + (uint32_t)(mt*16*GST + ks*8)*4u);
            uint32_t bf[4][2];
            #pragma unroll
            for (int p = 0; p < 2; p++)
                ldsm_x4(bf[2*p][0], bf[2*p][1], bf[2*p+1][0], bf[2*p+1][1],
                        bbuf + (uint32_t)(p*16*GST + ks*8)*4u);
            #pragma unroll
            for (int mt = 0; mt < 4; mt++)
                #pragma unroll
                for (int nt = 0; nt < 4; nt++)
                    mma_tf32(acc[mt*4+nt], af[mt], bf[nt]);
        }
    }

    #pragma unroll
    for (int mt = 0; mt < 4; mt++) {
        #pragma unroll
        for (int nt = 0; nt < 4; nt++) {
            const float* a4 = acc[mt*4+nt];
            int n = n0 + wn + nt*8 + 2*cq;
            #pragma unroll
            for (int p = 0; p < 2; p++) {
                int m = m0 + wm + mt*16 + r + 8*p;
                float v0 = a4[2*p+0];
                float v1 = a4[2*p+1];
                if (EPI == 2) {
                    float t0 = v0 + bias[n];
                    float t1 = v1 + bias[n+1];
                    float2 o2;
                    o2.x = tf32r(0.5f * t0 * (1.0f + erff(t0 * 0.70710678118654752f)));
                    o2.y = tf32r(0.5f * t1 * (1.0f + erff(t1 * 0.70710678118654752f)));
                    *reinterpret_cast<float2*>(C + (size_t)m*ldc + n) = o2;
                } else if (EPI == 3) {
                    float2 rr = *reinterpret_cast<const float2*>(res + (size_t)m*ldc + n);
                    float2 o2;
                    o2.x = v0 + bias[n]   + rr.x;
                    o2.y = v1 + bias[n+1] + rr.y;
                    *reinterpret_cast<float2*>(C + (size_t)m*ldc + n) = o2;
                } else if (EPI == 5) {
                    int kind = n >> 9;
                    int ww   = n & 511;
                    int hh   = ww >> 6;
                    int d    = ww & 63;
                    int b    = m >> 11;
                    int ntok = m & 2047;
                    size_t base = (((size_t)(b*Hh + hh))*Nn_ + ntok)*HD + d;
                    float2 o2; o2.x = v0; o2.y = v1;
                    if      (kind == 0) *reinterpret_cast<float2*>(C  + base) = o2;
                    else if (kind == 1) *reinterpret_cast<float2*>(C2 + base) = o2;
                    else                *reinterpret_cast<float2*>(C3 + base) = o2;
                }
            }
        }
    }
}

// ---------------------------------------------------------------------------
// Launch
// ---------------------------------------------------------------------------
extern "C" void kernel_launch(void* const* d_in, const int* in_sizes, int n_in,
                              void* d_out, int out_size)
{
    const float* x      = (const float*)d_in[0];
    const float* mask   = (const float*)d_in[1];
    const float* w_qkv  = (const float*)d_in[2];
    const float* w_proj = (const float*)d_in[3];
    const float* b_proj = (const float*)d_in[4];
    const float* g1     = (const float*)d_in[5];
    const float* beta1  = (const float*)d_in[6];
    const float* g2     = (const float*)d_in[7];
    const float* beta2  = (const float*)d_in[8];
    const float* w1     = (const float*)d_in[9];
    const float* bm1    = (const float*)d_in[10];
    const float* w2     = (const float*)d_in[11];
    const float* bm2    = (const float*)d_in[12];
    float* out = (float*)d_out;

    float *ln1, *q, *k, *v, *o, *y, *h2, *f, *wq, *wp, *w1r, *w2r;
    cudaGetSymbolAddress((void**)&ln1, g_ln1);
    cudaGetSymbolAddress((void**)&q,   g_q);
    cudaGetSymbolAddress((void**)&k,   g_k);
    cudaGetSymbolAddress((void**)&v,   g_v);
    cudaGetSymbolAddress((void**)&o,   g_o);
    cudaGetSymbolAddress((void**)&y,   g_y);
    cudaGetSymbolAddress((void**)&h2,  g_h2);
    cudaGetSymbolAddress((void**)&f,   g_f);
    cudaGetSymbolAddress((void**)&wq,  g_wq);
    cudaGetSymbolAddress((void**)&wp,  g_wp);
    cudaGetSymbolAddress((void**)&w1r, g_w1);
    cudaGetSymbolAddress((void**)&w2r, g_w2);

    const int FLASH_SMEM = 384*AST*4;             // 104448 B
    cudaFuncSetAttribute(flash_attn_tc,
        cudaFuncAttributeMaxDynamicSharedMemorySize, FLASH_SMEM);
    const int GEMM_SMEM = 3*STGW*4;               // 110592 B
    cudaFuncSetAttribute(gemm_tf32<2>,
        cudaFuncAttributeMaxDynamicSharedMemorySize, GEMM_SMEM);
    cudaFuncSetAttribute(gemm_tf32<3>,
        cudaFuncAttributeMaxDynamicSharedMemorySize, GEMM_SMEM);
    cudaFuncSetAttribute(gemm_tf32<5>,
        cudaFuncAttributeMaxDynamicSharedMemorySize, GEMM_SMEM);

    // 0) pre-round weights to tf32 values (single fused kernel)
    round_all_tf32<<<3145728/4/256, 256>>>(w_qkv, w_proj, w1, w2, wq, wp, w1r, w2r);

    // 1) LN1 (tf32-rounded output)
    layernorm_rows<<<Mrows, 128>>>(x, ln1, g1, beta1);

    // 2) QKV with scatter: M=4096, N=1536, K=512
    {
        dim3 grid(1536/128, Mrows/128);
        gemm_tf32<5><<<grid, 256, GEMM_SMEM>>>(ln1, wq, q, k, v,
                                    Cc, Cc, Cc, 0, nullptr, nullptr);
    }

    // 3) Fused attention v2 (tf32 tensor cores; O tf32-rounded)
    {
        dim3 grid(Nn_/128, BH);
        flash_attn_tc<<<grid, 256, FLASH_SMEM>>>(q, k, v, mask, o);
    }

    // 4) proj + bias + residual
    {
        dim3 grid(Cc/128, Mrows/128);
        gemm_tf32<3><<<grid, 256, GEMM_SMEM>>>(o, wp, y, nullptr, nullptr,
                                    Cc, Cc, Cc, Cc, b_proj, x);
    }

    // 5) LN2 (tf32-rounded output)
    layernorm_rows<<<Mrows, 128>>>(y, h2, g2, beta2);

    // 6) FFN1 + bias + gelu (tf32-rounded output)
    {
        dim3 grid(DFF/128, Mrows/128);
        gemm_tf32<2><<<grid, 256, GEMM_SMEM>>>(h2, w1r, f, nullptr, nullptr,
                                    Cc, Cc, Cc, DFF, bm1, nullptr);
    }

    // 7) FFN2 + bias + residual
    {
        dim3 grid(Cc/128, Mrows/128);
        gemm_tf32<3><<<grid, 256, GEMM_SMEM>>>(f, w2r, out, nullptr, nullptr,
                                    DFF, DFF, DFF, Cc, bm2, y);
    }

    (void)in_sizes; (void)n_in; (void)out_size;
}

// round 14
// speedup vs baseline: 3.9947x; 1.1497x over previous
#include <cuda_runtime.h>
#include <math.h>
#include <stdint.h>

// ---------------------------------------------------------------------------
// Problem constants
// ---------------------------------------------------------------------------
#define Bb   2
#define Nn_  2048
#define Cc   512
#define Hh   8
#define HD   64
#define DFF  2048
#define Mrows (Bb*Nn_)          // 4096
#define BH   (Bb*Hh)            // 16

// ---------------------------------------------------------------------------
// Device scratch (static allocation — no cudaMalloc allowed).  ~101 MB total.
// ---------------------------------------------------------------------------
__device__ float g_ln1[Mrows*Cc];
__device__ float g_q  [BH*Nn_*HD];
__device__ float g_k  [BH*Nn_*HD];
__device__ float g_vt [BH*HD*Nn_];    // V stored transposed: [bh][d][n]
__device__ float g_o  [Mrows*Cc];
__device__ float g_y  [Mrows*Cc];
__device__ float g_h2 [Mrows*Cc];
__device__ float g_f  [Mrows*DFF];
// tf32-pre-rounded weight copies
__device__ float g_wq [3*Cc*Cc];
__device__ float g_wp [Cc*Cc];
__device__ float g_w1 [DFF*Cc];
__device__ float g_w2 [Cc*DFF];

// ---------------------------------------------------------------------------
// TF32 helpers
// ---------------------------------------------------------------------------
__device__ __forceinline__ uint32_t f2tf32(float x) {
    uint32_t r;
    asm("cvt.rna.tf32.f32 %0, %1;" : "=r"(r) : "f"(x));
    return r;
}
__device__ __forceinline__ float tf32r(float x) {
    return __uint_as_float(f2tf32(x));
}

__device__ __forceinline__ void mma_tf32(float* d, const uint32_t* a, const uint32_t* b) {
    asm volatile(
        "mma.sync.aligned.m16n8k8.row.col.f32.tf32.tf32.f32 "
        "{%0,%1,%2,%3}, {%4,%5,%6,%7}, {%8,%9}, {%0,%1,%2,%3};"
        : "+f"(d[0]), "+f"(d[1]), "+f"(d[2]), "+f"(d[3])
        : "r"(a[0]), "r"(a[1]), "r"(a[2]), "r"(a[3]), "r"(b[0]), "r"(b[1]));
}

__device__ __forceinline__ void ldsm_x4(uint32_t& r0, uint32_t& r1,
                                        uint32_t& r2, uint32_t& r3, uint32_t addr) {
    asm volatile("ldmatrix.sync.aligned.m8n8.x4.shared.b16 {%0,%1,%2,%3}, [%4];"
                 : "=r"(r0), "=r"(r1), "=r"(r2), "=r"(r3) : "r"(addr));
}

__device__ __forceinline__ void cpasync16(uint32_t dst, const void* src) {
    asm volatile("cp.async.cg.shared.global [%0], [%1], 16;\n" :: "r"(dst), "l"(src));
}

// ---------------------------------------------------------------------------
// Fused weight pre-rounding (unchanged, passing)
// ---------------------------------------------------------------------------
__global__ __launch_bounds__(256)
void round_all_tf32(const float* __restrict__ wq_in, const float* __restrict__ wp_in,
                    const float* __restrict__ w1_in, const float* __restrict__ w2_in,
                    float* __restrict__ wq, float* __restrict__ wp,
                    float* __restrict__ w1o, float* __restrict__ w2o)
{
    int i4 = (blockIdx.x*256 + threadIdx.x) * 4;
    const float* src; float* dst; int off;
    if      (i4 < 786432)  { src = wq_in; dst = wq;  off = i4; }
    else if (i4 < 1048576) { src = wp_in; dst = wp;  off = i4 - 786432; }
    else if (i4 < 2097152) { src = w1_in; dst = w1o; off = i4 - 1048576; }
    else                   { src = w2_in; dst = w2o; off = i4 - 2097152; }
    float4 v = *reinterpret_cast<const float4*>(src + off);
    float4 o;
    o.x = tf32r(v.x); o.y = tf32r(v.y); o.z = tf32r(v.z); o.w = tf32r(v.w);
    *reinterpret_cast<float4*>(dst + off) = o;
}

// ---------------------------------------------------------------------------
// LayerNorm (unchanged, passing): tf32-rounded output
// ---------------------------------------------------------------------------
__global__ __launch_bounds__(128)
void layernorm_rows(const float* __restrict__ X, float* __restrict__ Y,
                    const float* __restrict__ g, const float* __restrict__ b)
{
    int row = blockIdx.x;
    int tid = threadIdx.x;
    const float* x = X + (size_t)row * Cc;
    float4 v = *reinterpret_cast<const float4*>(x + tid*4);

    __shared__ float red[128];
    red[tid] = v.x + v.y + v.z + v.w;
    __syncthreads();
    #pragma unroll
    for (int s = 64; s > 0; s >>= 1) {
        if (tid < s) red[tid] += red[tid+s];
        __syncthreads();
    }
    float mu = red[0] * (1.0f/Cc);
    __syncthreads();

    float dx = v.x-mu, dy = v.y-mu, dz = v.z-mu, dw = v.w-mu;
    red[tid] = dx*dx + dy*dy + dz*dz + dw*dw;
    __syncthreads();
    #pragma unroll
    for (int s = 64; s > 0; s >>= 1) {
        if (tid < s) red[tid] += red[tid+s];
        __syncthreads();
    }
    float var = red[0] * (1.0f/Cc);
    float r = rsqrtf(var + 1e-5f);

    float4 gg = *reinterpret_cast<const float4*>(g + tid*4);
    float4 bb = *reinterpret_cast<const float4*>(b + tid*4);
    float4 o;
    o.x = tf32r(dx*r*gg.x + bb.x);
    o.y = tf32r(dy*r*gg.y + bb.y);
    o.z = tf32r(dz*r*gg.z + bb.z);
    o.w = tf32r(dw*r*gg.w + bb.w);
    *reinterpret_cast<float4*>(Y + (size_t)row*Cc + tid*4) = o;
}

// ---------------------------------------------------------------------------
// Flash attention v3 (tf32): 128-row Q tile, 4 warps x 32 rows/warp,
// cp.async loads (inputs tf32-pre-rounded, V pre-transposed), ldmatrix frags,
// in-warp softmax.  2 CTAs/SM.
//   Grid: (N/128, BH).  Block: 128 thr.
//   SMEM: sQ[128][AST] | sK[64][AST] | sVt[64][AST] | sP[128][AST] = 104448 B
// ---------------------------------------------------------------------------
#define AST 68

__global__ __launch_bounds__(128, 2)
void flash_attn_tc(const float* __restrict__ Q, const float* __restrict__ K,
                   const float* __restrict__ Vt, const float* __restrict__ mask,
                   float* __restrict__ O)
{
    extern __shared__ uint32_t smu[];

    int tid  = threadIdx.x;
    int lane = tid & 31;
    int w    = tid >> 5;                 // 0..3, warp owns rows [w*32, w*32+32)
    int rg   = lane >> 2;
    int cq   = lane & 3;
    int wr   = w * 32;

    int q0 = blockIdx.x * 128;
    int bh = blockIdx.y;
    int b  = bh >> 3, hh = bh & 7;

    const float* Qb  = Q  + ((size_t)bh*Nn_ + q0)*HD;
    const float* Kb  = K  + (size_t)bh*Nn_*HD;
    const float* Vtb = Vt + (size_t)bh*HD*Nn_;     // [d][n]

    uint32_t smemb = (uint32_t)__cvta_generic_to_shared(smu);

    // ldmatrix lane geometry (validated)
    int rA = (lane & 7) + ((lane >> 3) & 1) * 8;
    int cA = ((lane >> 4) & 1) * 4;
    int rB = (lane & 7) + ((lane >> 4) & 1) * 8;
    int cB = ((lane >> 3) & 1) * 4;
    uint32_t qA0 = smemb + (uint32_t)(((wr       + rA)*AST) + cA)*4u;
    uint32_t qA1 = smemb + (uint32_t)(((wr + 16  + rA)*AST) + cA)*4u;
    uint32_t kB_ = smemb + (uint32_t)(((128 + rB)*AST) + cB)*4u;
    uint32_t vB_ = smemb + (uint32_t)(((192 + rB)*AST) + cB)*4u;
    uint32_t pA0 = smemb + (uint32_t)(((256 + wr      + rA)*AST) + cA)*4u;
    uint32_t pA1 = smemb + (uint32_t)(((256 + wr + 16 + rA)*AST) + cA)*4u;

    // Q tile: 128x64 = 2048 float4, 16 per thread, cp.async
    #pragma unroll
    for (int i = 0; i < 16; i++) {
        int f  = tid + i*128;
        int r  = f >> 4;
        int c4 = (f & 15) << 2;
        cpasync16(smemb + (uint32_t)(r*AST + c4)*4u, Qb + r*HD + c4);
    }
    asm volatile("cp.async.commit_group;\n");

    float oacc[2][8][4];
    #pragma unroll
    for (int mt = 0; mt < 2; mt++)
        #pragma unroll
        for (int nt = 0; nt < 8; nt++)
            #pragma unroll
            for (int c = 0; c < 4; c++) oacc[mt][nt][c] = 0.0f;
    float rmax[4] = {-1e30f,-1e30f,-1e30f,-1e30f};
    float rsum[4] = {0.0f,0.0f,0.0f,0.0f};

    for (int kt = 0; kt < Nn_; kt += 64) {
        __syncthreads();   // prev-tile readers of sK/sVt/sP done
        // K tile [j][d] and Vt tile [d][j]: 1024 float4 each, 8/thread each
        #pragma unroll
        for (int i = 0; i < 8; i++) {
            int f  = tid + i*128;
            int r  = f >> 4;
            int c4 = (f & 15) << 2;
            cpasync16(smemb + (uint32_t)((128 + r)*AST + c4)*4u,
                      Kb + (size_t)(kt+r)*HD + c4);
            cpasync16(smemb + (uint32_t)((192 + r)*AST + c4)*4u,
                      Vtb + (size_t)r*Nn_ + kt + c4);
        }
        asm volatile("cp.async.commit_group;\n");
        asm volatile("cp.async.wait_group 0;\n");
        __syncthreads();

        // S = Q @ K^T : warp's 32 rows x 64 keys
        float sc[2][8][4];
        #pragma unroll
        for (int mt = 0; mt < 2; mt++)
            #pragma unroll
            for (int nt = 0; nt < 8; nt++)
                #pragma unroll
                for (int c = 0; c < 4; c++) sc[mt][nt][c] = 0.0f;
        #pragma unroll
        for (int ks = 0; ks < 8; ks++) {
            uint32_t a0[4], a1[4];
            ldsm_x4(a0[0], a0[1], a0[2], a0[3], qA0 + (uint32_t)(ks*8)*4u);
            ldsm_x4(a1[0], a1[1], a1[2], a1[3], qA1 + (uint32_t)(ks*8)*4u);
            uint32_t bf[8][2];
            #pragma unroll
            for (int p = 0; p < 4; p++)
                ldsm_x4(bf[2*p][0], bf[2*p][1], bf[2*p+1][0], bf[2*p+1][1],
                        kB_ + (uint32_t)(p*16*AST + ks*8)*4u);
            #pragma unroll
            for (int nt = 0; nt < 8; nt++) {
                mma_tf32(sc[0][nt], a0, bf[nt]);
                mma_tf32(sc[1][nt], a1, bf[nt]);
            }
        }

        // scale * multiplicative mask, then per-mt online softmax
        #pragma unroll
        for (int mt = 0; mt < 2; mt++) {
            int r0 = wr + mt*16 + rg;
            int r1 = r0 + 8;
            #pragma unroll
            for (int nt = 0; nt < 8; nt++) {
                int colg = kt + nt*8 + 2*cq;
                float2 m0 = *reinterpret_cast<const float2*>(mask + (size_t)(q0+r0)*Nn_ + colg);
                float2 m1 = *reinterpret_cast<const float2*>(mask + (size_t)(q0+r1)*Nn_ + colg);
                sc[mt][nt][0] *= 0.125f * m0.x;
                sc[mt][nt][1] *= 0.125f * m0.y;
                sc[mt][nt][2] *= 0.125f * m1.x;
                sc[mt][nt][3] *= 0.125f * m1.y;
            }

            float mx0 = -1e30f, mx1 = -1e30f;
            #pragma unroll
            for (int nt = 0; nt < 8; nt++) {
                mx0 = fmaxf(mx0, fmaxf(sc[mt][nt][0], sc[mt][nt][1]));
                mx1 = fmaxf(mx1, fmaxf(sc[mt][nt][2], sc[mt][nt][3]));
            }
            #pragma unroll
            for (int off = 1; off <= 2; off <<= 1) {
                mx0 = fmaxf(mx0, __shfl_xor_sync(0xffffffffu, mx0, off));
                mx1 = fmaxf(mx1, __shfl_xor_sync(0xffffffffu, mx1, off));
            }
            float nm0 = fmaxf(rmax[2*mt],   mx0);
            float nm1 = fmaxf(rmax[2*mt+1], mx1);
            float corr0 = __expf(rmax[2*mt]   - nm0);
            float corr1 = __expf(rmax[2*mt+1] - nm1);
            rmax[2*mt] = nm0; rmax[2*mt+1] = nm1;

            float ps0 = 0.0f, ps1 = 0.0f;
            #pragma unroll
            for (int nt = 0; nt < 8; nt++) {
                float e0 = __expf(sc[mt][nt][0] - nm0);
                float e1 = __expf(sc[mt][nt][1] - nm0);
                float e2 = __expf(sc[mt][nt][2] - nm1);
                float e3 = __expf(sc[mt][nt][3] - nm1);
                ps0 += e0 + e1;
                ps1 += e2 + e3;
                int colp = nt*8 + 2*cq;
                uint2 u0; u0.x = f2tf32(e0); u0.y = f2tf32(e1);
                uint2 u1; u1.x = f2tf32(e2); u1.y = f2tf32(e3);
                *reinterpret_cast<uint2*>(&smu[(256 + r0)*AST + colp]) = u0;
                *reinterpret_cast<uint2*>(&smu[(256 + r1)*AST + colp]) = u1;
            }
            #pragma unroll
            for (int off = 1; off <= 2; off <<= 1) {
                ps0 += __shfl_xor_sync(0xffffffffu, ps0, off);
                ps1 += __shfl_xor_sync(0xffffffffu, ps1, off);
            }
            rsum[2*mt]   = rsum[2*mt]*corr0   + ps0;
            rsum[2*mt+1] = rsum[2*mt+1]*corr1 + ps1;
            #pragma unroll
            for (int nt = 0; nt < 8; nt++) {
                oacc[mt][nt][0] *= corr0;
                oacc[mt][nt][1] *= corr0;
                oacc[mt][nt][2] *= corr1;
                oacc[mt][nt][3] *= corr1;
            }
        }
        __syncwarp();   // P stores visible to this warp's ldmatrix

        // O += P @ V
        #pragma unroll
        for (int ks = 0; ks < 8; ks++) {
            uint32_t a0[4], a1[4];
            ldsm_x4(a0[0], a0[1], a0[2], a0[3], pA0 + (uint32_t)(ks*8)*4u);
            ldsm_x4(a1[0], a1[1], a1[2], a1[3], pA1 + (uint32_t)(ks*8)*4u);
            uint32_t bf[8][2];
            #pragma unroll
            for (int p = 0; p < 4; p++)
                ldsm_x4(bf[2*p][0], bf[2*p][1], bf[2*p+1][0], bf[2*p+1][1],
                        vB_ + (uint32_t)(p*16*AST + ks*8)*4u);
            #pragma unroll
            for (int nt = 0; nt < 8; nt++) {
                mma_tf32(oacc[0][nt], a0, bf[nt]);
                mma_tf32(oacc[1][nt], a1, bf[nt]);
            }
        }
    }

    // epilogue: normalize, tf32-round, scatter into [B*N, C]
    #pragma unroll
    for (int mt = 0; mt < 2; mt++) {
        int r0 = wr + mt*16 + rg;
        int r1 = r0 + 8;
        float inv0 = 1.0f / rsum[2*mt];
        float inv1 = 1.0f / rsum[2*mt+1];
        #pragma unroll
        for (int nt = 0; nt < 8; nt++) {
            int col = hh*HD + nt*8 + 2*cq;
            size_t m0g = (size_t)(b*Nn_ + q0 + r0);
            size_t m1g = (size_t)(b*Nn_ + q0 + r1);
            float2 o0; o0.x = tf32r(oacc[mt][nt][0]*inv0); o0.y = tf32r(oacc[mt][nt][1]*inv0);
            float2 o1; o1.x = tf32r(oacc[mt][nt][2]*inv1); o1.y = tf32r(oacc[mt][nt][3]*inv1);
            *reinterpret_cast<float2*>(O + m0g*Cc + col) = o0;
            *reinterpret_cast<float2*>(O + m1g*Cc + col) = o1;
        }
    }
}

// ---------------------------------------------------------------------------
// TF32 GEMM v3 (structure unchanged from passing R11/R13; EPI5 now stores
// tf32-rounded q/k and V transposed [bh][d][n]).
// ---------------------------------------------------------------------------
#define GST 36
#define GTILE (128*GST)
#define STGW (2*GTILE)

template<int EPI>
__global__ __launch_bounds__(256, 2)
void gemm_tf32(const float* __restrict__ A, const float* __restrict__ B,
               float* __restrict__ C, float* __restrict__ C2, float* __restrict__ C3,
               int K, int lda, int ldb, int ldc,
               const float* __restrict__ bias, const float* __restrict__ res)
{
    extern __shared__ __align__(16) uint32_t dsm[];   // [3][STGW]

    int tid  = threadIdx.x;
    int lane = tid & 31;
    int w    = tid >> 5;
    int wm   = (w >> 2) * 64;
    int wn   = (w & 3)  * 32;
    int r    = lane >> 2;
    int cq   = lane & 3;
    int m0   = blockIdx.y * 128;
    int n0   = blockIdx.x * 128;

    uint32_t smemb = (uint32_t)__cvta_generic_to_shared(dsm);

    int rA = (lane & 7) + ((lane >> 3) & 1) * 8;
    int cA = ((lane >> 4) & 1) * 4;
    int rB = (lane & 7) + ((lane >> 4) & 1) * 8;
    int cB = ((lane >> 3) & 1) * 4;
    uint32_t aBase = smemb + ((wm + rA)*GST + cA)*4u;
    uint32_t bBase = smemb + (GTILE + (wn + rB)*GST + cB)*4u;

    int f0 = tid;
    float acc[16][4];
    #pragma unroll
    for (int i = 0; i < 16; i++)
        #pragma unroll
        for (int j = 0; j < 4; j++) acc[i][j] = 0.0f;

    auto issue_stage = [&](int stage, int kt) {
        uint32_t sb = smemb + (uint32_t)(stage*STGW)*4u;
        #pragma unroll
        for (int i = 0; i < 4; i++) {
            int f  = f0 + i*256;
            int ar = f >> 3, ac4 = (f & 7) << 2;
            uint32_t da = sb + (uint32_t)(ar*GST + ac4)*4u;
            const float* sa = A + (size_t)(m0+ar)*lda + kt + ac4;
            asm volatile("cp.async.cg.shared.global [%0], [%1], 16;\n" :: "r"(da), "l"(sa));
            uint32_t db = sb + (uint32_t)(GTILE + ar*GST + ac4)*4u;
            const float* sb2 = B + (size_t)(n0+ar)*ldb + kt + ac4;
            asm volatile("cp.async.cg.shared.global [%0], [%1], 16;\n" :: "r"(db), "l"(sb2));
        }
        asm volatile("cp.async.commit_group;\n");
    };
    auto empty_group = [&]() {
        asm volatile("cp.async.commit_group;\n");
    };

    issue_stage(0, 0);
    if (K > 32) issue_stage(1, 32); else empty_group();

    int nT = K >> 5;
    for (int t = 0; t < nT; t++) {
        asm volatile("cp.async.wait_group 1;\n");
        __syncthreads();
        if (t + 2 < nT) issue_stage((t+2)%3, (t+2)*32); else empty_group();

        int cur = t % 3;
        uint32_t abuf = aBase + (uint32_t)(cur*STGW)*4u;
        uint32_t bbuf = bBase + (uint32_t)(cur*STGW)*4u;
        #pragma unroll
        for (int ks = 0; ks < 4; ks++) {
            uint32_t af[4][4];
            #pragma unroll
            for (int mt = 0; mt < 4; mt++)
                ldsm_x4(af[mt][0], af[mt][1], af[mt][2], af[mt][3],
                        abuf + (uint32_t)(mt*16*GST + ks*8)*4u);
            uint32_t bf[4][2];
            #pragma unroll
            for (int p = 0; p < 2; p++)
                ldsm_x4(bf[2*p][0], bf[2*p][1], bf[2*p+1][0], bf[2*p+1][1],
                        bbuf + (uint32_t)(p*16*GST + ks*8)*4u);
            #pragma unroll
            for (int mt = 0; mt < 4; mt++)
                #pragma unroll
                for (int nt = 0; nt < 4; nt++)
                    mma_tf32(acc[mt*4+nt], af[mt], bf[nt]);
        }
    }

    #pragma unroll
    for (int mt = 0; mt < 4; mt++) {
        #pragma unroll
        for (int nt = 0; nt < 4; nt++) {
            const float* a4 = acc[mt*4+nt];
            int n = n0 + wn + nt*8 + 2*cq;
            #pragma unroll
            for (int p = 0; p < 2; p++) {
                int m = m0 + wm + mt*16 + r + 8*p;
                float v0 = a4[2*p+0];
                float v1 = a4[2*p+1];
                if (EPI == 2) {
                    float t0 = v0 + bias[n];
                    float t1 = v1 + bias[n+1];
                    float2 o2;
                    o2.x = tf32r(0.5f * t0 * (1.0f + erff(t0 * 0.70710678118654752f)));
                    o2.y = tf32r(0.5f * t1 * (1.0f + erff(t1 * 0.70710678118654752f)));
                    *reinterpret_cast<float2*>(C + (size_t)m*ldc + n) = o2;
                } else if (EPI == 3) {
                    float2 rr = *reinterpret_cast<const float2*>(res + (size_t)m*ldc + n);
                    float2 o2;
                    o2.x = v0 + bias[n]   + rr.x;
                    o2.y = v1 + bias[n+1] + rr.y;
                    *reinterpret_cast<float2*>(C + (size_t)m*ldc + n) = o2;
                } else if (EPI == 5) {
                    int kind = n >> 9;
                    int ww   = n & 511;
                    int hh   = ww >> 6;
                    int d    = ww & 63;
                    int b    = m >> 11;
                    int ntok = m & 2047;
                    float r0 = tf32r(v0);
                    float r1 = tf32r(v1);
                    if (kind == 2) {
                        // V transposed: [bh][d][n]
                        size_t base = ((size_t)(b*Hh + hh)*HD + d)*Nn_ + ntok;
                        C3[base]       = r0;
                        C3[base + Nn_] = r1;   // d+1
                    } else {
                        size_t base = (((size_t)(b*Hh + hh))*Nn_ + ntok)*HD + d;
                        float2 o2; o2.x = r0; o2.y = r1;
                        if (kind == 0) *reinterpret_cast<float2*>(C  + base) = o2;
                        else           *reinterpret_cast<float2*>(C2 + base) = o2;
                    }
                }
            }
        }
    }
}

// ---------------------------------------------------------------------------
// Launch
// ---------------------------------------------------------------------------
extern "C" void kernel_launch(void* const* d_in, const int* in_sizes, int n_in,
                              void* d_out, int out_size)
{
    const float* x      = (const float*)d_in[0];
    const float* mask   = (const float*)d_in[1];
    const float* w_qkv  = (const float*)d_in[2];
    const float* w_proj = (const float*)d_in[3];
    const float* b_proj = (const float*)d_in[4];
    const float* g1     = (const float*)d_in[5];
    const float* beta1  = (const float*)d_in[6];
    const float* g2     = (const float*)d_in[7];
    const float* beta2  = (const float*)d_in[8];
    const float* w1     = (const float*)d_in[9];
    const float* bm1    = (const float*)d_in[10];
    const float* w2     = (const float*)d_in[11];
    const float* bm2    = (const float*)d_in[12];
    float* out = (float*)d_out;

    float *ln1, *q, *k, *vt, *o, *y, *h2, *f, *wq, *wp, *w1r, *w2r;
    cudaGetSymbolAddress((void**)&ln1, g_ln1);
    cudaGetSymbolAddress((void**)&q,   g_q);
    cudaGetSymbolAddress((void**)&k,   g_k);
    cudaGetSymbolAddress((void**)&vt,  g_vt);
    cudaGetSymbolAddress((void**)&o,   g_o);
    cudaGetSymbolAddress((void**)&y,   g_y);
    cudaGetSymbolAddress((void**)&h2,  g_h2);
    cudaGetSymbolAddress((void**)&f,   g_f);
    cudaGetSymbolAddress((void**)&wq,  g_wq);
    cudaGetSymbolAddress((void**)&wp,  g_wp);
    cudaGetSymbolAddress((void**)&w1r, g_w1);
    cudaGetSymbolAddress((void**)&w2r, g_w2);

    const int FLASH_SMEM = 384*AST*4;             // 104448 B
    cudaFuncSetAttribute(flash_attn_tc,
        cudaFuncAttributeMaxDynamicSharedMemorySize, FLASH_SMEM);
    const int GEMM_SMEM = 3*STGW*4;               // 110592 B
    cudaFuncSetAttribute(gemm_tf32<2>,
        cudaFuncAttributeMaxDynamicSharedMemorySize, GEMM_SMEM);
    cudaFuncSetAttribute(gemm_tf32<3>,
        cudaFuncAttributeMaxDynamicSharedMemorySize, GEMM_SMEM);
    cudaFuncSetAttribute(gemm_tf32<5>,
        cudaFuncAttributeMaxDynamicSharedMemorySize, GEMM_SMEM);

    // 0) pre-round weights to tf32 values (single fused kernel)
    round_all_tf32<<<3145728/4/256, 256>>>(w_qkv, w_proj, w1, w2, wq, wp, w1r, w2r);

    // 1) LN1 (tf32-rounded output)
    layernorm_rows<<<Mrows, 128>>>(x, ln1, g1, beta1);

    // 2) QKV with scatter (q/k rounded, v rounded+transposed)
    {
        dim3 grid(1536/128, Mrows/128);
        gemm_tf32<5><<<grid, 256, GEMM_SMEM>>>(ln1, wq, q, k, vt,
                                    Cc, Cc, Cc, 0, nullptr, nullptr);
    }

    // 3) Fused attention v3
    {
        dim3 grid(Nn_/128, BH);
        flash_attn_tc<<<grid, 128, FLASH_SMEM>>>(q, k, vt, mask, o);
    }

    // 4) proj + bias + residual
    {
        dim3 grid(Cc/128, Mrows/128);
        gemm_tf32<3><<<grid, 256, GEMM_SMEM>>>(o, wp, y, nullptr, nullptr,
                                    Cc, Cc, Cc, Cc, b_proj, x);
    }

    // 5) LN2 (tf32-rounded output)
    layernorm_rows<<<Mrows, 128>>>(y, h2, g2, beta2);

    // 6) FFN1 + bias + gelu (tf32-rounded output)
    {
        dim3 grid(DFF/128, Mrows/128);
        gemm_tf32<2><<<grid, 256, GEMM_SMEM>>>(h2, w1r, f, nullptr, nullptr,
                                    Cc, Cc, Cc, DFF, bm1, nullptr);
    }

    // 7) FFN2 + bias + residual
    {
        dim3 grid(Cc/128, Mrows/128);
        gemm_tf32<3><<<grid, 256, GEMM_SMEM>>>(f, w2r, out, nullptr, nullptr,
                                    DFF, DFF, DFF, Cc, bm2, y);
    }

    (void)in_sizes; (void)n_in; (void)out_size;
}

// round 15
// speedup vs baseline: 4.6728x; 1.1697x over previous
#include <cuda_runtime.h>
#include <cuda_bf16.h>
#include <math.h>
#include <stdint.h>

// ---------------------------------------------------------------------------
// Problem constants
// ---------------------------------------------------------------------------
#define Bb   2
#define Nn_  2048
#define Cc   512
#define Hh   8
#define HD   64
#define DFF  2048
#define Mrows (Bb*Nn_)          // 4096
#define BH   (Bb*Hh)            // 16

// ---------------------------------------------------------------------------
// Device scratch (static allocation — no cudaMalloc allowed).
// ---------------------------------------------------------------------------
__device__ float g_ln1[Mrows*Cc];
__device__ __nv_bfloat16 g_q [BH*Nn_*HD];     // bf16 [bh][n][d]
__device__ __nv_bfloat16 g_k [BH*Nn_*HD];     // bf16 [bh][n][d]
__device__ __nv_bfloat16 g_vt[BH*HD*Nn_];     // bf16 [bh][d][n]
__device__ float g_o  [Mrows*Cc];
__device__ float g_y  [Mrows*Cc];
__device__ float g_h2 [Mrows*Cc];
__device__ float g_f  [Mrows*DFF];
// tf32-pre-rounded weight copies
__device__ float g_wq [3*Cc*Cc];
__device__ float g_wp [Cc*Cc];
__device__ float g_w1 [DFF*Cc];
__device__ float g_w2 [Cc*DFF];

// ---------------------------------------------------------------------------
// Precision helpers
// ---------------------------------------------------------------------------
__device__ __forceinline__ uint32_t f2tf32(float x) {
    uint32_t r;
    asm("cvt.rna.tf32.f32 %0, %1;" : "=r"(r) : "f"(x));
    return r;
}
__device__ __forceinline__ float tf32r(float x) {
    return __uint_as_float(f2tf32(x));
}
__device__ __forceinline__ uint32_t pack_bf16x2(float lo, float hi) {
    uint32_t r;
    asm("cvt.rn.bf16x2.f32 %0, %1, %2;" : "=r"(r) : "f"(hi), "f"(lo));
    return r;
}

__device__ __forceinline__ void mma_tf32(float* d, const uint32_t* a, const uint32_t* b) {
    asm volatile(
        "mma.sync.aligned.m16n8k8.row.col.f32.tf32.tf32.f32 "
        "{%0,%1,%2,%3}, {%4,%5,%6,%7}, {%8,%9}, {%0,%1,%2,%3};"
        : "+f"(d[0]), "+f"(d[1]), "+f"(d[2]), "+f"(d[3])
        : "r"(a[0]), "r"(a[1]), "r"(a[2]), "r"(a[3]), "r"(b[0]), "r"(b[1]));
}
__device__ __forceinline__ void mma_bf16(float* d, const uint32_t* a, const uint32_t* b) {
    asm volatile(
        "mma.sync.aligned.m16n8k16.row.col.f32.bf16.bf16.f32 "
        "{%0,%1,%2,%3}, {%4,%5,%6,%7}, {%8,%9}, {%0,%1,%2,%3};"
        : "+f"(d[0]), "+f"(d[1]), "+f"(d[2]), "+f"(d[3])
        : "r"(a[0]), "r"(a[1]), "r"(a[2]), "r"(a[3]), "r"(b[0]), "r"(b[1]));
}

__device__ __forceinline__ void ldsm_x4(uint32_t& r0, uint32_t& r1,
                                        uint32_t& r2, uint32_t& r3, uint32_t addr) {
    asm volatile("ldmatrix.sync.aligned.m8n8.x4.shared.b16 {%0,%1,%2,%3}, [%4];"
                 : "=r"(r0), "=r"(r1), "=r"(r2), "=r"(r3) : "r"(addr));
}

__device__ __forceinline__ void cpasync16(uint32_t dst, const void* src) {
    asm volatile("cp.async.cg.shared.global [%0], [%1], 16;\n" :: "r"(dst), "l"(src));
}

// ---------------------------------------------------------------------------
// Fused weight pre-rounding (unchanged, passing)
// ---------------------------------------------------------------------------
__global__ __launch_bounds__(256)
void round_all_tf32(const float* __restrict__ wq_in, const float* __restrict__ wp_in,
                    const float* __restrict__ w1_in, const float* __restrict__ w2_in,
                    float* __restrict__ wq, float* __restrict__ wp,
                    float* __restrict__ w1o, float* __restrict__ w2o)
{
    int i4 = (blockIdx.x*256 + threadIdx.x) * 4;
    const float* src; float* dst; int off;
    if      (i4 < 786432)  { src = wq_in; dst = wq;  off = i4; }
    else if (i4 < 1048576) { src = wp_in; dst = wp;  off = i4 - 786432; }
    else if (i4 < 2097152) { src = w1_in; dst = w1o; off = i4 - 1048576; }
    else                   { src = w2_in; dst = w2o; off = i4 - 2097152; }
    float4 v = *reinterpret_cast<const float4*>(src + off);
    float4 o;
    o.x = tf32r(v.x); o.y = tf32r(v.y); o.z = tf32r(v.z); o.w = tf32r(v.w);
    *reinterpret_cast<float4*>(dst + off) = o;
}

// ---------------------------------------------------------------------------
// LayerNorm (unchanged, passing): tf32-rounded output
// ---------------------------------------------------------------------------
__global__ __launch_bounds__(128)
void layernorm_rows(const float* __restrict__ X, float* __restrict__ Y,
                    const float* __restrict__ g, const float* __restrict__ b)
{
    int row = blockIdx.x;
    int tid = threadIdx.x;
    const float* x = X + (size_t)row * Cc;
    float4 v = *reinterpret_cast<const float4*>(x + tid*4);

    __shared__ float red[128];
    red[tid] = v.x + v.y + v.z + v.w;
    __syncthreads();
    #pragma unroll
    for (int s = 64; s > 0; s >>= 1) {
        if (tid < s) red[tid] += red[tid+s];
        __syncthreads();
    }
    float mu = red[0] * (1.0f/Cc);
    __syncthreads();

    float dx = v.x-mu, dy = v.y-mu, dz = v.z-mu, dw = v.w-mu;
    red[tid] = dx*dx + dy*dy + dz*dz + dw*dw;
    __syncthreads();
    #pragma unroll
    for (int s = 64; s > 0; s >>= 1) {
        if (tid < s) red[tid] += red[tid+s];
        __syncthreads();
    }
    float var = red[0] * (1.0f/Cc);
    float r = rsqrtf(var + 1e-5f);

    float4 gg = *reinterpret_cast<const float4*>(g + tid*4);
    float4 bb = *reinterpret_cast<const float4*>(b + tid*4);
    float4 o;
    o.x = tf32r(dx*r*gg.x + bb.x);
    o.y = tf32r(dy*r*gg.y + bb.y);
    o.z = tf32r(dz*r*gg.z + bb.z);
    o.w = tf32r(dw*r*gg.w + bb.w);
    *reinterpret_cast<float4*>(Y + (size_t)row*Cc + tid*4) = o;
}

// ---------------------------------------------------------------------------
// Flash attention v4 (bf16 m16n8k16): 128-row Q tile, 4 warps x 32 rows/warp,
// cp.async bf16 loads (V pre-transposed), ldmatrix b16, in-warp softmax.
//   Grid: (N/128, BH).  Block: 128 thr.  2 CTAs/SM.
//   SMEM bytes: sQ 128*144 | sK 64*144 | sVt 64*144 | sP 128*144 = 55296 B
//   (row stride 144 B = 36 banks ≡ 4 mod 32 → conflict-free ldsm phases)
// ---------------------------------------------------------------------------
#define RSB 144          // bytes per smem row (64 bf16 + 8 pad)
#define QOFF 0
#define KOFF (128*RSB)
#define VOFF (192*RSB)
#define POFF (256*RSB)
#define ATT_SMEM (384*RSB)   // 55296

__global__ __launch_bounds__(128, 2)
void flash_attn_tc(const __nv_bfloat16* __restrict__ Q,
                   const __nv_bfloat16* __restrict__ K,
                   const __nv_bfloat16* __restrict__ Vt,
                   const float* __restrict__ mask,
                   float* __restrict__ O)
{
    extern __shared__ uint32_t smu[];

    int tid  = threadIdx.x;
    int lane = tid & 31;
    int w    = tid >> 5;                 // warp owns rows [w*32, w*32+32)
    int rg   = lane >> 2;
    int cq   = lane & 3;
    int wr   = w * 32;

    int q0 = blockIdx.x * 128;
    int bh = blockIdx.y;
    int b  = bh >> 3, hh = bh & 7;

    const __nv_bfloat16* Qb  = Q  + ((size_t)bh*Nn_ + q0)*HD;
    const __nv_bfloat16* Kb  = K  + (size_t)bh*Nn_*HD;
    const __nv_bfloat16* Vtb = Vt + (size_t)bh*HD*Nn_;

    uint32_t smemb = (uint32_t)__cvta_generic_to_shared(smu);

    // ldmatrix lane geometry (b16, m16n8k16)
    int rA16  = lane & 15;
    int aByte = (lane >> 4) * 16;
    int rB8   = (lane & 7) + ((lane >> 4) & 1) * 8;
    int bByte = ((lane >> 3) & 1) * 16;
    uint32_t qA0 = smemb + QOFF + (uint32_t)(wr      + rA16)*RSB + aByte;
    uint32_t qA1 = smemb + QOFF + (uint32_t)(wr + 16 + rA16)*RSB + aByte;
    uint32_t pA0 = smemb + POFF + (uint32_t)(wr      + rA16)*RSB + aByte;
    uint32_t pA1 = smemb + POFF + (uint32_t)(wr + 16 + rA16)*RSB + aByte;
    uint32_t kB_ = smemb + KOFF + (uint32_t)rB8*RSB + bByte;
    uint32_t vB_ = smemb + VOFF + (uint32_t)rB8*RSB + bByte;

    uint32_t* sP32 = reinterpret_cast<uint32_t*>(reinterpret_cast<char*>(smu) + POFF);

    // Q tile: 128 rows x 128 B = 1024 16B chunks, 8/thread
    #pragma unroll
    for (int i = 0; i < 8; i++) {
        int f = tid + i*128;
        int r = f >> 3;
        int c = (f & 7) * 16;            // byte offset within row
        cpasync16(smemb + QOFF + (uint32_t)r*RSB + c,
                  reinterpret_cast<const char*>(Qb) + r*128 + c);
    }
    asm volatile("cp.async.commit_group;\n");

    float oacc[2][8][4];
    #pragma unroll
    for (int mt = 0; mt < 2; mt++)
        #pragma unroll
        for (int nt = 0; nt < 8; nt++)
            #pragma unroll
            for (int c = 0; c < 4; c++) oacc[mt][nt][c] = 0.0f;
    float rmax[4] = {-1e30f,-1e30f,-1e30f,-1e30f};
    float rsum[4] = {0.0f,0.0f,0.0f,0.0f};

    for (int kt = 0; kt < Nn_; kt += 64) {
        __syncthreads();
        // K tile [j][d] and Vt tile [d][j]: 64 rows x 128 B each, 4 chunks/thread
        #pragma unroll
        for (int i = 0; i < 4; i++) {
            int f = tid + i*128;
            int r = f >> 3;
            int c = (f & 7) * 16;
            cpasync16(smemb + KOFF + (uint32_t)r*RSB + c,
                      reinterpret_cast<const char*>(Kb + (size_t)(kt+r)*HD) + c);
            cpasync16(smemb + VOFF + (uint32_t)r*RSB + c,
                      reinterpret_cast<const char*>(Vtb + (size_t)r*Nn_ + kt) + c);
        }
        asm volatile("cp.async.commit_group;\n");
        asm volatile("cp.async.wait_group 0;\n");
        __syncthreads();

        // S = Q @ K^T : warp's 32 rows x 64 keys (bf16 k16 chunks)
        float sc[2][8][4];
        #pragma unroll
        for (int mt = 0; mt < 2; mt++)
            #pragma unroll
            for (int nt = 0; nt < 8; nt++)
                #pragma unroll
                for (int c = 0; c < 4; c++) sc[mt][nt][c] = 0.0f;
        #pragma unroll
        for (int ks = 0; ks < 4; ks++) {
            uint32_t a0[4], a1[4];
            ldsm_x4(a0[0], a0[1], a0[2], a0[3], qA0 + ks*32);
            ldsm_x4(a1[0], a1[1], a1[2], a1[3], qA1 + ks*32);
            uint32_t bf[8][2];
            #pragma unroll
            for (int p = 0; p < 4; p++)
                ldsm_x4(bf[2*p][0], bf[2*p][1], bf[2*p+1][0], bf[2*p+1][1],
                        kB_ + (uint32_t)(p*16*RSB) + ks*32);
            #pragma unroll
            for (int nt = 0; nt < 8; nt++) {
                mma_bf16(sc[0][nt], a0, bf[nt]);
                mma_bf16(sc[1][nt], a1, bf[nt]);
            }
        }

        // scale * multiplicative mask, then per-mt online softmax
        #pragma unroll
        for (int mt = 0; mt < 2; mt++) {
            int r0 = wr + mt*16 + rg;
            int r1 = r0 + 8;
            #pragma unroll
            for (int nt = 0; nt < 8; nt++) {
                int colg = kt + nt*8 + 2*cq;
                float2 m0 = *reinterpret_cast<const float2*>(mask + (size_t)(q0+r0)*Nn_ + colg);
                float2 m1 = *reinterpret_cast<const float2*>(mask + (size_t)(q0+r1)*Nn_ + colg);
                sc[mt][nt][0] *= 0.125f * m0.x;
                sc[mt][nt][1] *= 0.125f * m0.y;
                sc[mt][nt][2] *= 0.125f * m1.x;
                sc[mt][nt][3] *= 0.125f * m1.y;
            }

            float mx0 = -1e30f, mx1 = -1e30f;
            #pragma unroll
            for (int nt = 0; nt < 8; nt++) {
                mx0 = fmaxf(mx0, fmaxf(sc[mt][nt][0], sc[mt][nt][1]));
                mx1 = fmaxf(mx1, fmaxf(sc[mt][nt][2], sc[mt][nt][3]));
            }
            #pragma unroll
            for (int off = 1; off <= 2; off <<= 1) {
                mx0 = fmaxf(mx0, __shfl_xor_sync(0xffffffffu, mx0, off));
                mx1 = fmaxf(mx1, __shfl_xor_sync(0xffffffffu, mx1, off));
            }
            float nm0 = fmaxf(rmax[2*mt],   mx0);
            float nm1 = fmaxf(rmax[2*mt+1], mx1);
            float corr0 = __expf(rmax[2*mt]   - nm0);
            float corr1 = __expf(rmax[2*mt+1] - nm1);
            rmax[2*mt] = nm0; rmax[2*mt+1] = nm1;

            float ps0 = 0.0f, ps1 = 0.0f;
            #pragma unroll
            for (int nt = 0; nt < 8; nt++) {
                float e0 = __expf(sc[mt][nt][0] - nm0);
                float e1 = __expf(sc[mt][nt][1] - nm0);
                float e2 = __expf(sc[mt][nt][2] - nm1);
                float e3 = __expf(sc[mt][nt][3] - nm1);
                ps0 += e0 + e1;
                ps1 += e2 + e3;
                int cp2 = nt*4 + cq;            // u32 index of key pair
                sP32[r0*36 + cp2] = pack_bf16x2(e0, e1);
                sP32[r1*36 + cp2] = pack_bf16x2(e2, e3);
            }
            #pragma unroll
            for (int off = 1; off <= 2; off <<= 1) {
                ps0 += __shfl_xor_sync(0xffffffffu, ps0, off);
                ps1 += __shfl_xor_sync(0xffffffffu, ps1, off);
            }
            rsum[2*mt]   = rsum[2*mt]*corr0   + ps0;
            rsum[2*mt+1] = rsum[2*mt+1]*corr1 + ps1;
            #pragma unroll
            for (int nt = 0; nt < 8; nt++) {
                oacc[mt][nt][0] *= corr0;
                oacc[mt][nt][1] *= corr0;
                oacc[mt][nt][2] *= corr1;
                oacc[mt][nt][3] *= corr1;
            }
        }
        __syncwarp();   // P stores visible to this warp's ldmatrix

        // O += P @ V   (A = P rows x keys, B = Vt[d][j])
        #pragma unroll
        for (int ks = 0; ks < 4; ks++) {
            uint32_t a0[4], a1[4];
            ldsm_x4(a0[0], a0[1], a0[2], a0[3], pA0 + ks*32);
            ldsm_x4(a1[0], a1[1], a1[2], a1[3], pA1 + ks*32);
            uint32_t bf[8][2];
            #pragma unroll
            for (int p = 0; p < 4; p++)
                ldsm_x4(bf[2*p][0], bf[2*p][1], bf[2*p+1][0], bf[2*p+1][1],
                        vB_ + (uint32_t)(p*16*RSB) + ks*32);
            #pragma unroll
            for (int nt = 0; nt < 8; nt++) {
                mma_bf16(oacc[0][nt], a0, bf[nt]);
                mma_bf16(oacc[1][nt], a1, bf[nt]);
            }
        }
    }

    // epilogue: normalize, tf32-round, scatter into [B*N, C] (fp32)
    #pragma unroll
    for (int mt = 0; mt < 2; mt++) {
        int r0 = wr + mt*16 + rg;
        int r1 = r0 + 8;
        float inv0 = 1.0f / rsum[2*mt];
        float inv1 = 1.0f / rsum[2*mt+1];
        #pragma unroll
        for (int nt = 0; nt < 8; nt++) {
            int col = hh*HD + nt*8 + 2*cq;
            size_t m0g = (size_t)(b*Nn_ + q0 + r0);
            size_t m1g = (size_t)(b*Nn_ + q0 + r1);
            float2 o0; o0.x = tf32r(oacc[mt][nt][0]*inv0); o0.y = tf32r(oacc[mt][nt][1]*inv0);
            float2 o1; o1.x = tf32r(oacc[mt][nt][2]*inv1); o1.y = tf32r(oacc[mt][nt][3]*inv1);
            *reinterpret_cast<float2*>(O + m0g*Cc + col) = o0;
            *reinterpret_cast<float2*>(O + m1g*Cc + col) = o1;
        }
    }
}

// ---------------------------------------------------------------------------
// TF32 GEMM v3 (unchanged structure; EPI5 emits bf16 q/k and bf16 Vt).
// ---------------------------------------------------------------------------
#define GST 36
#define GTILE (128*GST)
#define STGW (2*GTILE)

template<int EPI>
__global__ __launch_bounds__(256, 2)
void gemm_tf32(const float* __restrict__ A, const float* __restrict__ B,
               float* __restrict__ C, float* __restrict__ C2, float* __restrict__ C3,
               int K, int lda, int ldb, int ldc,
               const float* __restrict__ bias, const float* __restrict__ res)
{
    extern __shared__ __align__(16) uint32_t dsm[];   // [3][STGW]

    int tid  = threadIdx.x;
    int lane = tid & 31;
    int w    = tid >> 5;
    int wm   = (w >> 2) * 64;
    int wn   = (w & 3)  * 32;
    int r    = lane >> 2;
    int cq   = lane & 3;
    int m0   = blockIdx.y * 128;
    int n0   = blockIdx.x * 128;

    uint32_t smemb = (uint32_t)__cvta_generic_to_shared(dsm);

    int rA = (lane & 7) + ((lane >> 3) & 1) * 8;
    int cA = ((lane >> 4) & 1) * 4;
    int rB = (lane & 7) + ((lane >> 4) & 1) * 8;
    int cB = ((lane >> 3) & 1) * 4;
    uint32_t aBase = smemb + ((wm + rA)*GST + cA)*4u;
    uint32_t bBase = smemb + (GTILE + (wn + rB)*GST + cB)*4u;

    int f0 = tid;
    float acc[16][4];
    #pragma unroll
    for (int i = 0; i < 16; i++)
        #pragma unroll
        for (int j = 0; j < 4; j++) acc[i][j] = 0.0f;

    auto issue_stage = [&](int stage, int kt) {
        uint32_t sb = smemb + (uint32_t)(stage*STGW)*4u;
        #pragma unroll
        for (int i = 0; i < 4; i++) {
            int f  = f0 + i*256;
            int ar = f >> 3, ac4 = (f & 7) << 2;
            uint32_t da = sb + (uint32_t)(ar*GST + ac4)*4u;
            const float* sa = A + (size_t)(m0+ar)*lda + kt + ac4;
            asm volatile("cp.async.cg.shared.global [%0], [%1], 16;\n" :: "r"(da), "l"(sa));
            uint32_t db = sb + (uint32_t)(GTILE + ar*GST + ac4)*4u;
            const float* sb2 = B + (size_t)(n0+ar)*ldb + kt + ac4;
            asm volatile("cp.async.cg.shared.global [%0], [%1], 16;\n" :: "r"(db), "l"(sb2));
        }
        asm volatile("cp.async.commit_group;\n");
    };
    auto empty_group = [&]() {
        asm volatile("cp.async.commit_group;\n");
    };

    issue_stage(0, 0);
    if (K > 32) issue_stage(1, 32); else empty_group();

    int nT = K >> 5;
    for (int t = 0; t < nT; t++) {
        asm volatile("cp.async.wait_group 1;\n");
        __syncthreads();
        if (t + 2 < nT) issue_stage((t+2)%3, (t+2)*32); else empty_group();

        int cur = t % 3;
        uint32_t abuf = aBase + (uint32_t)(cur*STGW)*4u;
        uint32_t bbuf = bBase + (uint32_t)(cur*STGW)*4u;
        #pragma unroll
        for (int ks = 0; ks < 4; ks++) {
            uint32_t af[4][4];
            #pragma unroll
            for (int mt = 0; mt < 4; mt++)
                ldsm_x4(af[mt][0], af[mt][1], af[mt][2], af[mt][3],
                        abuf + (uint32_t)(mt*16*GST + ks*8)*4u);
            uint32_t bf[4][2];
            #pragma unroll
            for (int p = 0; p < 2; p++)
                ldsm_x4(bf[2*p][0], bf[2*p][1], bf[2*p+1][0], bf[2*p+1][1],
                        bbuf + (uint32_t)(p*16*GST + ks*8)*4u);
            #pragma unroll
            for (int mt = 0; mt < 4; mt++)
                #pragma unroll
                for (int nt = 0; nt < 4; nt++)
                    mma_tf32(acc[mt*4+nt], af[mt], bf[nt]);
        }
    }

    #pragma unroll
    for (int mt = 0; mt < 4; mt++) {
        #pragma unroll
        for (int nt = 0; nt < 4; nt++) {
            const float* a4 = acc[mt*4+nt];
            int n = n0 + wn + nt*8 + 2*cq;
            #pragma unroll
            for (int p = 0; p < 2; p++) {
                int m = m0 + wm + mt*16 + r + 8*p;
                float v0 = a4[2*p+0];
                float v1 = a4[2*p+1];
                if (EPI == 2) {
                    float t0 = v0 + bias[n];
                    float t1 = v1 + bias[n+1];
                    float2 o2;
                    o2.x = tf32r(0.5f * t0 * (1.0f + erff(t0 * 0.70710678118654752f)));
                    o2.y = tf32r(0.5f * t1 * (1.0f + erff(t1 * 0.70710678118654752f)));
                    *reinterpret_cast<float2*>(C + (size_t)m*ldc + n) = o2;
                } else if (EPI == 3) {
                    float2 rr = *reinterpret_cast<const float2*>(res + (size_t)m*ldc + n);
                    float2 o2;
                    o2.x = v0 + bias[n]   + rr.x;
                    o2.y = v1 + bias[n+1] + rr.y;
                    *reinterpret_cast<float2*>(C + (size_t)m*ldc + n) = o2;
                } else if (EPI == 5) {
                    int kind = n >> 9;
                    int ww   = n & 511;
                    int hh   = ww >> 6;
                    int d    = ww & 63;
                    int b    = m >> 11;
                    int ntok = m & 2047;
                    if (kind == 2) {
                        // Vt bf16: [bh][d][n]
                        __nv_bfloat16* vt = reinterpret_cast<__nv_bfloat16*>(C3);
                        size_t base = ((size_t)(b*Hh + hh)*HD + d)*Nn_ + ntok;
                        vt[base]       = __float2bfloat16(v0);
                        vt[base + Nn_] = __float2bfloat16(v1);
                    } else {
                        size_t base = (((size_t)(b*Hh + hh))*Nn_ + ntok)*HD + d;
                        uint32_t pk = pack_bf16x2(v0, v1);
                        uint32_t* dst = reinterpret_cast<uint32_t*>(kind == 0 ? C : C2);
                        dst[base >> 1] = pk;
                    }
                }
            }
        }
    }
}

// ---------------------------------------------------------------------------
// Launch
// ---------------------------------------------------------------------------
extern "C" void kernel_launch(void* const* d_in, const int* in_sizes, int n_in,
                              void* d_out, int out_size)
{
    const float* x      = (const float*)d_in[0];
    const float* mask   = (const float*)d_in[1];
    const float* w_qkv  = (const float*)d_in[2];
    const float* w_proj = (const float*)d_in[3];
    const float* b_proj = (const float*)d_in[4];
    const float* g1     = (const float*)d_in[5];
    const float* beta1  = (const float*)d_in[6];
    const float* g2     = (const float*)d_in[7];
    const float* beta2  = (const float*)d_in[8];
    const float* w1     = (const float*)d_in[9];
    const float* bm1    = (const float*)d_in[10];
    const float* w2     = (const float*)d_in[11];
    const float* bm2    = (const float*)d_in[12];
    float* out = (float*)d_out;

    float *ln1, *o, *y, *h2, *f, *wq, *wp, *w1r, *w2r;
    __nv_bfloat16 *q, *k, *vt;
    cudaGetSymbolAddress((void**)&ln1, g_ln1);
    cudaGetSymbolAddress((void**)&q,   g_q);
    cudaGetSymbolAddress((void**)&k,   g_k);
    cudaGetSymbolAddress((void**)&vt,  g_vt);
    cudaGetSymbolAddress((void**)&o,   g_o);
    cudaGetSymbolAddress((void**)&y,   g_y);
    cudaGetSymbolAddress((void**)&h2,  g_h2);
    cudaGetSymbolAddress((void**)&f,   g_f);
    cudaGetSymbolAddress((void**)&wq,  g_wq);
    cudaGetSymbolAddress((void**)&wp,  g_wp);
    cudaGetSymbolAddress((void**)&w1r, g_w1);
    cudaGetSymbolAddress((void**)&w2r, g_w2);

    cudaFuncSetAttribute(flash_attn_tc,
        cudaFuncAttributeMaxDynamicSharedMemorySize, ATT_SMEM);
    const int GEMM_SMEM = 3*STGW*4;               // 110592 B
    cudaFuncSetAttribute(gemm_tf32<2>,
        cudaFuncAttributeMaxDynamicSharedMemorySize, GEMM_SMEM);
    cudaFuncSetAttribute(gemm_tf32<3>,
        cudaFuncAttributeMaxDynamicSharedMemorySize, GEMM_SMEM);
    cudaFuncSetAttribute(gemm_tf32<5>,
        cudaFuncAttributeMaxDynamicSharedMemorySize, GEMM_SMEM);

    // 0) pre-round weights to tf32 values (single fused kernel)
    round_all_tf32<<<3145728/4/256, 256>>>(w_qkv, w_proj, w1, w2, wq, wp, w1r, w2r);

    // 1) LN1 (tf32-rounded output)
    layernorm_rows<<<Mrows, 128>>>(x, ln1, g1, beta1);

    // 2) QKV with scatter (q/k bf16, vt bf16 transposed)
    {
        dim3 grid(1536/128, Mrows/128);
        gemm_tf32<5><<<grid, 256, GEMM_SMEM>>>(ln1, wq,
                                    (float*)q, (float*)k, (float*)vt,
                                    Cc, Cc, Cc, 0, nullptr, nullptr);
    }

    // 3) Fused attention v4 (bf16 tensor cores)
    {
        dim3 grid(Nn_/128, BH);
        flash_attn_tc<<<grid, 128, ATT_SMEM>>>(q, k, vt, mask, o);
    }

    // 4) proj + bias + residual
    {
        dim3 grid(Cc/128, Mrows/128);
        gemm_tf32<3><<<grid, 256, GEMM_SMEM>>>(o, wp, y, nullptr, nullptr,
                                    Cc, Cc, Cc, Cc, b_proj, x);
    }

    // 5) LN2 (tf32-rounded output)
    layernorm_rows<<<Mrows, 128>>>(y, h2, g2, beta2);

    // 6) FFN1 + bias + gelu (tf32-rounded output)
    {
        dim3 grid(DFF/128, Mrows/128);
        gemm_tf32<2><<<grid, 256, GEMM_SMEM>>>(h2, w1r, f, nullptr, nullptr,
                                    Cc, Cc, Cc, DFF, bm1, nullptr);
    }

    // 7) FFN2 + bias + residual
    {
        dim3 grid(Cc/128, Mrows/128);
        gemm_tf32<3><<<grid, 256, GEMM_SMEM>>>(f, w2r, out, nullptr, nullptr,
                                    DFF, DFF, DFF, Cc, bm2, y);
    }

    (void)in_sizes; (void)n_in; (void)out_size;
}

// round 17
// speedup vs baseline: 5.0524x; 1.0812x over previous
#include <cuda_runtime.h>
#include <cuda_bf16.h>
#include <math.h>
#include <stdint.h>

// ---------------------------------------------------------------------------
// Problem constants
// ---------------------------------------------------------------------------
#define Bb   2
#define Nn_  2048
#define Cc   512
#define Hh   8
#define HD   64
#define DFF  2048
#define Mrows (Bb*Nn_)          // 4096
#define BH   (Bb*Hh)            // 16

// ---------------------------------------------------------------------------
// Device scratch (static allocation — no cudaMalloc allowed).
// ---------------------------------------------------------------------------
__device__ __nv_bfloat16 g_ln1b[Mrows*Cc];    // LN1 out, bf16
__device__ __nv_bfloat16 g_q [BH*Nn_*HD];     // bf16 [bh][n][d]
__device__ __nv_bfloat16 g_k [BH*Nn_*HD];     // bf16 [bh][n][d]
__device__ __nv_bfloat16 g_vt[BH*HD*Nn_];     // bf16 [bh][d][n]
__device__ __nv_bfloat16 g_ob[Mrows*Cc];      // attention out, bf16
__device__ float g_y  [Mrows*Cc];
__device__ float g_h2 [Mrows*Cc];
__device__ float g_f  [Mrows*DFF];
// pre-rounded weights
__device__ __nv_bfloat16 g_wqb[3*Cc*Cc];      // bf16
__device__ __nv_bfloat16 g_wpb[Cc*Cc];        // bf16
__device__ float g_w1 [DFF*Cc];               // tf32-in-fp32
__device__ float g_w2 [Cc*DFF];               // tf32-in-fp32

// ---------------------------------------------------------------------------
// Precision helpers
// ---------------------------------------------------------------------------
__device__ __forceinline__ uint32_t f2tf32(float x) {
    uint32_t r;
    asm("cvt.rna.tf32.f32 %0, %1;" : "=r"(r) : "f"(x));
    return r;
}
__device__ __forceinline__ float tf32r(float x) {
    return __uint_as_float(f2tf32(x));
}
__device__ __forceinline__ uint32_t pack_bf16x2(float lo, float hi) {
    uint32_t r;
    asm("cvt.rn.bf16x2.f32 %0, %1, %2;" : "=r"(r) : "f"(hi), "f"(lo));
    return r;
}

__device__ __forceinline__ void mma_tf32(float* d, const uint32_t* a, const uint32_t* b) {
    asm volatile(
        "mma.sync.aligned.m16n8k8.row.col.f32.tf32.tf32.f32 "
        "{%0,%1,%2,%3}, {%4,%5,%6,%7}, {%8,%9}, {%0,%1,%2,%3};"
        : "+f"(d[0]), "+f"(d[1]), "+f"(d[2]), "+f"(d[3])
        : "r"(a[0]), "r"(a[1]), "r"(a[2]), "r"(a[3]), "r"(b[0]), "r"(b[1]));
}
__device__ __forceinline__ void mma_bf16(float* d, const uint32_t* a, const uint32_t* b) {
    asm volatile(
        "mma.sync.aligned.m16n8k16.row.col.f32.bf16.bf16.f32 "
        "{%0,%1,%2,%3}, {%4,%5,%6,%7}, {%8,%9}, {%0,%1,%2,%3};"
        : "+f"(d[0]), "+f"(d[1]), "+f"(d[2]), "+f"(d[3])
        : "r"(a[0]), "r"(a[1]), "r"(a[2]), "r"(a[3]), "r"(b[0]), "r"(b[1]));
}

__device__ __forceinline__ void ldsm_x4(uint32_t& r0, uint32_t& r1,
                                        uint32_t& r2, uint32_t& r3, uint32_t addr) {
    asm volatile("ldmatrix.sync.aligned.m8n8.x4.shared.b16 {%0,%1,%2,%3}, [%4];"
                 : "=r"(r0), "=r"(r1), "=r"(r2), "=r"(r3) : "r"(addr));
}

__device__ __forceinline__ void cpasync16(uint32_t dst, const void* src) {
    asm volatile("cp.async.cg.shared.global [%0], [%1], 16;\n" :: "r"(dst), "l"(src));
}

// ---------------------------------------------------------------------------
// Fused weight pre-rounding: wq/wp -> bf16, w1/w2 -> tf32-in-fp32
// ---------------------------------------------------------------------------
__global__ __launch_bounds__(256)
void round_all(const float* __restrict__ wq_in, const float* __restrict__ wp_in,
               const float* __restrict__ w1_in, const float* __restrict__ w2_in,
               __nv_bfloat16* __restrict__ wqb, __nv_bfloat16* __restrict__ wpb,
               float* __restrict__ w1o, float* __restrict__ w2o)
{
    int i4 = (blockIdx.x*256 + threadIdx.x) * 4;
    if (i4 < 786432) {
        float4 v = *reinterpret_cast<const float4*>(wq_in + i4);
        uint2 u; u.x = pack_bf16x2(v.x, v.y); u.y = pack_bf16x2(v.z, v.w);
        *reinterpret_cast<uint2*>(wqb + i4) = u;
    } else if (i4 < 1048576) {
        int off = i4 - 786432;
        float4 v = *reinterpret_cast<const float4*>(wp_in + off);
        uint2 u; u.x = pack_bf16x2(v.x, v.y); u.y = pack_bf16x2(v.z, v.w);
        *reinterpret_cast<uint2*>(wpb + off) = u;
    } else if (i4 < 2097152) {
        int off = i4 - 1048576;
        float4 v = *reinterpret_cast<const float4*>(w1_in + off);
        float4 o;
        o.x = tf32r(v.x); o.y = tf32r(v.y); o.z = tf32r(v.z); o.w = tf32r(v.w);
        *reinterpret_cast<float4*>(w1o + off) = o;
    } else {
        int off = i4 - 2097152;
        float4 v = *reinterpret_cast<const float4*>(w2_in + off);
        float4 o;
        o.x = tf32r(v.x); o.y = tf32r(v.y); o.z = tf32r(v.z); o.w = tf32r(v.w);
        *reinterpret_cast<float4*>(w2o + off) = o;
    }
}

// ---------------------------------------------------------------------------
// LayerNorm: one block (128 thr) per row of 512.
//   BF16OUT=1: bf16 output (LN1 -> bf16 QKV GEMM)
//   BF16OUT=0: tf32-rounded fp32 output (LN2 -> tf32 FFN1)
// ---------------------------------------------------------------------------
template<int BF16OUT>
__global__ __launch_bounds__(128)
void layernorm_rows(const float* __restrict__ X, void* __restrict__ Yv,
                    const float* __restrict__ g, const float* __restrict__ b)
{
    int row = blockIdx.x;
    int tid = threadIdx.x;
    const float* x = X + (size_t)row * Cc;
    float4 v = *reinterpret_cast<const float4*>(x + tid*4);

    __shared__ float red[128];
    red[tid] = v.x + v.y + v.z + v.w;
    __syncthreads();
    #pragma unroll
    for (int s = 64; s > 0; s >>= 1) {
        if (tid < s) red[tid] += red[tid+s];
        __syncthreads();
    }
    float mu = red[0] * (1.0f/Cc);
    __syncthreads();

    float dx = v.x-mu, dy = v.y-mu, dz = v.z-mu, dw = v.w-mu;
    red[tid] = dx*dx + dy*dy + dz*dz + dw*dw;
    __syncthreads();
    #pragma unroll
    for (int s = 64; s > 0; s >>= 1) {
        if (tid < s) red[tid] += red[tid+s];
        __syncthreads();
    }
    float var = red[0] * (1.0f/Cc);
    float r = rsqrtf(var + 1e-5f);

    float4 gg = *reinterpret_cast<const float4*>(g + tid*4);
    float4 bb = *reinterpret_cast<const float4*>(b + tid*4);
    float ox = dx*r*gg.x + bb.x;
    float oy = dy*r*gg.y + bb.y;
    float oz = dz*r*gg.z + bb.z;
    float ow = dw*r*gg.w + bb.w;
    if (BF16OUT) {
        __nv_bfloat16* Y = reinterpret_cast<__nv_bfloat16*>(Yv);
        uint2 u; u.x = pack_bf16x2(ox, oy); u.y = pack_bf16x2(oz, ow);
        *reinterpret_cast<uint2*>(Y + (size_t)row*Cc + tid*4) = u;
    } else {
        float* Y = reinterpret_cast<float*>(Yv);
        float4 o;
        o.x = tf32r(ox); o.y = tf32r(oy); o.z = tf32r(oz); o.w = tf32r(ow);
        *reinterpret_cast<float4*>(Y + (size_t)row*Cc + tid*4) = o;
    }
}

// ---------------------------------------------------------------------------
// Flash attention v5 (bf16 m16n8k16): 128-row Q tile, 4 warps x 32 rows/warp,
// DOUBLE-BUFFERED K/V cp.async pipeline, ldmatrix b16, in-warp softmax.
//   Grid: (N/128, BH).  Block: 128 thr.  2 CTAs/SM.
//   SMEM rows (stride 144 B): Q 128 | KV stage0 128 | KV stage1 128 | P 128
//   = 512*144 = 73728 B
// ---------------------------------------------------------------------------
#define RSB 144
#define POFFR 384            // P row offset
#define ATT_SMEM (512*RSB)   // 73728

__global__ __launch_bounds__(128, 2)
void flash_attn_tc(const __nv_bfloat16* __restrict__ Q,
                   const __nv_bfloat16* __restrict__ K,
                   const __nv_bfloat16* __restrict__ Vt,
                   const float* __restrict__ mask,
                   __nv_bfloat16* __restrict__ O)
{
    extern __shared__ uint32_t smu[];

    int tid  = threadIdx.x;
    int lane = tid & 31;
    int w    = tid >> 5;
    int rg   = lane >> 2;
    int cq   = lane & 3;
    int wr   = w * 32;

    int q0 = blockIdx.x * 128;
    int bh = blockIdx.y;
    int b  = bh >> 3, hh = bh & 7;

    const __nv_bfloat16* Qb  = Q  + ((size_t)bh*Nn_ + q0)*HD;
    const __nv_bfloat16* Kb  = K  + (size_t)bh*Nn_*HD;
    const __nv_bfloat16* Vtb = Vt + (size_t)bh*HD*Nn_;

    uint32_t smemb = (uint32_t)__cvta_generic_to_shared(smu);

    // ldmatrix lane geometry (validated R15)
    int rA16  = lane & 15;
    int aByte = (lane >> 4) * 16;
    int rB8   = (lane & 7) + ((lane >> 4) & 1) * 8;
    int bByte = ((lane >> 3) & 1) * 16;
    uint32_t qA0 = smemb + (uint32_t)(wr      + rA16)*RSB + aByte;
    uint32_t qA1 = smemb + (uint32_t)(wr + 16 + rA16)*RSB + aByte;
    uint32_t pA0 = smemb + (uint32_t)(POFFR + wr      + rA16)*RSB + aByte;
    uint32_t pA1 = smemb + (uint32_t)(POFFR + wr + 16 + rA16)*RSB + aByte;

    uint32_t* sP32 = reinterpret_cast<uint32_t*>(
        reinterpret_cast<char*>(smu) + POFFR*RSB);

    // KV stage issue: K rows [base..base+63], Vt rows [base+64..base+127]
    auto issue_kv = [&](int st, int kt) {
        uint32_t base = (uint32_t)(128 + 128*st);
        #pragma unroll
        for (int i = 0; i < 4; i++) {
            int f = tid + i*128;
            int r = f >> 3;
            int c = (f & 7) * 16;
            cpasync16(smemb + (base + r)*RSB + c,
                      reinterpret_cast<const char*>(Kb + (size_t)(kt+r)*HD) + c);
            cpasync16(smemb + (base + 64 + r)*RSB + c,
                      reinterpret_cast<const char*>(Vtb + (size_t)r*Nn_ + kt) + c);
        }
        asm volatile("cp.async.commit_group;\n");
    };

    // prologue: Q group, then KV tile 0
    #pragma unroll
    for (int i = 0; i < 8; i++) {
        int f = tid + i*128;
        int r = f >> 3;
        int c = (f & 7) * 16;
        cpasync16(smemb + (uint32_t)r*RSB + c,
                  reinterpret_cast<const char*>(Qb) + r*128 + c);
    }
    asm volatile("cp.async.commit_group;\n");
    issue_kv(0, 0);

    float oacc[2][8][4];
    #pragma unroll
    for (int mt = 0; mt < 2; mt++)
        #pragma unroll
        for (int nt = 0; nt < 8; nt++)
            #pragma unroll
            for (int c = 0; c < 4; c++) oacc[mt][nt][c] = 0.0f;
    float rmax[4] = {-1e30f,-1e30f,-1e30f,-1e30f};
    float rsum[4] = {0.0f,0.0f,0.0f,0.0f};

    const int nT = Nn_/64;   // 32
    for (int t = 0; t < nT; t++) {
        int kt = t*64;
        __syncthreads();   // all readers of stage (t-1)&1 done
        if (t + 1 < nT) issue_kv((t+1)&1, kt+64);
        else asm volatile("cp.async.commit_group;\n");
        asm volatile("cp.async.wait_group 1;\n");   // tile t resident
        __syncthreads();

        int st = t & 1;
        uint32_t kB_ = smemb + (uint32_t)(128 + 128*st + rB8)*RSB + bByte;
        uint32_t vB_ = kB_ + 64u*RSB;

        // S = Q @ K^T
        float sc[2][8][4];
        #pragma unroll
        for (int mt = 0; mt < 2; mt++)
            #pragma unroll
            for (int nt = 0; nt < 8; nt++)
                #pragma unroll
                for (int c = 0; c < 4; c++) sc[mt][nt][c] = 0.0f;
        #pragma unroll
        for (int ks = 0; ks < 4; ks++) {
            uint32_t a0[4], a1[4];
            ldsm_x4(a0[0], a0[1], a0[2], a0[3], qA0 + ks*32);
            ldsm_x4(a1[0], a1[1], a1[2], a1[3], qA1 + ks*32);
            uint32_t bf[8][2];
            #pragma unroll
            for (int p = 0; p < 4; p++)
                ldsm_x4(bf[2*p][0], bf[2*p][1], bf[2*p+1][0], bf[2*p+1][1],
                        kB_ + (uint32_t)(p*16*RSB) + ks*32);
            #pragma unroll
            for (int nt = 0; nt < 8; nt++) {
                mma_bf16(sc[0][nt], a0, bf[nt]);
                mma_bf16(sc[1][nt], a1, bf[nt]);
            }
        }

        // scale * multiplicative mask, per-mt online softmax
        #pragma unroll
        for (int mt = 0; mt < 2; mt++) {
            int r0 = wr + mt*16 + rg;
            int r1 = r0 + 8;
            #pragma unroll
            for (int nt = 0; nt < 8; nt++) {
                int colg = kt + nt*8 + 2*cq;
                float2 m0 = *reinterpret_cast<const float2*>(mask + (size_t)(q0+r0)*Nn_ + colg);
                float2 m1 = *reinterpret_cast<const float2*>(mask + (size_t)(q0+r1)*Nn_ + colg);
                sc[mt][nt][0] *= 0.125f * m0.x;
                sc[mt][nt][1] *= 0.125f * m0.y;
                sc[mt][nt][2] *= 0.125f * m1.x;
                sc[mt][nt][3] *= 0.125f * m1.y;
            }

            float mx0 = -1e30f, mx1 = -1e30f;
            #pragma unroll
            for (int nt = 0; nt < 8; nt++) {
                mx0 = fmaxf(mx0, fmaxf(sc[mt][nt][0], sc[mt][nt][1]));
                mx1 = fmaxf(mx1, fmaxf(sc[mt][nt][2], sc[mt][nt][3]));
            }
            #pragma unroll
            for (int off = 1; off <= 2; off <<= 1) {
                mx0 = fmaxf(mx0, __shfl_xor_sync(0xffffffffu, mx0, off));
                mx1 = fmaxf(mx1, __shfl_xor_sync(0xffffffffu, mx1, off));
            }
            float nm0 = fmaxf(rmax[2*mt],   mx0);
            float nm1 = fmaxf(rmax[2*mt+1], mx1);
            float corr0 = __expf(rmax[2*mt]   - nm0);
            float corr1 = __expf(rmax[2*mt+1] - nm1);
            rmax[2*mt] = nm0; rmax[2*mt+1] = nm1;

            float ps0 = 0.0f, ps1 = 0.0f;
            #pragma unroll
            for (int nt = 0; nt < 8; nt++) {
                float e0 = __expf(sc[mt][nt][0] - nm0);
                float e1 = __expf(sc[mt][nt][1] - nm0);
                float e2 = __expf(sc[mt][nt][2] - nm1);
                float e3 = __expf(sc[mt][nt][3] - nm1);
                ps0 += e0 + e1;
                ps1 += e2 + e3;
                int cp2 = nt*4 + cq;
                sP32[r0*36 + cp2] = pack_bf16x2(e0, e1);
                sP32[r1*36 + cp2] = pack_bf16x2(e2, e3);
            }
            #pragma unroll
            for (int off = 1; off <= 2; off <<= 1) {
                ps0 += __shfl_xor_sync(0xffffffffu, ps0, off);
                ps1 += __shfl_xor_sync(0xffffffffu, ps1, off);
            }
            rsum[2*mt]   = rsum[2*mt]*corr0   + ps0;
            rsum[2*mt+1] = rsum[2*mt+1]*corr1 + ps1;
            #pragma unroll
            for (int nt = 0; nt < 8; nt++) {
                oacc[mt][nt][0] *= corr0;
                oacc[mt][nt][1] *= corr0;
                oacc[mt][nt][2] *= corr1;
                oacc[mt][nt][3] *= corr1;
            }
        }
        __syncwarp();

        // O += P @ V
        #pragma unroll
        for (int ks = 0; ks < 4; ks++) {
            uint32_t a0[4], a1[4];
            ldsm_x4(a0[0], a0[1], a0[2], a0[3], pA0 + ks*32);
            ldsm_x4(a1[0], a1[1], a1[2], a1[3], pA1 + ks*32);
            uint32_t bf[8][2];
            #pragma unroll
            for (int p = 0; p < 4; p++)
                ldsm_x4(bf[2*p][0], bf[2*p][1], bf[2*p+1][0], bf[2*p+1][1],
                        vB_ + (uint32_t)(p*16*RSB) + ks*32);
            #pragma unroll
            for (int nt = 0; nt < 8; nt++) {
                mma_bf16(oacc[0][nt], a0, bf[nt]);
                mma_bf16(oacc[1][nt], a1, bf[nt]);
            }
        }
    }

    // epilogue: normalize, pack bf16, scatter into [B*N, C]
    #pragma unroll
    for (int mt = 0; mt < 2; mt++) {
        int r0 = wr + mt*16 + rg;
        int r1 = r0 + 8;
        float inv0 = 1.0f / rsum[2*mt];
        float inv1 = 1.0f / rsum[2*mt+1];
        #pragma unroll
        for (int nt = 0; nt < 8; nt++) {
            int col = hh*HD + nt*8 + 2*cq;
            size_t m0g = (size_t)(b*Nn_ + q0 + r0);
            size_t m1g = (size_t)(b*Nn_ + q0 + r1);
            uint32_t* o32 = reinterpret_cast<uint32_t*>(O);
            o32[(m0g*Cc + col) >> 1] = pack_bf16x2(oacc[mt][nt][0]*inv0, oacc[mt][nt][1]*inv0);
            o32[(m1g*Cc + col) >> 1] = pack_bf16x2(oacc[mt][nt][2]*inv1, oacc[mt][nt][3]*inv1);
        }
    }
}

// ---------------------------------------------------------------------------
// BF16 GEMM (m16n8k16): C[m,n] = sum_k A[m,k]*B[n,k], A/B bf16, acc fp32.
//   Block 128x128, BK=64 elements (128 B).  cp.async 3-stage + ldmatrix.
//   SMEM: 3 stages x (A 128 + B 128 rows) x 144 B = 110592 B.
//   EPI 3 = bias+res fp32 store | 5 = QKV scatter (q/k bf16, vt bf16 transposed)
// ---------------------------------------------------------------------------
#define BSTG (256*RSB)       // bytes per stage

template<int EPI>
__global__ __launch_bounds__(256, 2)
void gemm_bf16k(const __nv_bfloat16* __restrict__ A, const __nv_bfloat16* __restrict__ B,
                float* __restrict__ C, __nv_bfloat16* __restrict__ C2,
                __nv_bfloat16* __restrict__ C3,
                int K, int lda, int ldb, int ldc,
                const float* __restrict__ bias, const float* __restrict__ res)
{
    extern __shared__ __align__(16) char dsmc[];

    int tid  = threadIdx.x;
    int lane = tid & 31;
    int w    = tid >> 5;
    int wm   = (w >> 2) * 64;
    int wn   = (w & 3)  * 32;
    int r    = lane >> 2;
    int cq   = lane & 3;
    int m0   = blockIdx.y * 128;
    int n0   = blockIdx.x * 128;

    uint32_t smemb = (uint32_t)__cvta_generic_to_shared(dsmc);

    int rA16  = lane & 15;
    int aByte = (lane >> 4) * 16;
    int rB8   = (lane & 7) + ((lane >> 4) & 1) * 8;
    int bByte = ((lane >> 3) & 1) * 16;
    uint32_t aBase = smemb + (uint32_t)(wm + rA16)*RSB + aByte;
    uint32_t bBase = smemb + (uint32_t)(128 + wn + rB8)*RSB + bByte;

    float acc[16][4];
    #pragma unroll
    for (int i = 0; i < 16; i++)
        #pragma unroll
        for (int j = 0; j < 4; j++) acc[i][j] = 0.0f;

    auto issue_stage = [&](int stage, int kt) {
        uint32_t sb = smemb + (uint32_t)stage*BSTG;
        #pragma unroll
        for (int i = 0; i < 4; i++) {
            int f = tid + i*256;               // 0..1023 : A chunks
            int ar = f >> 3, ac = (f & 7) * 16;
            cpasync16(sb + (uint32_t)ar*RSB + ac,
                      reinterpret_cast<const char*>(A + (size_t)(m0+ar)*lda + kt) + ac);
        }
        #pragma unroll
        for (int i = 0; i < 4; i++) {
            int f = tid + i*256;               // B chunks
            int br = f >> 3, bc = (f & 7) * 16;
            cpasync16(sb + (uint32_t)(128 + br)*RSB + bc,
                      reinterpret_cast<const char*>(B + (size_t)(n0+br)*ldb + kt) + bc);
        }
        asm volatile("cp.async.commit_group;\n");
    };
    auto empty_group = [&]() { asm volatile("cp.async.commit_group;\n"); };

    issue_stage(0, 0);
    if (K > 64) issue_stage(1, 64); else empty_group();

    int nT = K >> 6;
    for (int t = 0; t < nT; t++) {
        asm volatile("cp.async.wait_group 1;\n");
        __syncthreads();
        if (t + 2 < nT) issue_stage((t+2)%3, (t+2)*64); else empty_group();

        uint32_t sb = (uint32_t)(t%3)*BSTG;
        #pragma unroll
        for (int ks = 0; ks < 4; ks++) {
            uint32_t af[4][4];
            #pragma unroll
            for (int mt = 0; mt < 4; mt++)
                ldsm_x4(af[mt][0], af[mt][1], af[mt][2], af[mt][3],
                        aBase + sb + (uint32_t)(mt*16*RSB) + ks*32);
            uint32_t bf[4][2];
            #pragma unroll
            for (int p = 0; p < 2; p++)
                ldsm_x4(bf[2*p][0], bf[2*p][1], bf[2*p+1][0], bf[2*p+1][1],
                        bBase + sb + (uint32_t)(p*16*RSB) + ks*32);
            #pragma unroll
            for (int mt = 0; mt < 4; mt++)
                #pragma unroll
                for (int nt = 0; nt < 4; nt++)
                    mma_bf16(acc[mt*4+nt], af[mt], bf[nt]);
        }
        __syncthreads();
    }

    #pragma unroll
    for (int mt = 0; mt < 4; mt++) {
        #pragma unroll
        for (int nt = 0; nt < 4; nt++) {
            const float* a4 = acc[mt*4+nt];
            int n = n0 + wn + nt*8 + 2*cq;
            #pragma unroll
            for (int p = 0; p < 2; p++) {
                int m = m0 + wm + mt*16 + r + 8*p;
                float v0 = a4[2*p+0];
                float v1 = a4[2*p+1];
                if (EPI == 3) {
                    float2 rr = *reinterpret_cast<const float2*>(res + (size_t)m*ldc + n);
                    float2 o2;
                    o2.x = v0 + bias[n]   + rr.x;
                    o2.y = v1 + bias[n+1] + rr.y;
                    *reinterpret_cast<float2*>(C + (size_t)m*ldc + n) = o2;
                } else if (EPI == 5) {
                    int kind = n >> 9;
                    int ww   = n & 511;
                    int hh   = ww >> 6;
                    int d    = ww & 63;
                    int b    = m >> 11;
                    int ntok = m & 2047;
                    if (kind == 2) {
                        size_t base = ((size_t)(b*Hh + hh)*HD + d)*Nn_ + ntok;
                        C3[base]       = __float2bfloat16(v0);
                        C3[base + Nn_] = __float2bfloat16(v1);
                    } else {
                        size_t base = (((size_t)(b*Hh + hh))*Nn_ + ntok)*HD + d;
                        uint32_t pk = pack_bf16x2(v0, v1);
                        uint32_t* dst = reinterpret_cast<uint32_t*>(
                            kind == 0 ? (void*)C : (void*)C2);
                        dst[base >> 1] = pk;
                    }
                }
            }
        }
    }
}

// ---------------------------------------------------------------------------
// TF32 GEMM (unchanged, passing): FFN1 (gelu) + FFN2 (bias+res)
// ---------------------------------------------------------------------------
#define GST 36
#define GTILE (128*GST)
#define STGW (2*GTILE)

template<int EPI>
__global__ __launch_bounds__(256, 2)
void gemm_tf32(const float* __restrict__ A, const float* __restrict__ B,
               float* __restrict__ C,
               int K, int lda, int ldb, int ldc,
               const float* __restrict__ bias, const float* __restrict__ res)
{
    extern __shared__ __align__(16) uint32_t dsm[];

    int tid  = threadIdx.x;
    int lane = tid & 31;
    int w    = tid >> 5;
    int wm   = (w >> 2) * 64;
    int wn   = (w & 3)  * 32;
    int r    = lane >> 2;
    int cq   = lane & 3;
    int m0   = blockIdx.y * 128;
    int n0   = blockIdx.x * 128;

    uint32_t smemb = (uint32_t)__cvta_generic_to_shared(dsm);

    int rA = (lane & 7) + ((lane >> 3) & 1) * 8;
    int cA = ((lane >> 4) & 1) * 4;
    int rB = (lane & 7) + ((lane >> 4) & 1) * 8;
    int cB = ((lane >> 3) & 1) * 4;
    uint32_t aBase = smemb + ((wm + rA)*GST + cA)*4u;
    uint32_t bBase = smemb + (GTILE + (wn + rB)*GST + cB)*4u;

    int f0 = tid;
    float acc[16][4];
    #pragma unroll
    for (int i = 0; i < 16; i++)
        #pragma unroll
        for (int j = 0; j < 4; j++) acc[i][j] = 0.0f;

    auto issue_stage = [&](int stage, int kt) {
        uint32_t sb = smemb + (uint32_t)(stage*STGW)*4u;
        #pragma unroll
        for (int i = 0; i < 4; i++) {
            int f  = f0 + i*256;
            int ar = f >> 3, ac4 = (f & 7) << 2;
            uint32_t da = sb + (uint32_t)(ar*GST + ac4)*4u;
            const float* sa = A + (size_t)(m0+ar)*lda + kt + ac4;
            asm volatile("cp.async.cg.shared.global [%0], [%1], 16;\n" :: "r"(da), "l"(sa));
            uint32_t db = sb + (uint32_t)(GTILE + ar*GST + ac4)*4u;
            const float* sb2 = B + (size_t)(n0+ar)*ldb + kt + ac4;
            asm volatile("cp.async.cg.shared.global [%0], [%1], 16;\n" :: "r"(db), "l"(sb2));
        }
        asm volatile("cp.async.commit_group;\n");
    };
    auto empty_group = [&]() { asm volatile("cp.async.commit_group;\n"); };

    issue_stage(0, 0);
    if (K > 32) issue_stage(1, 32); else empty_group();

    int nT = K >> 5;
    for (int t = 0; t < nT; t++) {
        asm volatile("cp.async.wait_group 1;\n");
        __syncthreads();
        if (t + 2 < nT) issue_stage((t+2)%3, (t+2)*32); else empty_group();

        int cur = t % 3;
        uint32_t abuf = aBase + (uint32_t)(cur*STGW)*4u;
        uint32_t bbuf = bBase + (uint32_t)(cur*STGW)*4u;
        #pragma unroll
        for (int ks = 0; ks < 4; ks++) {
            uint32_t af[4][4];
            #pragma unroll
            for (int mt = 0; mt < 4; mt++)
                ldsm_x4(af[mt][0], af[mt][1], af[mt][2], af[mt][3],
                        abuf + (uint32_t)(mt*16*GST + ks*8)*4u);
            uint32_t bf[4][2];
            #pragma unroll
            for (int p = 0; p < 2; p++)
                ldsm_x4(bf[2*p][0], bf[2*p][1], bf[2*p+1][0], bf[2*p+1][1],
                        bbuf + (uint32_t)(p*16*GST + ks*8)*4u);
            #pragma unroll
            for (int mt = 0; mt < 4; mt++)
                #pragma unroll
                for (int nt = 0; nt < 4; nt++)
                    mma_tf32(acc[mt*4+nt], af[mt], bf[nt]);
        }
    }

    #pragma unroll
    for (int mt = 0; mt < 4; mt++) {
        #pragma unroll
        for (int nt = 0; nt < 4; nt++) {
            const float* a4 = acc[mt*4+nt];
            int n = n0 + wn + nt*8 + 2*cq;
            #pragma unroll
            for (int p = 0; p < 2; p++) {
                int m = m0 + wm + mt*16 + r + 8*p;
                float v0 = a4[2*p+0];
                float v1 = a4[2*p+1];
                if (EPI == 2) {
                    float t0 = v0 + bias[n];
                    float t1 = v1 + bias[n+1];
                    float2 o2;
                    o2.x = tf32r(0.5f * t0 * (1.0f + erff(t0 * 0.70710678118654752f)));
                    o2.y = tf32r(0.5f * t1 * (1.0f + erff(t1 * 0.70710678118654752f)));
                    *reinterpret_cast<float2*>(C + (size_t)m*ldc + n) = o2;
                } else if (EPI == 3) {
                    float2 rr = *reinterpret_cast<const float2*>(res + (size_t)m*ldc + n);
                    float2 o2;
                    o2.x = v0 + bias[n]   + rr.x;
                    o2.y = v1 + bias[n+1] + rr.y;
                    *reinterpret_cast<float2*>(C + (size_t)m*ldc + n) = o2;
                }
            }
        }
    }
}

// ---------------------------------------------------------------------------
// Launch
// ---------------------------------------------------------------------------
extern "C" void kernel_launch(void* const* d_in, const int* in_sizes, int n_in,
                              void* d_out, int out_size)
{
    const float* x      = (const float*)d_in[0];
    const float* mask   = (const float*)d_in[1];
    const float* w_qkv  = (const float*)d_in[2];
    const float* w_proj = (const float*)d_in[3];
    const float* b_proj = (const float*)d_in[4];
    const float* g1     = (const float*)d_in[5];
    const float* beta1  = (const float*)d_in[6];
    const float* g2     = (const float*)d_in[7];
    const float* beta2  = (const float*)d_in[8];
    const float* w1     = (const float*)d_in[9];
    const float* bm1    = (const float*)d_in[10];
    const float* w2     = (const float*)d_in[11];
    const float* bm2    = (const float*)d_in[12];
    float* out = (float*)d_out;

    float *y, *h2, *f, *w1r, *w2r;
    __nv_bfloat16 *ln1b, *q, *k, *vt, *ob, *wqb, *wpb;
    cudaGetSymbolAddress((void**)&ln1b, g_ln1b);
    cudaGetSymbolAddress((void**)&q,    g_q);
    cudaGetSymbolAddress((void**)&k,    g_k);
    cudaGetSymbolAddress((void**)&vt,   g_vt);
    cudaGetSymbolAddress((void**)&ob,   g_ob);
    cudaGetSymbolAddress((void**)&y,    g_y);
    cudaGetSymbolAddress((void**)&h2,   g_h2);
    cudaGetSymbolAddress((void**)&f,    g_f);
    cudaGetSymbolAddress((void**)&wqb,  g_wqb);
    cudaGetSymbolAddress((void**)&wpb,  g_wpb);
    cudaGetSymbolAddress((void**)&w1r,  g_w1);
    cudaGetSymbolAddress((void**)&w2r,  g_w2);

    cudaFuncSetAttribute(flash_attn_tc,
        cudaFuncAttributeMaxDynamicSharedMemorySize, ATT_SMEM);
    const int BG_SMEM = 3*BSTG;                   // 110592
    cudaFuncSetAttribute(gemm_bf16k<3>,
        cudaFuncAttributeMaxDynamicSharedMemorySize, BG_SMEM);
    cudaFuncSetAttribute(gemm_bf16k<5>,
        cudaFuncAttributeMaxDynamicSharedMemorySize, BG_SMEM);
    const int GEMM_SMEM = 3*STGW*4;               // 110592
    cudaFuncSetAttribute(gemm_tf32<2>,
        cudaFuncAttributeMaxDynamicSharedMemorySize, GEMM_SMEM);
    cudaFuncSetAttribute(gemm_tf32<3>,
        cudaFuncAttributeMaxDynamicSharedMemorySize, GEMM_SMEM);

    // 0) weight pre-rounding (wq/wp -> bf16, w1/w2 -> tf32)
    round_all<<<3145728/4/256, 256>>>(w_qkv, w_proj, w1, w2, wqb, wpb, w1r, w2r);

    // 1) LN1 -> bf16
    layernorm_rows<1><<<Mrows, 128>>>(x, ln1b, g1, beta1);

    // 2) QKV (bf16 mma) with scatter: M=4096, N=1536, K=512
    {
        dim3 grid(1536/128, Mrows/128);
        gemm_bf16k<5><<<grid, 256, BG_SMEM>>>(ln1b, wqb, (float*)q, k, vt,
                                              Cc, Cc, Cc, 0, nullptr, nullptr);
    }

    // 3) Fused attention v5 (bf16, double-buffered K/V) -> bf16 O
    {
        dim3 grid(Nn_/128, BH);
        flash_attn_tc<<<grid, 128, ATT_SMEM>>>(q, k, vt, mask, ob);
    }

    // 4) proj (bf16 mma) + bias + residual -> fp32 y
    {
        dim3 grid(Cc/128, Mrows/128);
        gemm_bf16k<3><<<grid, 256, BG_SMEM>>>(ob, wpb, y, nullptr, nullptr,
                                              Cc, Cc, Cc, Cc, b_proj, x);
    }

    // 5) LN2 -> tf32 fp32
    layernorm_rows<0><<<Mrows, 128>>>(y, h2, g2, beta2);

    // 6) FFN1 + bias + gelu (tf32)
    {
        dim3 grid(DFF/128, Mrows/128);
        gemm_tf32<2><<<grid, 256, GEMM_SMEM>>>(h2, w1r, f,
                                    Cc, Cc, Cc, DFF, bm1, nullptr);
    }

    // 7) FFN2 + bias + residual (tf32)
    {
        dim3 grid(Cc/128, Mrows/128);
        gemm_tf32<3><<<grid, 256, GEMM_SMEM>>>(f, w2r, out,
                                    DFF, DFF, DFF, Cc, bm2, y);
    }

    (void)in_sizes; (void)n_in; (void)out_size;
}